// round 9
// baseline (speedup 1.0000x reference)
#include <cuda_runtime.h>
#include <cuda_bf16.h>
#include <math.h>
#include <stdint.h>

// ---------------- problem constants ----------------
#define BATCH    2
#define SEQLEN   1024
#define DMODEL   1024
#define DINNER   2048
#define NHEADS   32
#define HEADDIM  64
#define DSTATE   128
#define DCONV    4
#define CONVDIM  2304
#define DINPROJ  4384
#define ROWS     (BATCH*SEQLEN)
#define EPS      1e-5f
#define CLEN     64
#define NCH      (SEQLEN/CLEN)     // 16 chunks

// ---------------- scratch ----------------
__device__ __align__(1024) float g_zx [ROWS*DINPROJ];
__device__ __align__(1024) float g_xbc[ROWS*CONVDIM];
__device__ __align__(1024) float g_dt [ROWS*NHEADS];
__device__ __align__(1024) float g_y  [ROWS*DINNER];
__device__ __align__(1024) float g_hc [BATCH*NHEADS*NCH*HEADDIM*DSTATE];
__device__ __align__(1024) float g_h0 [BATCH*NHEADS*NCH*HEADDIM*DSTATE];
__device__ __align__(1024) float g_pi [BATCH*NHEADS*NCH];
__device__ __align__(1024) __nv_bfloat16 g_xh [ROWS*DMODEL];
__device__ __align__(1024) __nv_bfloat16 g_xl [ROWS*DMODEL];
__device__ __align__(1024) __nv_bfloat16 g_w1h[DINPROJ*DMODEL];
__device__ __align__(1024) __nv_bfloat16 g_w1l[DINPROJ*DMODEL];
__device__ __align__(1024) __nv_bfloat16 g_w2h[DMODEL*DINNER];
__device__ __align__(1024) __nv_bfloat16 g_w2l[DMODEL*DINNER];
__device__ __align__(1024) __nv_bfloat16 g_ynh[ROWS*DINNER];
__device__ __align__(1024) __nv_bfloat16 g_ynl[ROWS*DINNER];

// ---------------- primitives ----------------
__device__ __forceinline__ uint32_t smem_u32(const void* p) {
    uint32_t a;
    asm("{ .reg .u64 t; cvta.to.shared.u64 t, %1; cvt.u32.u64 %0, t; }" : "=r"(a) : "l"(p));
    return a;
}
__device__ __forceinline__ void cp16(uint32_t dst, const void* src) {
    asm volatile("cp.async.cg.shared.global [%0], [%1], 16;" :: "r"(dst), "l"(src));
}
__device__ __forceinline__ void cp_commit() { asm volatile("cp.async.commit_group;" ::: "memory"); }
template<int W> __device__ __forceinline__ void cp_wait() {
    asm volatile("cp.async.wait_group %0;" :: "n"(W) : "memory");
}
__device__ __forceinline__ void ldsm_x4(uint32_t& r0, uint32_t& r1, uint32_t& r2, uint32_t& r3, uint32_t a) {
    asm volatile("ldmatrix.sync.aligned.m8n8.x4.shared.b16 {%0,%1,%2,%3}, [%4];"
                 : "=r"(r0), "=r"(r1), "=r"(r2), "=r"(r3) : "r"(a));
}
__device__ __forceinline__ void ldsm_x4_t(uint32_t& r0, uint32_t& r1, uint32_t& r2, uint32_t& r3, uint32_t a) {
    asm volatile("ldmatrix.sync.aligned.m8n8.x4.trans.shared.b16 {%0,%1,%2,%3}, [%4];"
                 : "=r"(r0), "=r"(r1), "=r"(r2), "=r"(r3) : "r"(a));
}
__device__ __forceinline__ void mma_bf16(float* c, const uint32_t* a, uint32_t b0, uint32_t b1) {
    asm volatile(
        "mma.sync.aligned.m16n8k16.row.col.f32.bf16.bf16.f32 "
        "{%0,%1,%2,%3}, {%4,%5,%6,%7}, {%8,%9}, {%0,%1,%2,%3};"
        : "+f"(c[0]), "+f"(c[1]), "+f"(c[2]), "+f"(c[3])
        : "r"(a[0]), "r"(a[1]), "r"(a[2]), "r"(a[3]), "r"(b0), "r"(b1));
}
__device__ __forceinline__ uint32_t swz(int row, int seg) {
    return (uint32_t)(row * 128 + ((seg ^ (row & 7)) << 4));
}
__device__ __forceinline__ uint32_t swzb(int row, int colb) {
    return (uint32_t)(row * 128 + (((colb >> 4) ^ (row & 7)) << 4) + (colb & 15));
}
__device__ __forceinline__ void hilo(float v, __nv_bfloat16& h, __nv_bfloat16& l) {
    h = __float2bfloat16(v);
    l = __float2bfloat16(v - __bfloat162float(h));
}

// =====================================================================
// Tensor-core GEMM, BN=64 / 2-CTA-per-SM variant.
// CTA tile 128x64, K-chunk 64, 2-stage cp.async pipeline, 256 threads,
// warp tile 64x16, acc[4][2][4]. smem 96KB -> 2 CTAs resident.
// =====================================================================
#define BM 128
#define BN 64
#define KC 64
#define GTILE_A  16384u            // 128 rows * 128B
#define GTILE_B  8192u             // 64 rows * 128B
#define GSTAGE_B 49152u            // Ah,Al,Bh,Bl
#define SMEM_GEMM (2u*GSTAGE_B)    // 98304

template<bool RES>
__global__ __launch_bounds__(256, 2)
void gemm_mma(const __nv_bfloat16* __restrict__ Ahp, const __nv_bfloat16* __restrict__ Alp,
              const __nv_bfloat16* __restrict__ Bhp, const __nv_bfloat16* __restrict__ Blp,
              const float* __restrict__ resid, float* __restrict__ C,
              int N, int K)
{
    extern __shared__ __align__(1024) char smem[];
    const uint32_t sb = smem_u32(smem);

    const int tid = threadIdx.x;
    const int wid = tid >> 5, lane = tid & 31;
    const int wm = wid & 1, wn = wid >> 1;           // 2 x 4 warps
    const int m0 = blockIdx.y * BM, n0 = blockIdx.x * BN;
    const int NC = K / KC;

    auto load_chunk = [&](int stage, int k0) {
        uint32_t s = sb + stage * GSTAGE_B;
#pragma unroll
        for (int it = 0; it < 4; it++) {             // A: 1024 cp16 per tile
            int idx = tid + it * 256;
            int row = idx >> 3, seg = idx & 7;
            uint32_t d = swz(row, seg);
            size_t aoff = (size_t)(m0 + row) * K + k0 + seg * 8;
            cp16(s + d,          Ahp + aoff);
            cp16(s + GTILE_A + d, Alp + aoff);
        }
#pragma unroll
        for (int it = 0; it < 2; it++) {             // B: 512 cp16 per tile
            int idx = tid + it * 256;
            int row = idx >> 3, seg = idx & 7;
            uint32_t d = swz(row, seg);
            int brow = n0 + row; if (brow >= N) brow = N - 1;
            size_t boff = (size_t)brow * K + k0 + seg * 8;
            cp16(s + 2 * GTILE_A + d,            Bhp + boff);
            cp16(s + 2 * GTILE_A + GTILE_B + d,  Blp + boff);
        }
        cp_commit();
    };

    float acc[4][2][4];
#pragma unroll
    for (int mi = 0; mi < 4; mi++)
#pragma unroll
        for (int ni = 0; ni < 2; ni++)
#pragma unroll
            for (int q = 0; q < 4; q++) acc[mi][ni][q] = 0.f;

    const int lgrp = lane >> 3, lr = lane & 7;
    const int a_roff = lr + (lgrp & 1) * 8;
    const int a_koff = lgrp >> 1;
    const int b_roff = lr + (lgrp >> 1) * 8;
    const int b_koff = lgrp & 1;

    load_chunk(0, 0);
    load_chunk(1, KC);

    for (int c = 0; c < NC; c++) {
        cp_wait<1>();                    // chunk c resident
        __syncthreads();

        uint32_t s = sb + (c & 1) * GSTAGE_B;
#pragma unroll
        for (int k16 = 0; k16 < 4; k16++) {
            int k2 = k16 * 2;
            uint32_t aH[4][4], aL[4][4], bH[2][2], bL[2][2];
#pragma unroll
            for (int mi = 0; mi < 4; mi++) {
                int row = wm * 64 + mi * 16 + a_roff;
                uint32_t ad = swz(row, k2 + a_koff);
                ldsm_x4(aH[mi][0], aH[mi][1], aH[mi][2], aH[mi][3], s + ad);
                ldsm_x4(aL[mi][0], aL[mi][1], aL[mi][2], aL[mi][3], s + GTILE_A + ad);
            }
            {
                int row = wn * 16 + b_roff;
                uint32_t bd = swz(row, k2 + b_koff);
                uint32_t r0, r1, r2, r3;
                ldsm_x4(r0, r1, r2, r3, s + 2 * GTILE_A + bd);
                bH[0][0] = r0; bH[0][1] = r1; bH[1][0] = r2; bH[1][1] = r3;
                ldsm_x4(r0, r1, r2, r3, s + 2 * GTILE_A + GTILE_B + bd);
                bL[0][0] = r0; bL[0][1] = r1; bL[1][0] = r2; bL[1][1] = r3;
            }
#pragma unroll
            for (int mi = 0; mi < 4; mi++)
#pragma unroll
                for (int ni = 0; ni < 2; ni++) {
                    mma_bf16(acc[mi][ni], aH[mi], bH[ni][0], bH[ni][1]);
                    mma_bf16(acc[mi][ni], aH[mi], bL[ni][0], bL[ni][1]);
                    mma_bf16(acc[mi][ni], aL[mi], bH[ni][0], bH[ni][1]);
                }
        }
        __syncthreads();
        if (c + 2 < NC) load_chunk((c + 2) & 1, (c + 2) * KC);
        else            cp_commit();     // keep group count consistent
    }

    const int quad = lane >> 2, qt = lane & 3;
#pragma unroll
    for (int mi = 0; mi < 4; mi++) {
#pragma unroll
        for (int ni = 0; ni < 2; ni++) {
            int gm = m0 + wm * 64 + mi * 16 + quad;
            int gn = n0 + wn * 16 + ni * 8 + qt * 2;
            if (gn < N) {
                {
                    float2 v = make_float2(acc[mi][ni][0], acc[mi][ni][1]);
                    size_t o = (size_t)gm * N + gn;
                    if (RES) { float2 rv = *(const float2*)(resid + o); v.x += rv.x; v.y += rv.y; }
                    *(float2*)(C + o) = v;
                }
                {
                    float2 v = make_float2(acc[mi][ni][2], acc[mi][ni][3]);
                    size_t o = (size_t)(gm + 8) * N + gn;
                    if (RES) { float2 rv = *(const float2*)(resid + o); v.x += rv.x; v.y += rv.y; }
                    *(float2*)(C + o) = v;
                }
            }
        }
    }
}

// =====================================================================
// merged fp32 -> bf16 hi/lo split
// =====================================================================
#define N4_X  (ROWS*DMODEL/4)
#define N4_W1 (DINPROJ*DMODEL/4)
#define N4_W2 (DMODEL*DINNER/4)

__device__ __forceinline__ void split4(float4 v, __nv_bfloat162* hi, __nv_bfloat162* lo, int i) {
    __nv_bfloat16 hx, lx, hy, ly, hz, lz, hw, lw;
    hilo(v.x, hx, lx); hilo(v.y, hy, ly); hilo(v.z, hz, lz); hilo(v.w, hw, lw);
    hi[i * 2]     = __halves2bfloat162(hx, hy);
    hi[i * 2 + 1] = __halves2bfloat162(hz, hw);
    lo[i * 2]     = __halves2bfloat162(lx, ly);
    lo[i * 2 + 1] = __halves2bfloat162(lz, lw);
}

__global__ __launch_bounds__(256)
void cvt_all(const float4* __restrict__ x, const float4* __restrict__ w1,
             const float4* __restrict__ w2)
{
    int i = blockIdx.x * 256 + threadIdx.x;
    if (i < N4_X) {
        split4(x[i], (__nv_bfloat162*)g_xh, (__nv_bfloat162*)g_xl, i);
    } else if (i < N4_X + N4_W1) {
        int j = i - N4_X;
        split4(w1[j], (__nv_bfloat162*)g_w1h, (__nv_bfloat162*)g_w1l, j);
    } else if (i < N4_X + N4_W1 + N4_W2) {
        int j = i - N4_X - N4_W1;
        split4(w2[j], (__nv_bfloat162*)g_w2h, (__nv_bfloat162*)g_w2l, j);
    }
}

// =====================================================================
// Causal depthwise conv + SiLU; dt softplus
// =====================================================================
__global__ __launch_bounds__(256)
void conv_act_kernel(const float* __restrict__ conv_w, const float* __restrict__ conv_b,
                     const float* __restrict__ dt_bias)
{
    const int c  = blockIdx.x * 256 + threadIdx.x;
    const int tb = blockIdx.y * 4;
    const int b  = blockIdx.z;

    float w0 = conv_w[c * 4 + 0], w1 = conv_w[c * 4 + 1];
    float w2 = conv_w[c * 4 + 2], w3 = conv_w[c * 4 + 3];
    float bias = conv_b[c];

    float v[7];
#pragma unroll
    for (int k = 0; k < 7; k++) {
        int tt = tb - 3 + k;
        v[k] = (tt >= 0) ? g_zx[((size_t)b * SEQLEN + tt) * DINPROJ + DINNER + c] : 0.f;
    }
#pragma unroll
    for (int i = 0; i < 4; i++) {
        float a = bias + v[i] * w0 + v[i + 1] * w1 + v[i + 2] * w2 + v[i + 3] * w3;
        g_xbc[((size_t)b * SEQLEN + tb + i) * CONVDIM + c] = a / (1.f + expf(-a));
    }
    if (blockIdx.x == 0 && threadIdx.x < NHEADS) {
        int hh = threadIdx.x;
        float bth = dt_bias[hh];
#pragma unroll
        for (int i = 0; i < 4; i++) {
            size_t row = (size_t)b * SEQLEN + tb + i;
            float raw = g_zx[row * DINPROJ + (DINNER + CONVDIM) + hh] + bth;
            g_dt[row * NHEADS + hh] = (raw > 20.f) ? raw : log1pf(expf(raw));
        }
    }
}

// =====================================================================
// SSD phase 1: per-chunk local scan on tensor cores.
// G overlays the C panels (C dead after GEMM2) -> smem 96.75KB -> 2 CTAs/SM.
// =====================================================================
#define OFF_CPH 0u
#define OFF_CPL 16384u
#define OFF_BPH 32768u
#define OFF_BPL 49152u
#define OFF_UTH 65536u
#define OFF_UTL 73728u
#define OFF_UWH 81920u
#define OFF_UWL 90112u
#define OFF_GH  OFF_CPH            // overlay: C panels reused for G
#define OFF_GL  (OFF_CPH + 8192u)
#define OFF_SDT 98304u
#define OFF_DTS 98560u
#define OFF_WS  98816u
#define SMEM_SSD1 99072u

__global__ __launch_bounds__(256, 2)
void ssd_chunk_kernel(const float* __restrict__ A_log)
{
    extern __shared__ __align__(1024) char smem[];
    const uint32_t sb = smem_u32(smem);
    const int c = blockIdx.x, b = blockIdx.y, hh = blockIdx.z;
    const int tid = threadIdx.x;
    const int wid = tid >> 5, lane = tid & 31;
    const int wm = wid & 1, wn = wid >> 1;
    const int t0 = c * CLEN;
    const float Ah = -expf(A_log[hh]);

    float* s_sdt = (float*)(smem + OFF_SDT);
    float* s_dt  = (float*)(smem + OFF_DTS);
    float* s_w   = (float*)(smem + OFF_WS);

    // ---- dt load + inclusive scan ----
    if (tid < 64) {
        float d = g_dt[((size_t)b * SEQLEN + t0 + tid) * NHEADS + hh];
        s_dt[tid] = d;
        s_sdt[tid] = d;
    }
    __syncthreads();
#pragma unroll
    for (int off = 1; off < 64; off <<= 1) {
        float v = 0.f;
        if (tid < 64 && tid >= off) v = s_sdt[tid - off];
        __syncthreads();
        if (tid < 64) s_sdt[tid] += v;
        __syncthreads();
    }
    float sdtTOT = s_sdt[63];
    if (tid < 64) s_w[tid] = expf(Ah * (sdtTOT - s_sdt[tid]));
    if (tid == 0) g_pi[((size_t)b * NHEADS + hh) * NCH + c] = sdtTOT;
    __syncthreads();

    // ---- convert C, B (t-major panels; vectorized only) ----
#pragma unroll
    for (int i = 0; i < 8; i++) {
        int idx = tid + i * 256;                 // 2048 float4
        int t = idx >> 5, n4 = idx & 31;
        size_t row = ((size_t)b * SEQLEN + t0 + t) * CONVDIM;
        int kp = n4 >> 4, cb = n4 & 15;
        uint32_t off = (uint32_t)kp * 8192u + (uint32_t)t * 128u
                     + ((((uint32_t)cb >> 1) ^ (t & 7)) << 4) + (cb & 1) * 8;
        {
            float4 v = *(const float4*)&g_xbc[row + DINNER + DSTATE + n4 * 4];
            __nv_bfloat16 h0,l0,h1,l1,h2,l2,h3,l3;
            hilo(v.x,h0,l0); hilo(v.y,h1,l1); hilo(v.z,h2,l2); hilo(v.w,h3,l3);
            *(__nv_bfloat162*)(smem + OFF_CPH + off)     = __halves2bfloat162(h0,h1);
            *(__nv_bfloat162*)(smem + OFF_CPH + off + 4) = __halves2bfloat162(h2,h3);
            *(__nv_bfloat162*)(smem + OFF_CPL + off)     = __halves2bfloat162(l0,l1);
            *(__nv_bfloat162*)(smem + OFF_CPL + off + 4) = __halves2bfloat162(l2,l3);
        }
        {
            float4 v = *(const float4*)&g_xbc[row + DINNER + n4 * 4];
            __nv_bfloat16 h0,l0,h1,l1,h2,l2,h3,l3;
            hilo(v.x,h0,l0); hilo(v.y,h1,l1); hilo(v.z,h2,l2); hilo(v.w,h3,l3);
            *(__nv_bfloat162*)(smem + OFF_BPH + off)     = __halves2bfloat162(h0,h1);
            *(__nv_bfloat162*)(smem + OFF_BPH + off + 4) = __halves2bfloat162(h2,h3);
            *(__nv_bfloat162*)(smem + OFF_BPL + off)     = __halves2bfloat162(l0,l1);
            *(__nv_bfloat162*)(smem + OFF_BPL + off + 4) = __halves2bfloat162(l2,l3);
        }
    }
    // ---- convert U = dt*x and Uw = w*U (natural [s][p] layout) ----
#pragma unroll
    for (int i = 0; i < 4; i++) {
        int idx = tid + i * 256;                 // 1024 float4
        int t = idx >> 4, p4 = idx & 15;
        size_t row = ((size_t)b * SEQLEN + t0 + t) * CONVDIM;
        float4 xv = *(const float4*)&g_xbc[row + hh * HEADDIM + p4 * 4];
        float dtv = s_dt[t], wv = s_w[t];
        float u0 = dtv*xv.x, u1 = dtv*xv.y, u2 = dtv*xv.z, u3 = dtv*xv.w;
        uint32_t off = swzb(t, p4 * 8);
        __nv_bfloat16 h0,l0,h1,l1,h2,l2,h3,l3;
        hilo(u0,h0,l0); hilo(u1,h1,l1); hilo(u2,h2,l2); hilo(u3,h3,l3);
        *(__nv_bfloat162*)(smem + OFF_UTH + off)     = __halves2bfloat162(h0,h1);
        *(__nv_bfloat162*)(smem + OFF_UTH + off + 4) = __halves2bfloat162(h2,h3);
        *(__nv_bfloat162*)(smem + OFF_UTL + off)     = __halves2bfloat162(l0,l1);
        *(__nv_bfloat162*)(smem + OFF_UTL + off + 4) = __halves2bfloat162(l2,l3);
        hilo(u0*wv,h0,l0); hilo(u1*wv,h1,l1); hilo(u2*wv,h2,l2); hilo(u3*wv,h3,l3);
        *(__nv_bfloat162*)(smem + OFF_UWH + off)     = __halves2bfloat162(h0,h1);
        *(__nv_bfloat162*)(smem + OFF_UWH + off + 4) = __halves2bfloat162(h2,h3);
        *(__nv_bfloat162*)(smem + OFF_UWL + off)     = __halves2bfloat162(l0,l1);
        *(__nv_bfloat162*)(smem + OFF_UWL + off + 4) = __halves2bfloat162(l2,l3);
    }
    __syncthreads();

    const int lgrp = lane >> 3, lr = lane & 7;
    const int a_roff = lr + (lgrp & 1) * 8;
    const int a_koff = lgrp >> 1;
    const int b_roff = lr + (lgrp >> 1) * 8;
    const int b_koff = lgrp & 1;
    const int quad = lane >> 2, qt = lane & 3;
    const int bt_row = lr + (lgrp & 1) * 8;
    const int bt_col = (lgrp >> 1) * 8;
    const int at_row = lr + (lgrp >> 1) * 8;
    const int at_col = (lgrp & 1) * 8;

    // ---- GEMM2: G = C @ B^T   [64t x 64s], K=n=128 ----
    float accG[2][2][4];
#pragma unroll
    for (int mi = 0; mi < 2; mi++)
#pragma unroll
        for (int ni = 0; ni < 2; ni++)
#pragma unroll
            for (int q = 0; q < 4; q++) accG[mi][ni][q] = 0.f;

#pragma unroll
    for (int kp = 0; kp < 2; kp++) {
#pragma unroll
        for (int k16 = 0; k16 < 4; k16++) {
            int k2 = k16 * 2;
            uint32_t aH[2][4], aL[2][4], bH[2][2], bL[2][2];
#pragma unroll
            for (int mi = 0; mi < 2; mi++) {
                int row = wm * 32 + mi * 16 + a_roff;
                uint32_t ad = kp * 8192u + swz(row, k2 + a_koff);
                ldsm_x4(aH[mi][0], aH[mi][1], aH[mi][2], aH[mi][3], sb + OFF_CPH + ad);
                ldsm_x4(aL[mi][0], aL[mi][1], aL[mi][2], aL[mi][3], sb + OFF_CPL + ad);
            }
            {
                int row = wn * 16 + b_roff;
                uint32_t bd = kp * 8192u + swz(row, k2 + b_koff);
                uint32_t r0, r1, r2, r3;
                ldsm_x4(r0, r1, r2, r3, sb + OFF_BPH + bd);
                bH[0][0] = r0; bH[0][1] = r1; bH[1][0] = r2; bH[1][1] = r3;
                ldsm_x4(r0, r1, r2, r3, sb + OFF_BPL + bd);
                bL[0][0] = r0; bL[0][1] = r1; bL[1][0] = r2; bL[1][1] = r3;
            }
#pragma unroll
            for (int mi = 0; mi < 2; mi++)
#pragma unroll
                for (int ni = 0; ni < 2; ni++) {
                    mma_bf16(accG[mi][ni], aH[mi], bH[ni][0], bH[ni][1]);
                    mma_bf16(accG[mi][ni], aH[mi], bL[ni][0], bL[ni][1]);
                    mma_bf16(accG[mi][ni], aL[mi], bH[ni][0], bH[ni][1]);
                }
        }
    }
    __syncthreads();   // all warps done reading C panels before G overlays them

#pragma unroll
    for (int mi = 0; mi < 2; mi++)
#pragma unroll
        for (int ni = 0; ni < 2; ni++)
#pragma unroll
            for (int half = 0; half < 2; half++) {
                int t = wm * 32 + mi * 16 + quad + half * 8;
                int s = wn * 16 + ni * 8 + qt * 2;
                float sdt_t = s_sdt[t];
                float v0 = accG[mi][ni][half * 2 + 0];
                float v1 = accG[mi][ni][half * 2 + 1];
                v0 = (t >= s)     ? v0 * expf(Ah * (sdt_t - s_sdt[s]))     : 0.f;
                v1 = (t >= s + 1) ? v1 * expf(Ah * (sdt_t - s_sdt[s + 1])) : 0.f;
                __nv_bfloat16 h0,l0,h1,l1;
                hilo(v0,h0,l0); hilo(v1,h1,l1);
                uint32_t off = swzb(t, s * 2);
                *(__nv_bfloat162*)(smem + OFF_GH + off) = __halves2bfloat162(h0,h1);
                *(__nv_bfloat162*)(smem + OFF_GL + off) = __halves2bfloat162(l0,l1);
            }
    __syncthreads();

    // ---- GEMM4: Y = G @ U  [64t x 64p], K=s=64; U via trans-B ----
    {
        float accY[2][2][4];
#pragma unroll
        for (int mi = 0; mi < 2; mi++)
#pragma unroll
            for (int ni = 0; ni < 2; ni++)
#pragma unroll
                for (int q = 0; q < 4; q++) accY[mi][ni][q] = 0.f;

#pragma unroll
        for (int k16 = 0; k16 < 4; k16++) {
            int k2 = k16 * 2, kb = k16 * 16;
            uint32_t aH[2][4], aL[2][4], bH[2][2], bL[2][2];
#pragma unroll
            for (int mi = 0; mi < 2; mi++) {
                int row = wm * 32 + mi * 16 + a_roff;
                uint32_t ad = swz(row, k2 + a_koff);
                ldsm_x4(aH[mi][0], aH[mi][1], aH[mi][2], aH[mi][3], sb + OFF_GH + ad);
                ldsm_x4(aL[mi][0], aL[mi][1], aL[mi][2], aL[mi][3], sb + OFF_GL + ad);
            }
            {
                int row = kb + bt_row;
                int col = wn * 16 + bt_col;
                uint32_t bd = swzb(row, col * 2);
                uint32_t r0, r1, r2, r3;
                ldsm_x4_t(r0, r1, r2, r3, sb + OFF_UTH + bd);
                bH[0][0] = r0; bH[0][1] = r1; bH[1][0] = r2; bH[1][1] = r3;
                ldsm_x4_t(r0, r1, r2, r3, sb + OFF_UTL + bd);
                bL[0][0] = r0; bL[0][1] = r1; bL[1][0] = r2; bL[1][1] = r3;
            }
#pragma unroll
            for (int mi = 0; mi < 2; mi++)
#pragma unroll
                for (int ni = 0; ni < 2; ni++) {
                    mma_bf16(accY[mi][ni], aH[mi], bH[ni][0], bH[ni][1]);
                    mma_bf16(accY[mi][ni], aH[mi], bL[ni][0], bL[ni][1]);
                    mma_bf16(accY[mi][ni], aL[mi], bH[ni][0], bH[ni][1]);
                }
        }
#pragma unroll
        for (int mi = 0; mi < 2; mi++)
#pragma unroll
            for (int ni = 0; ni < 2; ni++) {
                int t = wm * 32 + mi * 16 + quad;
                int p = wn * 16 + ni * 8 + qt * 2;
                size_t o = ((size_t)b * SEQLEN + t0 + t) * DINNER + hh * HEADDIM + p;
                *(float2*)&g_y[o] = make_float2(accY[mi][ni][0], accY[mi][ni][1]);
                o += (size_t)8 * DINNER;
                *(float2*)&g_y[o] = make_float2(accY[mi][ni][2], accY[mi][ni][3]);
            }
    }

    // ---- GEMM5: Hc = Uw^T-form @ B  [64p x 128n], K=s=64 (A,B via trans) ----
    {
        float accH[2][4][4];
#pragma unroll
        for (int mi = 0; mi < 2; mi++)
#pragma unroll
            for (int ni = 0; ni < 4; ni++)
#pragma unroll
                for (int q = 0; q < 4; q++) accH[mi][ni][q] = 0.f;

#pragma unroll
        for (int k16 = 0; k16 < 4; k16++) {
            int kb = k16 * 16;
            uint32_t aH[2][4], aL[2][4], bH[4][2], bL[4][2];
#pragma unroll
            for (int mi = 0; mi < 2; mi++) {
                int row = kb + at_row;
                int col = wm * 32 + mi * 16 + at_col;
                uint32_t ad = swzb(row, col * 2);
                ldsm_x4_t(aH[mi][0], aH[mi][1], aH[mi][2], aH[mi][3], sb + OFF_UWH + ad);
                ldsm_x4_t(aL[mi][0], aL[mi][1], aL[mi][2], aL[mi][3], sb + OFF_UWL + ad);
            }
#pragma unroll
            for (int nj = 0; nj < 2; nj++) {
                int n0 = wn * 32 + nj * 16;
                int kp = n0 >> 6, ncol = n0 & 63;
                int row = kb + bt_row;
                int col = ncol + bt_col;
                uint32_t bd = kp * 8192u + swzb(row, col * 2);
                uint32_t r0, r1, r2, r3;
                ldsm_x4_t(r0, r1, r2, r3, sb + OFF_BPH + bd);
                bH[nj*2][0] = r0; bH[nj*2][1] = r1; bH[nj*2+1][0] = r2; bH[nj*2+1][1] = r3;
                ldsm_x4_t(r0, r1, r2, r3, sb + OFF_BPL + bd);
                bL[nj*2][0] = r0; bL[nj*2][1] = r1; bL[nj*2+1][0] = r2; bL[nj*2+1][1] = r3;
            }
#pragma unroll
            for (int mi = 0; mi < 2; mi++)
#pragma unroll
                for (int ni = 0; ni < 4; ni++) {
                    mma_bf16(accH[mi][ni], aH[mi], bH[ni][0], bH[ni][1]);
                    mma_bf16(accH[mi][ni], aH[mi], bL[ni][0], bL[ni][1]);
                    mma_bf16(accH[mi][ni], aL[mi], bH[ni][0], bH[ni][1]);
                }
        }
        float* hc = &g_hc[(((size_t)b * NHEADS + hh) * NCH + c) * (HEADDIM * DSTATE)];
#pragma unroll
        for (int mi = 0; mi < 2; mi++)
#pragma unroll
            for (int ni = 0; ni < 4; ni++) {
                int p = wm * 32 + mi * 16 + quad;
                int n = wn * 32 + ni * 8 + qt * 2;
                *(float2*)&hc[p * DSTATE + n] = make_float2(accH[mi][ni][0], accH[mi][ni][1]);
                *(float2*)&hc[(p + 8) * DSTATE + n] = make_float2(accH[mi][ni][2], accH[mi][ni][3]);
            }
    }
}

// =====================================================================
// SSD phase 2: inter-chunk state recurrence
// =====================================================================
__global__ __launch_bounds__(256)
void ssd_prop_kernel(const float* __restrict__ A_log)
{
    const int bh = blockIdx.x;
    const int hh = bh & (NHEADS - 1);
    const int tid = threadIdx.x;
    const float Ah = -expf(A_log[hh]);

    float4 acc[8];
#pragma unroll
    for (int j = 0; j < 8; j++) acc[j] = make_float4(0.f, 0.f, 0.f, 0.f);

    for (int c = 1; c < NCH; c++) {
        float Pi = expf(Ah * g_pi[(size_t)bh * NCH + c - 1]);
        const float4* hc = (const float4*)&g_hc[((size_t)bh * NCH + c - 1) * (HEADDIM * DSTATE)];
        float4* h0 = (float4*)&g_h0[((size_t)bh * NCH + c) * (HEADDIM * DSTATE)];
#pragma unroll
        for (int j = 0; j < 8; j++) {
            float4 v = hc[tid * 8 + j];
            acc[j].x = Pi * acc[j].x + v.x;
            acc[j].y = Pi * acc[j].y + v.y;
            acc[j].z = Pi * acc[j].z + v.z;
            acc[j].w = Pi * acc[j].w + v.w;
            h0[tid * 8 + j] = acc[j];
        }
    }
}

// =====================================================================
// SSD phase 3: carry  Y_t += r_t * (C_t @ h0)
// =====================================================================
#define C3_CPH 0u
#define C3_CPL 16384u
#define C3_H0H 32768u
#define C3_H0L 49152u
#define C3_SDT 65536u
#define C3_R   65792u
#define SMEM_SSD3 66560u

__global__ __launch_bounds__(256, 2)
void ssd_carry_kernel(const float* __restrict__ A_log)
{
    extern __shared__ __align__(1024) char smem[];
    const uint32_t sb = smem_u32(smem);
    const int c = blockIdx.x + 1, b = blockIdx.y, hh = blockIdx.z;
    const int tid = threadIdx.x;
    const int wid = tid >> 5, lane = tid & 31;
    const int wm = wid & 1, wn = wid >> 1;
    const int t0 = c * CLEN;
    const float Ah = -expf(A_log[hh]);

    float* s_sdt = (float*)(smem + C3_SDT);
    float* s_r   = (float*)(smem + C3_R);

    if (tid < 64)
        s_sdt[tid] = g_dt[((size_t)b * SEQLEN + t0 + tid) * NHEADS + hh];
    __syncthreads();
#pragma unroll
    for (int off = 1; off < 64; off <<= 1) {
        float v = 0.f;
        if (tid < 64 && tid >= off) v = s_sdt[tid - off];
        __syncthreads();
        if (tid < 64) s_sdt[tid] += v;
        __syncthreads();
    }
    if (tid < 64) s_r[tid] = expf(Ah * s_sdt[tid]);
    __syncthreads();

    const float* h0src = &g_h0[(((size_t)b * NHEADS + hh) * NCH + c) * (HEADDIM * DSTATE)];
#pragma unroll
    for (int i = 0; i < 8; i++) {
        int idx = tid + i * 256;
        int r = idx >> 5, n4 = idx & 31;
        int kp = n4 >> 4, cb = n4 & 15;
        uint32_t off = (uint32_t)kp * 8192u + (uint32_t)r * 128u
                     + ((((uint32_t)cb >> 1) ^ (r & 7)) << 4) + (cb & 1) * 8;
        {
            size_t row = ((size_t)b * SEQLEN + t0 + r) * CONVDIM;
            float4 v = *(const float4*)&g_xbc[row + DINNER + DSTATE + n4 * 4];
            __nv_bfloat16 h0b,l0,h1,l1,h2,l2,h3,l3;
            hilo(v.x,h0b,l0); hilo(v.y,h1,l1); hilo(v.z,h2,l2); hilo(v.w,h3,l3);
            *(__nv_bfloat162*)(smem + C3_CPH + off)     = __halves2bfloat162(h0b,h1);
            *(__nv_bfloat162*)(smem + C3_CPH + off + 4) = __halves2bfloat162(h2,h3);
            *(__nv_bfloat162*)(smem + C3_CPL + off)     = __halves2bfloat162(l0,l1);
            *(__nv_bfloat162*)(smem + C3_CPL + off + 4) = __halves2bfloat162(l2,l3);
        }
        {
            float4 v = *(const float4*)&h0src[r * DSTATE + n4 * 4];
            __nv_bfloat16 h0b,l0,h1,l1,h2,l2,h3,l3;
            hilo(v.x,h0b,l0); hilo(v.y,h1,l1); hilo(v.z,h2,l2); hilo(v.w,h3,l3);
            *(__nv_bfloat162*)(smem + C3_H0H + off)     = __halves2bfloat162(h0b,h1);
            *(__nv_bfloat162*)(smem + C3_H0H + off + 4) = __halves2bfloat162(h2,h3);
            *(__nv_bfloat162*)(smem + C3_H0L + off)     = __halves2bfloat162(l0,l1);
            *(__nv_bfloat162*)(smem + C3_H0L + off + 4) = __halves2bfloat162(l2,l3);
        }
    }
    __syncthreads();

    const int lgrp = lane >> 3, lr = lane & 7;
    const int a_roff = lr + (lgrp & 1) * 8;
    const int a_koff = lgrp >> 1;
    const int b_roff = lr + (lgrp >> 1) * 8;
    const int b_koff = lgrp & 1;
    const int quad = lane >> 2, qt = lane & 3;

    float acc[2][2][4];
#pragma unroll
    for (int mi = 0; mi < 2; mi++)
#pragma unroll
        for (int ni = 0; ni < 2; ni++)
#pragma unroll
            for (int q = 0; q < 4; q++) acc[mi][ni][q] = 0.f;

#pragma unroll
    for (int kp = 0; kp < 2; kp++) {
#pragma unroll
        for (int k16 = 0; k16 < 4; k16++) {
            int k2 = k16 * 2;
            uint32_t aH[2][4], aL[2][4], bH[2][2], bL[2][2];
#pragma unroll
            for (int mi = 0; mi < 2; mi++) {
                int row = wm * 32 + mi * 16 + a_roff;
                uint32_t ad = kp * 8192u + swz(row, k2 + a_koff);
                ldsm_x4(aH[mi][0], aH[mi][1], aH[mi][2], aH[mi][3], sb + C3_CPH + ad);
                ldsm_x4(aL[mi][0], aL[mi][1], aL[mi][2], aL[mi][3], sb + C3_CPL + ad);
            }
            {
                int row = wn * 16 + b_roff;
                uint32_t bd = kp * 8192u + swz(row, k2 + b_koff);
                uint32_t r0, r1, r2, r3;
                ldsm_x4(r0, r1, r2, r3, sb + C3_H0H + bd);
                bH[0][0] = r0; bH[0][1] = r1; bH[1][0] = r2; bH[1][1] = r3;
                ldsm_x4(r0, r1, r2, r3, sb + C3_H0L + bd);
                bL[0][0] = r0; bL[0][1] = r1; bL[1][0] = r2; bL[1][1] = r3;
            }
#pragma unroll
            for (int mi = 0; mi < 2; mi++)
#pragma unroll
                for (int ni = 0; ni < 2; ni++) {
                    mma_bf16(acc[mi][ni], aH[mi], bH[ni][0], bH[ni][1]);
                    mma_bf16(acc[mi][ni], aH[mi], bL[ni][0], bL[ni][1]);
                    mma_bf16(acc[mi][ni], aL[mi], bH[ni][0], bH[ni][1]);
                }
        }
    }

#pragma unroll
    for (int mi = 0; mi < 2; mi++)
#pragma unroll
        for (int ni = 0; ni < 2; ni++) {
            int t = wm * 32 + mi * 16 + quad;
            int p = wn * 16 + ni * 8 + qt * 2;
            {
                float rt = s_r[t];
                size_t o = ((size_t)b * SEQLEN + t0 + t) * DINNER + hh * HEADDIM + p;
                float2 v = *(float2*)&g_y[o];
                v.x += rt * acc[mi][ni][0];
                v.y += rt * acc[mi][ni][1];
                *(float2*)&g_y[o] = v;
            }
            {
                float rt = s_r[t + 8];
                size_t o = ((size_t)b * SEQLEN + t0 + t + 8) * DINNER + hh * HEADDIM + p;
                float2 v = *(float2*)&g_y[o];
                v.x += rt * acc[mi][ni][2];
                v.y += rt * acc[mi][ni][3];
                *(float2*)&g_y[o] = v;
            }
        }
}

// =====================================================================
// skip + gate + RMSNorm -> bf16 hi/lo
// =====================================================================
__global__ __launch_bounds__(256)
void gate_norm_kernel(const float* __restrict__ Dw, const float* __restrict__ norm_w)
{
    const int t = blockIdx.x;
    const int b = blockIdx.y;
    const size_t row = (size_t)b * SEQLEN + t;
    const float4* __restrict__ z4 = (const float4*)&g_zx [row * DINPROJ];
    const float4* __restrict__ x4 = (const float4*)&g_xbc[row * CONVDIM];
    const float4* __restrict__ y4 = (const float4*)&g_y  [row * DINNER];

    float4 vals[2];
    float ss = 0.f;
#pragma unroll
    for (int r = 0; r < 2; r++) {
        int f = r * 256 + threadIdx.x;
        float dv = Dw[f >> 4];
        float4 a = y4[f], xv = x4[f], zv = z4[f];
        float4 v;
        v.x = a.x + dv * xv.x;
        v.y = a.y + dv * xv.y;
        v.z = a.z + dv * xv.z;
        v.w = a.w + dv * xv.w;
        v.x *= zv.x / (1.f + expf(-zv.x));
        v.y *= zv.y / (1.f + expf(-zv.y));
        v.z *= zv.z / (1.f + expf(-zv.z));
        v.w *= zv.w / (1.f + expf(-zv.w));
        vals[r] = v;
        ss += v.x * v.x + v.y * v.y + v.z * v.z + v.w * v.w;
    }
    __shared__ float red[256];
    red[threadIdx.x] = ss;
    __syncthreads();
    for (int off = 128; off > 0; off >>= 1) {
        if (threadIdx.x < off) red[threadIdx.x] += red[threadIdx.x + off];
        __syncthreads();
    }
    float scale = rsqrtf(red[0] / (float)DINNER + EPS);
    __nv_bfloat162* outh = (__nv_bfloat162*)&g_ynh[row * DINNER];
    __nv_bfloat162* outl = (__nv_bfloat162*)&g_ynl[row * DINNER];
    const float4* nw4 = (const float4*)norm_w;
#pragma unroll
    for (int r = 0; r < 2; r++) {
        int f = r * 256 + threadIdx.x;
        float4 w = nw4[f];
        float4 v = vals[r];
        v.x *= scale * w.x; v.y *= scale * w.y; v.z *= scale * w.z; v.w *= scale * w.w;
        split4(v, outh, outl, f);
    }
}

// =====================================================================
extern "C" void kernel_launch(void* const* d_in, const int* in_sizes, int n_in,
                              void* d_out, int out_size)
{
    const float* x          = (const float*)d_in[0];
    const float* in_proj_w  = (const float*)d_in[1];
    const float* conv_w     = (const float*)d_in[2];
    const float* conv_b     = (const float*)d_in[3];
    const float* dt_bias    = (const float*)d_in[4];
    const float* A_log      = (const float*)d_in[5];
    const float* Dw         = (const float*)d_in[6];
    const float* norm_w     = (const float*)d_in[7];
    const float* out_proj_w = (const float*)d_in[8];
    float* out = (float*)d_out;

    float *p_zx = nullptr;
    void *p_xh, *p_xl, *p_w1h, *p_w1l, *p_w2h, *p_w2l, *p_ynh, *p_ynl;
    cudaGetSymbolAddress((void**)&p_zx, g_zx);
    cudaGetSymbolAddress(&p_xh,  g_xh);  cudaGetSymbolAddress(&p_xl,  g_xl);
    cudaGetSymbolAddress(&p_w1h, g_w1h); cudaGetSymbolAddress(&p_w1l, g_w1l);
    cudaGetSymbolAddress(&p_w2h, g_w2h); cudaGetSymbolAddress(&p_w2l, g_w2l);
    cudaGetSymbolAddress(&p_ynh, g_ynh); cudaGetSymbolAddress(&p_ynl, g_ynl);

    cudaFuncSetAttribute(gemm_mma<false>, cudaFuncAttributeMaxDynamicSharedMemorySize, SMEM_GEMM);
    cudaFuncSetAttribute(gemm_mma<true>,  cudaFuncAttributeMaxDynamicSharedMemorySize, SMEM_GEMM);
    cudaFuncSetAttribute(ssd_chunk_kernel, cudaFuncAttributeMaxDynamicSharedMemorySize, SMEM_SSD1);
    cudaFuncSetAttribute(ssd_carry_kernel, cudaFuncAttributeMaxDynamicSharedMemorySize, SMEM_SSD3);

    // 0) fp32 -> bf16 hi/lo conversions
    {
        int total4 = N4_X + N4_W1 + N4_W2;
        cvt_all<<<(total4 + 255)/256, 256>>>(
            (const float4*)x, (const float4*)in_proj_w, (const float4*)out_proj_w);
    }

    // 1) zxbcdt = x @ in_proj_w^T
    gemm_mma<false><<<dim3((DINPROJ + BN - 1)/BN, ROWS/BM), 256, SMEM_GEMM>>>(
        (const __nv_bfloat16*)p_xh, (const __nv_bfloat16*)p_xl,
        (const __nv_bfloat16*)p_w1h, (const __nv_bfloat16*)p_w1l,
        nullptr, p_zx, DINPROJ, DMODEL);

    // 2) conv + SiLU; dt softplus
    conv_act_kernel<<<dim3(CONVDIM/256, SEQLEN/4, BATCH), 256>>>(conv_w, conv_b, dt_bias);

    // 3) SSD scan
    ssd_chunk_kernel<<<dim3(NCH, BATCH, NHEADS), 256, SMEM_SSD1>>>(A_log);
    ssd_prop_kernel<<<BATCH * NHEADS, 256>>>(A_log);
    ssd_carry_kernel<<<dim3(NCH - 1, BATCH, NHEADS), 256, SMEM_SSD3>>>(A_log);

    // 4) skip + gate + RMSNorm
    gate_norm_kernel<<<dim3(SEQLEN, BATCH), 256>>>(Dw, norm_w);

    // 5) out = x + yn @ out_proj_w^T
    gemm_mma<true><<<dim3(DMODEL/BN, ROWS/BM), 256, SMEM_GEMM>>>(
        (const __nv_bfloat16*)p_ynh, (const __nv_bfloat16*)p_ynl,
        (const __nv_bfloat16*)p_w2h, (const __nv_bfloat16*)p_w2l,
        x, out, DMODEL, DINNER);
}

// round 10
// speedup vs baseline: 1.0639x; 1.0639x over previous
#include <cuda_runtime.h>
#include <cuda_bf16.h>
#include <math.h>
#include <stdint.h>

// ---------------- problem constants ----------------
#define BATCH    2
#define SEQLEN   1024
#define DMODEL   1024
#define DINNER   2048
#define NHEADS   32
#define HEADDIM  64
#define DSTATE   128
#define DCONV    4
#define CONVDIM  2304
#define DINPROJ  4384
#define ROWS     (BATCH*SEQLEN)
#define EPS      1e-5f
#define CLEN     64
#define NCH      (SEQLEN/CLEN)     // 16 chunks

// ---------------- scratch ----------------
__device__ __align__(1024) float g_zx [ROWS*DINPROJ];
__device__ __align__(1024) float g_xbc[ROWS*CONVDIM];
__device__ __align__(1024) float g_dt [ROWS*NHEADS];
__device__ __align__(1024) float g_y  [ROWS*DINNER];
__device__ __align__(1024) float g_hc [BATCH*NHEADS*NCH*HEADDIM*DSTATE];
__device__ __align__(1024) float g_h0 [BATCH*NHEADS*NCH*HEADDIM*DSTATE];
__device__ __align__(1024) float g_pi [BATCH*NHEADS*NCH];
// pre-swizzled bf16 hi/lo B and C panel tiles: [b][chunk][kp] x 4096 bf16 (8KB)
#define PTILES (BATCH*NCH*2)
__device__ __align__(1024) __nv_bfloat16 g_pBh[PTILES*4096];
__device__ __align__(1024) __nv_bfloat16 g_pBl[PTILES*4096];
__device__ __align__(1024) __nv_bfloat16 g_pCh[PTILES*4096];
__device__ __align__(1024) __nv_bfloat16 g_pCl[PTILES*4096];
__device__ __align__(1024) __nv_bfloat16 g_xh [ROWS*DMODEL];
__device__ __align__(1024) __nv_bfloat16 g_xl [ROWS*DMODEL];
__device__ __align__(1024) __nv_bfloat16 g_w1h[DINPROJ*DMODEL];
__device__ __align__(1024) __nv_bfloat16 g_w1l[DINPROJ*DMODEL];
__device__ __align__(1024) __nv_bfloat16 g_w2h[DMODEL*DINNER];
__device__ __align__(1024) __nv_bfloat16 g_w2l[DMODEL*DINNER];
__device__ __align__(1024) __nv_bfloat16 g_ynh[ROWS*DINNER];
__device__ __align__(1024) __nv_bfloat16 g_ynl[ROWS*DINNER];

// ---------------- primitives ----------------
__device__ __forceinline__ uint32_t smem_u32(const void* p) {
    uint32_t a;
    asm("{ .reg .u64 t; cvta.to.shared.u64 t, %1; cvt.u32.u64 %0, t; }" : "=r"(a) : "l"(p));
    return a;
}
__device__ __forceinline__ void cp16(uint32_t dst, const void* src) {
    asm volatile("cp.async.cg.shared.global [%0], [%1], 16;" :: "r"(dst), "l"(src));
}
__device__ __forceinline__ void cp_commit() { asm volatile("cp.async.commit_group;" ::: "memory"); }
template<int W> __device__ __forceinline__ void cp_wait() {
    asm volatile("cp.async.wait_group %0;" :: "n"(W) : "memory");
}
__device__ __forceinline__ void ldsm_x4(uint32_t& r0, uint32_t& r1, uint32_t& r2, uint32_t& r3, uint32_t a) {
    asm volatile("ldmatrix.sync.aligned.m8n8.x4.shared.b16 {%0,%1,%2,%3}, [%4];"
                 : "=r"(r0), "=r"(r1), "=r"(r2), "=r"(r3) : "r"(a));
}
__device__ __forceinline__ void ldsm_x4_t(uint32_t& r0, uint32_t& r1, uint32_t& r2, uint32_t& r3, uint32_t a) {
    asm volatile("ldmatrix.sync.aligned.m8n8.x4.trans.shared.b16 {%0,%1,%2,%3}, [%4];"
                 : "=r"(r0), "=r"(r1), "=r"(r2), "=r"(r3) : "r"(a));
}
__device__ __forceinline__ void mma_bf16(float* c, const uint32_t* a, uint32_t b0, uint32_t b1) {
    asm volatile(
        "mma.sync.aligned.m16n8k16.row.col.f32.bf16.bf16.f32 "
        "{%0,%1,%2,%3}, {%4,%5,%6,%7}, {%8,%9}, {%0,%1,%2,%3};"
        : "+f"(c[0]), "+f"(c[1]), "+f"(c[2]), "+f"(c[3])
        : "r"(a[0]), "r"(a[1]), "r"(a[2]), "r"(a[3]), "r"(b0), "r"(b1));
}
__device__ __forceinline__ uint32_t swz(int row, int seg) {
    return (uint32_t)(row * 128 + ((seg ^ (row & 7)) << 4));
}
__device__ __forceinline__ uint32_t swzb(int row, int colb) {
    return (uint32_t)(row * 128 + (((colb >> 4) ^ (row & 7)) << 4) + (colb & 15));
}
__device__ __forceinline__ void hilo(float v, __nv_bfloat16& h, __nv_bfloat16& l) {
    h = __float2bfloat16(v);
    l = __float2bfloat16(v - __bfloat162float(h));
}

// =====================================================================
// Tensor-core GEMM (R8 version: BM128/BN128, 3-stage, 1 CTA/SM)
// =====================================================================
#define BM 128
#define BN 128
#define KC 64
#define TILE_B   16384u
#define STAGE_B  (4u*TILE_B)
#define NSTAGE   3
#define SMEM_GEMM (NSTAGE*STAGE_B)

template<bool RES>
__global__ __launch_bounds__(256, 1)
void gemm_mma(const __nv_bfloat16* __restrict__ Ahp, const __nv_bfloat16* __restrict__ Alp,
              const __nv_bfloat16* __restrict__ Bhp, const __nv_bfloat16* __restrict__ Blp,
              const float* __restrict__ resid, float* __restrict__ C,
              int N, int K)
{
    extern __shared__ __align__(1024) char smem[];
    const uint32_t sb = smem_u32(smem);

    const int tid = threadIdx.x;
    const int wid = tid >> 5, lane = tid & 31;
    const int wm = wid & 1, wn = wid >> 1;
    const int m0 = blockIdx.y * BM, n0 = blockIdx.x * BN;
    const int NC = K / KC;

    int lrow[4], lseg[4];
#pragma unroll
    for (int it = 0; it < 4; it++) {
        int idx = tid + it * 256;
        lrow[it] = idx >> 3;
        lseg[it] = idx & 7;
    }

    auto load_chunk = [&](int stage, int k0) {
        uint32_t s = sb + stage * STAGE_B;
#pragma unroll
        for (int it = 0; it < 4; it++) {
            int row = lrow[it], seg = lseg[it];
            uint32_t d = swz(row, seg);
            size_t aoff = (size_t)(m0 + row) * K + k0 + seg * 8;
            cp16(s + d,              Ahp + aoff);
            cp16(s + TILE_B + d,     Alp + aoff);
            int brow = n0 + row; if (brow >= N) brow = N - 1;
            size_t boff = (size_t)brow * K + k0 + seg * 8;
            cp16(s + 2 * TILE_B + d, Bhp + boff);
            cp16(s + 3 * TILE_B + d, Blp + boff);
        }
        cp_commit();
    };

    float acc[4][4][4];
#pragma unroll
    for (int mi = 0; mi < 4; mi++)
#pragma unroll
        for (int ni = 0; ni < 4; ni++)
#pragma unroll
            for (int q = 0; q < 4; q++) acc[mi][ni][q] = 0.f;

    const int lgrp = lane >> 3, lr = lane & 7;
    const int a_roff = lr + (lgrp & 1) * 8;
    const int a_koff = lgrp >> 1;
    const int b_roff = lr + (lgrp >> 1) * 8;
    const int b_koff = lgrp & 1;

    load_chunk(0, 0);
    load_chunk(1, KC);

    for (int c = 0; c < NC; c++) {
        if (c + 2 < NC) load_chunk((c + 2) % NSTAGE, (c + 2) * KC);
        else            cp_commit();
        cp_wait<2>();
        __syncthreads();

        uint32_t s = sb + (c % NSTAGE) * STAGE_B;
#pragma unroll
        for (int k16 = 0; k16 < 4; k16++) {
            int k2 = k16 * 2;
            uint32_t ah[4][4], al[4][4], bh[4][2], bl[4][2];
#pragma unroll
            for (int mi = 0; mi < 4; mi++) {
                int row = wm * 64 + mi * 16 + a_roff;
                uint32_t ad = swz(row, k2 + a_koff);
                ldsm_x4(ah[mi][0], ah[mi][1], ah[mi][2], ah[mi][3], s + ad);
                ldsm_x4(al[mi][0], al[mi][1], al[mi][2], al[mi][3], s + TILE_B + ad);
            }
#pragma unroll
            for (int nj = 0; nj < 2; nj++) {
                int row = wn * 32 + nj * 16 + b_roff;
                uint32_t bd = swz(row, k2 + b_koff);
                uint32_t r0, r1, r2, r3;
                ldsm_x4(r0, r1, r2, r3, s + 2 * TILE_B + bd);
                bh[nj * 2][0] = r0; bh[nj * 2][1] = r1;
                bh[nj * 2 + 1][0] = r2; bh[nj * 2 + 1][1] = r3;
                ldsm_x4(r0, r1, r2, r3, s + 3 * TILE_B + bd);
                bl[nj * 2][0] = r0; bl[nj * 2][1] = r1;
                bl[nj * 2 + 1][0] = r2; bl[nj * 2 + 1][1] = r3;
            }
#pragma unroll
            for (int mi = 0; mi < 4; mi++)
#pragma unroll
                for (int ni = 0; ni < 4; ni++) {
                    mma_bf16(acc[mi][ni], ah[mi], bh[ni][0], bh[ni][1]);
                    mma_bf16(acc[mi][ni], ah[mi], bl[ni][0], bl[ni][1]);
                    mma_bf16(acc[mi][ni], al[mi], bh[ni][0], bh[ni][1]);
                }
        }
        __syncthreads();
    }

    const int quad = lane >> 2, qt = lane & 3;
#pragma unroll
    for (int mi = 0; mi < 4; mi++) {
#pragma unroll
        for (int ni = 0; ni < 4; ni++) {
            int gm = m0 + wm * 64 + mi * 16 + quad;
            int gn = n0 + wn * 32 + ni * 8 + qt * 2;
            if (gn < N) {
                {
                    float2 v = make_float2(acc[mi][ni][0], acc[mi][ni][1]);
                    size_t o = (size_t)gm * N + gn;
                    if (RES) { float2 rv = *(const float2*)(resid + o); v.x += rv.x; v.y += rv.y; }
                    *(float2*)(C + o) = v;
                }
                {
                    float2 v = make_float2(acc[mi][ni][2], acc[mi][ni][3]);
                    size_t o = (size_t)(gm + 8) * N + gn;
                    if (RES) { float2 rv = *(const float2*)(resid + o); v.x += rv.x; v.y += rv.y; }
                    *(float2*)(C + o) = v;
                }
            }
        }
    }
}

// =====================================================================
// merged fp32 -> bf16 hi/lo split
// =====================================================================
#define N4_X  (ROWS*DMODEL/4)
#define N4_W1 (DINPROJ*DMODEL/4)
#define N4_W2 (DMODEL*DINNER/4)

__device__ __forceinline__ void split4(float4 v, __nv_bfloat162* hi, __nv_bfloat162* lo, int i) {
    __nv_bfloat16 hx, lx, hy, ly, hz, lz, hw, lw;
    hilo(v.x, hx, lx); hilo(v.y, hy, ly); hilo(v.z, hz, lz); hilo(v.w, hw, lw);
    hi[i * 2]     = __halves2bfloat162(hx, hy);
    hi[i * 2 + 1] = __halves2bfloat162(hz, hw);
    lo[i * 2]     = __halves2bfloat162(lx, ly);
    lo[i * 2 + 1] = __halves2bfloat162(lz, lw);
}

__global__ __launch_bounds__(256)
void cvt_all(const float4* __restrict__ x, const float4* __restrict__ w1,
             const float4* __restrict__ w2)
{
    int i = blockIdx.x * 256 + threadIdx.x;
    if (i < N4_X) {
        split4(x[i], (__nv_bfloat162*)g_xh, (__nv_bfloat162*)g_xl, i);
    } else if (i < N4_X + N4_W1) {
        int j = i - N4_X;
        split4(w1[j], (__nv_bfloat162*)g_w1h, (__nv_bfloat162*)g_w1l, j);
    } else if (i < N4_X + N4_W1 + N4_W2) {
        int j = i - N4_X - N4_W1;
        split4(w2[j], (__nv_bfloat162*)g_w2h, (__nv_bfloat162*)g_w2l, j);
    }
}

// =====================================================================
// Causal depthwise conv + SiLU; dt softplus
// =====================================================================
__global__ __launch_bounds__(256)
void conv_act_kernel(const float* __restrict__ conv_w, const float* __restrict__ conv_b,
                     const float* __restrict__ dt_bias)
{
    const int c  = blockIdx.x * 256 + threadIdx.x;
    const int tb = blockIdx.y * 4;
    const int b  = blockIdx.z;

    float w0 = conv_w[c * 4 + 0], w1 = conv_w[c * 4 + 1];
    float w2 = conv_w[c * 4 + 2], w3 = conv_w[c * 4 + 3];
    float bias = conv_b[c];

    float v[7];
#pragma unroll
    for (int k = 0; k < 7; k++) {
        int tt = tb - 3 + k;
        v[k] = (tt >= 0) ? g_zx[((size_t)b * SEQLEN + tt) * DINPROJ + DINNER + c] : 0.f;
    }
#pragma unroll
    for (int i = 0; i < 4; i++) {
        float a = bias + v[i] * w0 + v[i + 1] * w1 + v[i + 2] * w2 + v[i + 3] * w3;
        g_xbc[((size_t)b * SEQLEN + tb + i) * CONVDIM + c] = a / (1.f + expf(-a));
    }
    if (blockIdx.x == 0 && threadIdx.x < NHEADS) {
        int hh = threadIdx.x;
        float bth = dt_bias[hh];
#pragma unroll
        for (int i = 0; i < 4; i++) {
            size_t row = (size_t)b * SEQLEN + tb + i;
            float raw = g_zx[row * DINPROJ + (DINNER + CONVDIM) + hh] + bth;
            g_dt[row * NHEADS + hh] = (raw > 20.f) ? raw : log1pf(expf(raw));
        }
    }
}

// =====================================================================
// pack B/C into pre-swizzled bf16 hi/lo tiles (shared by all heads)
// one thread per 16-byte unit: u = [isC][b][chunk][kp][t][s]
// =====================================================================
__global__ __launch_bounds__(256)
void pack_bc_kernel()
{
    int u = blockIdx.x * 256 + threadIdx.x;      // 131072 total
    int s   = u & 7;
    int t   = (u >> 3) & 63;
    int kp  = (u >> 9) & 1;
    int ch  = (u >> 10) & 15;
    int b   = (u >> 14) & 1;
    int isC = (u >> 15);

    size_t src = ((size_t)b * SEQLEN + ch * 64 + t) * CONVDIM
               + DINNER + (isC ? DSTATE : 0) + kp * 64 + s * 8;
    float4 v0 = *(const float4*)&g_xbc[src];
    float4 v1 = *(const float4*)&g_xbc[src + 4];

    __nv_bfloat16 h[8], l[8];
    hilo(v0.x, h[0], l[0]); hilo(v0.y, h[1], l[1]);
    hilo(v0.z, h[2], l[2]); hilo(v0.w, h[3], l[3]);
    hilo(v1.x, h[4], l[4]); hilo(v1.y, h[5], l[5]);
    hilo(v1.z, h[6], l[6]); hilo(v1.w, h[7], l[7]);

    __nv_bfloat162 ph[4], pl[4];
#pragma unroll
    for (int j = 0; j < 4; j++) {
        ph[j] = __halves2bfloat162(h[j * 2], h[j * 2 + 1]);
        pl[j] = __halves2bfloat162(l[j * 2], l[j * 2 + 1]);
    }

    size_t off = (size_t)(((b * NCH + ch) * 2) + kp) * 4096 + t * 64 + ((s ^ (t & 7)) * 8);
    __nv_bfloat16* dh = (isC ? g_pCh : g_pBh) + off;
    __nv_bfloat16* dl = (isC ? g_pCl : g_pBl) + off;
    *(uint4*)dh = *(uint4*)ph;
    *(uint4*)dl = *(uint4*)pl;
}

// =====================================================================
// SSD phase 1: B/C panels cp.async'd from packed global (overlapped with
// dt scan + U conversion); G overlays C panels after GEMM2.
// =====================================================================
#define OFF_CPH 0u
#define OFF_CPL 16384u
#define OFF_BPH 32768u
#define OFF_BPL 49152u
#define OFF_UTH 65536u
#define OFF_UTL 73728u
#define OFF_UWH 81920u
#define OFF_UWL 90112u
#define OFF_GH  OFF_CPH
#define OFF_GL  (OFF_CPH + 8192u)
#define OFF_SDT 98304u
#define OFF_DTS 98560u
#define OFF_WS  98816u
#define SMEM_SSD1 99072u

__global__ __launch_bounds__(256, 2)
void ssd_chunk_kernel(const float* __restrict__ A_log)
{
    extern __shared__ __align__(1024) char smem[];
    const uint32_t sb = smem_u32(smem);
    const int c = blockIdx.x, b = blockIdx.y, hh = blockIdx.z;
    const int tid = threadIdx.x;
    const int wid = tid >> 5, lane = tid & 31;
    const int wm = wid & 1, wn = wid >> 1;
    const int t0 = c * CLEN;
    const float Ah = -expf(A_log[hh]);

    // ---- stage B/C panels via cp.async (16KB contiguous per region) ----
    {
        size_t tb = (size_t)((b * NCH + c) * 2) * 4096;
#pragma unroll
        for (int i = 0; i < 4; i++) {
            int idx = tid + i * 256;             // 1024 16B units per region
            cp16(sb + OFF_BPH + idx * 16, g_pBh + tb + idx * 8);
            cp16(sb + OFF_BPL + idx * 16, g_pBl + tb + idx * 8);
            cp16(sb + OFF_CPH + idx * 16, g_pCh + tb + idx * 8);
            cp16(sb + OFF_CPL + idx * 16, g_pCl + tb + idx * 8);
        }
        cp_commit();
    }

    float* s_sdt = (float*)(smem + OFF_SDT);
    float* s_dt  = (float*)(smem + OFF_DTS);
    float* s_w   = (float*)(smem + OFF_WS);

    // ---- dt load + inclusive scan (overlaps cp.async) ----
    if (tid < 64) {
        float d = g_dt[((size_t)b * SEQLEN + t0 + tid) * NHEADS + hh];
        s_dt[tid] = d;
        s_sdt[tid] = d;
    }
    __syncthreads();
#pragma unroll
    for (int off = 1; off < 64; off <<= 1) {
        float v = 0.f;
        if (tid < 64 && tid >= off) v = s_sdt[tid - off];
        __syncthreads();
        if (tid < 64) s_sdt[tid] += v;
        __syncthreads();
    }
    float sdtTOT = s_sdt[63];
    if (tid < 64) s_w[tid] = expf(Ah * (sdtTOT - s_sdt[tid]));
    if (tid == 0) g_pi[((size_t)b * NHEADS + hh) * NCH + c] = sdtTOT;
    __syncthreads();

    // ---- convert U = dt*x and Uw = w*U (head-specific) ----
#pragma unroll
    for (int i = 0; i < 4; i++) {
        int idx = tid + i * 256;
        int t = idx >> 4, p4 = idx & 15;
        size_t row = ((size_t)b * SEQLEN + t0 + t) * CONVDIM;
        float4 xv = *(const float4*)&g_xbc[row + hh * HEADDIM + p4 * 4];
        float dtv = s_dt[t], wv = s_w[t];
        float u0 = dtv*xv.x, u1 = dtv*xv.y, u2 = dtv*xv.z, u3 = dtv*xv.w;
        uint32_t off = swzb(t, p4 * 8);
        __nv_bfloat16 h0,l0,h1,l1,h2,l2,h3,l3;
        hilo(u0,h0,l0); hilo(u1,h1,l1); hilo(u2,h2,l2); hilo(u3,h3,l3);
        *(__nv_bfloat162*)(smem + OFF_UTH + off)     = __halves2bfloat162(h0,h1);
        *(__nv_bfloat162*)(smem + OFF_UTH + off + 4) = __halves2bfloat162(h2,h3);
        *(__nv_bfloat162*)(smem + OFF_UTL + off)     = __halves2bfloat162(l0,l1);
        *(__nv_bfloat162*)(smem + OFF_UTL + off + 4) = __halves2bfloat162(l2,l3);
        hilo(u0*wv,h0,l0); hilo(u1*wv,h1,l1); hilo(u2*wv,h2,l2); hilo(u3*wv,h3,l3);
        *(__nv_bfloat162*)(smem + OFF_UWH + off)     = __halves2bfloat162(h0,h1);
        *(__nv_bfloat162*)(smem + OFF_UWH + off + 4) = __halves2bfloat162(h2,h3);
        *(__nv_bfloat162*)(smem + OFF_UWL + off)     = __halves2bfloat162(l0,l1);
        *(__nv_bfloat162*)(smem + OFF_UWL + off + 4) = __halves2bfloat162(l2,l3);
    }
    cp_wait<0>();
    __syncthreads();

    const int lgrp = lane >> 3, lr = lane & 7;
    const int a_roff = lr + (lgrp & 1) * 8;
    const int a_koff = lgrp >> 1;
    const int b_roff = lr + (lgrp >> 1) * 8;
    const int b_koff = lgrp & 1;
    const int quad = lane >> 2, qt = lane & 3;
    const int bt_row = lr + (lgrp & 1) * 8;
    const int bt_col = (lgrp >> 1) * 8;
    const int at_row = lr + (lgrp >> 1) * 8;
    const int at_col = (lgrp & 1) * 8;

    // ---- GEMM2: G = C @ B^T   [64t x 64s], K=n=128 ----
    float accG[2][2][4];
#pragma unroll
    for (int mi = 0; mi < 2; mi++)
#pragma unroll
        for (int ni = 0; ni < 2; ni++)
#pragma unroll
            for (int q = 0; q < 4; q++) accG[mi][ni][q] = 0.f;

#pragma unroll
    for (int kp = 0; kp < 2; kp++) {
#pragma unroll
        for (int k16 = 0; k16 < 4; k16++) {
            int k2 = k16 * 2;
            uint32_t aH[2][4], aL[2][4], bH[2][2], bL[2][2];
#pragma unroll
            for (int mi = 0; mi < 2; mi++) {
                int row = wm * 32 + mi * 16 + a_roff;
                uint32_t ad = kp * 8192u + swz(row, k2 + a_koff);
                ldsm_x4(aH[mi][0], aH[mi][1], aH[mi][2], aH[mi][3], sb + OFF_CPH + ad);
                ldsm_x4(aL[mi][0], aL[mi][1], aL[mi][2], aL[mi][3], sb + OFF_CPL + ad);
            }
            {
                int row = wn * 16 + b_roff;
                uint32_t bd = kp * 8192u + swz(row, k2 + b_koff);
                uint32_t r0, r1, r2, r3;
                ldsm_x4(r0, r1, r2, r3, sb + OFF_BPH + bd);
                bH[0][0] = r0; bH[0][1] = r1; bH[1][0] = r2; bH[1][1] = r3;
                ldsm_x4(r0, r1, r2, r3, sb + OFF_BPL + bd);
                bL[0][0] = r0; bL[0][1] = r1; bL[1][0] = r2; bL[1][1] = r3;
            }
#pragma unroll
            for (int mi = 0; mi < 2; mi++)
#pragma unroll
                for (int ni = 0; ni < 2; ni++) {
                    mma_bf16(accG[mi][ni], aH[mi], bH[ni][0], bH[ni][1]);
                    mma_bf16(accG[mi][ni], aH[mi], bL[ni][0], bL[ni][1]);
                    mma_bf16(accG[mi][ni], aL[mi], bH[ni][0], bH[ni][1]);
                }
        }
    }
    __syncthreads();   // done reading C panels before G overlays them

#pragma unroll
    for (int mi = 0; mi < 2; mi++)
#pragma unroll
        for (int ni = 0; ni < 2; ni++)
#pragma unroll
            for (int half = 0; half < 2; half++) {
                int t = wm * 32 + mi * 16 + quad + half * 8;
                int s = wn * 16 + ni * 8 + qt * 2;
                float sdt_t = s_sdt[t];
                float v0 = accG[mi][ni][half * 2 + 0];
                float v1 = accG[mi][ni][half * 2 + 1];
                v0 = (t >= s)     ? v0 * expf(Ah * (sdt_t - s_sdt[s]))     : 0.f;
                v1 = (t >= s + 1) ? v1 * expf(Ah * (sdt_t - s_sdt[s + 1])) : 0.f;
                __nv_bfloat16 h0,l0,h1,l1;
                hilo(v0,h0,l0); hilo(v1,h1,l1);
                uint32_t off = swzb(t, s * 2);
                *(__nv_bfloat162*)(smem + OFF_GH + off) = __halves2bfloat162(h0,h1);
                *(__nv_bfloat162*)(smem + OFF_GL + off) = __halves2bfloat162(l0,l1);
            }
    __syncthreads();

    // ---- GEMM4: Y = G @ U  [64t x 64p], K=s=64 ----
    {
        float accY[2][2][4];
#pragma unroll
        for (int mi = 0; mi < 2; mi++)
#pragma unroll
            for (int ni = 0; ni < 2; ni++)
#pragma unroll
                for (int q = 0; q < 4; q++) accY[mi][ni][q] = 0.f;

#pragma unroll
        for (int k16 = 0; k16 < 4; k16++) {
            int k2 = k16 * 2, kb = k16 * 16;
            uint32_t aH[2][4], aL[2][4], bH[2][2], bL[2][2];
#pragma unroll
            for (int mi = 0; mi < 2; mi++) {
                int row = wm * 32 + mi * 16 + a_roff;
                uint32_t ad = swz(row, k2 + a_koff);
                ldsm_x4(aH[mi][0], aH[mi][1], aH[mi][2], aH[mi][3], sb + OFF_GH + ad);
                ldsm_x4(aL[mi][0], aL[mi][1], aL[mi][2], aL[mi][3], sb + OFF_GL + ad);
            }
            {
                int row = kb + bt_row;
                int col = wn * 16 + bt_col;
                uint32_t bd = swzb(row, col * 2);
                uint32_t r0, r1, r2, r3;
                ldsm_x4_t(r0, r1, r2, r3, sb + OFF_UTH + bd);
                bH[0][0] = r0; bH[0][1] = r1; bH[1][0] = r2; bH[1][1] = r3;
                ldsm_x4_t(r0, r1, r2, r3, sb + OFF_UTL + bd);
                bL[0][0] = r0; bL[0][1] = r1; bL[1][0] = r2; bL[1][1] = r3;
            }
#pragma unroll
            for (int mi = 0; mi < 2; mi++)
#pragma unroll
                for (int ni = 0; ni < 2; ni++) {
                    mma_bf16(accY[mi][ni], aH[mi], bH[ni][0], bH[ni][1]);
                    mma_bf16(accY[mi][ni], aH[mi], bL[ni][0], bL[ni][1]);
                    mma_bf16(accY[mi][ni], aL[mi], bH[ni][0], bH[ni][1]);
                }
        }
#pragma unroll
        for (int mi = 0; mi < 2; mi++)
#pragma unroll
            for (int ni = 0; ni < 2; ni++) {
                int t = wm * 32 + mi * 16 + quad;
                int p = wn * 16 + ni * 8 + qt * 2;
                size_t o = ((size_t)b * SEQLEN + t0 + t) * DINNER + hh * HEADDIM + p;
                *(float2*)&g_y[o] = make_float2(accY[mi][ni][0], accY[mi][ni][1]);
                o += (size_t)8 * DINNER;
                *(float2*)&g_y[o] = make_float2(accY[mi][ni][2], accY[mi][ni][3]);
            }
    }

    // ---- GEMM5: Hc = Uw^T-form @ B  [64p x 128n], K=s=64 ----
    {
        float accH[2][4][4];
#pragma unroll
        for (int mi = 0; mi < 2; mi++)
#pragma unroll
            for (int ni = 0; ni < 4; ni++)
#pragma unroll
                for (int q = 0; q < 4; q++) accH[mi][ni][q] = 0.f;

#pragma unroll
        for (int k16 = 0; k16 < 4; k16++) {
            int kb = k16 * 16;
            uint32_t aH[2][4], aL[2][4], bH[4][2], bL[4][2];
#pragma unroll
            for (int mi = 0; mi < 2; mi++) {
                int row = kb + at_row;
                int col = wm * 32 + mi * 16 + at_col;
                uint32_t ad = swzb(row, col * 2);
                ldsm_x4_t(aH[mi][0], aH[mi][1], aH[mi][2], aH[mi][3], sb + OFF_UWH + ad);
                ldsm_x4_t(aL[mi][0], aL[mi][1], aL[mi][2], aL[mi][3], sb + OFF_UWL + ad);
            }
#pragma unroll
            for (int nj = 0; nj < 2; nj++) {
                int n0 = wn * 32 + nj * 16;
                int kp = n0 >> 6, ncol = n0 & 63;
                int row = kb + bt_row;
                int col = ncol + bt_col;
                uint32_t bd = kp * 8192u + swzb(row, col * 2);
                uint32_t r0, r1, r2, r3;
                ldsm_x4_t(r0, r1, r2, r3, sb + OFF_BPH + bd);
                bH[nj*2][0] = r0; bH[nj*2][1] = r1; bH[nj*2+1][0] = r2; bH[nj*2+1][1] = r3;
                ldsm_x4_t(r0, r1, r2, r3, sb + OFF_BPL + bd);
                bL[nj*2][0] = r0; bL[nj*2][1] = r1; bL[nj*2+1][0] = r2; bL[nj*2+1][1] = r3;
            }
#pragma unroll
            for (int mi = 0; mi < 2; mi++)
#pragma unroll
                for (int ni = 0; ni < 4; ni++) {
                    mma_bf16(accH[mi][ni], aH[mi], bH[ni][0], bH[ni][1]);
                    mma_bf16(accH[mi][ni], aH[mi], bL[ni][0], bL[ni][1]);
                    mma_bf16(accH[mi][ni], aL[mi], bH[ni][0], bH[ni][1]);
                }
        }
        float* hc = &g_hc[(((size_t)b * NHEADS + hh) * NCH + c) * (HEADDIM * DSTATE)];
#pragma unroll
        for (int mi = 0; mi < 2; mi++)
#pragma unroll
            for (int ni = 0; ni < 4; ni++) {
                int p = wm * 32 + mi * 16 + quad;
                int n = wn * 32 + ni * 8 + qt * 2;
                *(float2*)&hc[p * DSTATE + n] = make_float2(accH[mi][ni][0], accH[mi][ni][1]);
                *(float2*)&hc[(p + 8) * DSTATE + n] = make_float2(accH[mi][ni][2], accH[mi][ni][3]);
            }
    }
}

// =====================================================================
// SSD phase 2: inter-chunk state recurrence (grid 64 x 4 = 256 blocks)
// =====================================================================
__global__ __launch_bounds__(256)
void ssd_prop_kernel(const float* __restrict__ A_log)
{
    const int bh = blockIdx.x;
    const int q  = blockIdx.y;                    // quarter of the state
    const int hh = bh & (NHEADS - 1);
    const int tid = threadIdx.x;
    const float Ah = -expf(A_log[hh]);
    const int base = q * 512 + tid * 2;           // float4 index

    float4 acc[2];
    acc[0] = make_float4(0.f, 0.f, 0.f, 0.f);
    acc[1] = make_float4(0.f, 0.f, 0.f, 0.f);

    for (int c = 1; c < NCH; c++) {
        float Pi = expf(Ah * g_pi[(size_t)bh * NCH + c - 1]);
        const float4* hc = (const float4*)&g_hc[((size_t)bh * NCH + c - 1) * (HEADDIM * DSTATE)];
        float4* h0 = (float4*)&g_h0[((size_t)bh * NCH + c) * (HEADDIM * DSTATE)];
#pragma unroll
        for (int j = 0; j < 2; j++) {
            float4 v = hc[base + j];
            acc[j].x = Pi * acc[j].x + v.x;
            acc[j].y = Pi * acc[j].y + v.y;
            acc[j].z = Pi * acc[j].z + v.z;
            acc[j].w = Pi * acc[j].w + v.w;
            h0[base + j] = acc[j];
        }
    }
}

// =====================================================================
// SSD phase 3: carry  Y_t += r_t * (C_t @ h0)
// C panels cp.async'd from packed global
// =====================================================================
#define C3_CPH 0u
#define C3_CPL 16384u
#define C3_H0H 32768u
#define C3_H0L 49152u
#define C3_SDT 65536u
#define C3_R   65792u
#define SMEM_SSD3 66560u

__global__ __launch_bounds__(256, 2)
void ssd_carry_kernel(const float* __restrict__ A_log)
{
    extern __shared__ __align__(1024) char smem[];
    const uint32_t sb = smem_u32(smem);
    const int c = blockIdx.x + 1, b = blockIdx.y, hh = blockIdx.z;
    const int tid = threadIdx.x;
    const int wid = tid >> 5, lane = tid & 31;
    const int wm = wid & 1, wn = wid >> 1;
    const int t0 = c * CLEN;
    const float Ah = -expf(A_log[hh]);

    // stage C panels (2 x 16KB contiguous)
    {
        size_t tb = (size_t)((b * NCH + c) * 2) * 4096;
#pragma unroll
        for (int i = 0; i < 4; i++) {
            int idx = tid + i * 256;
            cp16(sb + C3_CPH + idx * 16, g_pCh + tb + idx * 8);
            cp16(sb + C3_CPL + idx * 16, g_pCl + tb + idx * 8);
        }
        cp_commit();
    }

    float* s_sdt = (float*)(smem + C3_SDT);
    float* s_r   = (float*)(smem + C3_R);

    if (tid < 64)
        s_sdt[tid] = g_dt[((size_t)b * SEQLEN + t0 + tid) * NHEADS + hh];
    __syncthreads();
#pragma unroll
    for (int off = 1; off < 64; off <<= 1) {
        float v = 0.f;
        if (tid < 64 && tid >= off) v = s_sdt[tid - off];
        __syncthreads();
        if (tid < 64) s_sdt[tid] += v;
        __syncthreads();
    }
    if (tid < 64) s_r[tid] = expf(Ah * s_sdt[tid]);

    // convert h0 (head-specific fp32 -> hi/lo panels)
    const float* h0src = &g_h0[(((size_t)b * NHEADS + hh) * NCH + c) * (HEADDIM * DSTATE)];
#pragma unroll
    for (int i = 0; i < 8; i++) {
        int idx = tid + i * 256;
        int r = idx >> 5, n4 = idx & 31;
        int kp = n4 >> 4, cb = n4 & 15;
        uint32_t off = (uint32_t)kp * 8192u + (uint32_t)r * 128u
                     + ((((uint32_t)cb >> 1) ^ (r & 7)) << 4) + (cb & 1) * 8;
        float4 v = *(const float4*)&h0src[r * DSTATE + n4 * 4];
        __nv_bfloat16 h0b,l0,h1,l1,h2,l2,h3,l3;
        hilo(v.x,h0b,l0); hilo(v.y,h1,l1); hilo(v.z,h2,l2); hilo(v.w,h3,l3);
        *(__nv_bfloat162*)(smem + C3_H0H + off)     = __halves2bfloat162(h0b,h1);
        *(__nv_bfloat162*)(smem + C3_H0H + off + 4) = __halves2bfloat162(h2,h3);
        *(__nv_bfloat162*)(smem + C3_H0L + off)     = __halves2bfloat162(l0,l1);
        *(__nv_bfloat162*)(smem + C3_H0L + off + 4) = __halves2bfloat162(l2,l3);
    }
    cp_wait<0>();
    __syncthreads();

    const int lgrp = lane >> 3, lr = lane & 7;
    const int a_roff = lr + (lgrp & 1) * 8;
    const int a_koff = lgrp >> 1;
    const int b_roff = lr + (lgrp >> 1) * 8;
    const int b_koff = lgrp & 1;
    const int quad = lane >> 2, qt = lane & 3;

    float acc[2][2][4];
#pragma unroll
    for (int mi = 0; mi < 2; mi++)
#pragma unroll
        for (int ni = 0; ni < 2; ni++)
#pragma unroll
            for (int q = 0; q < 4; q++) acc[mi][ni][q] = 0.f;

#pragma unroll
    for (int kp = 0; kp < 2; kp++) {
#pragma unroll
        for (int k16 = 0; k16 < 4; k16++) {
            int k2 = k16 * 2;
            uint32_t aH[2][4], aL[2][4], bH[2][2], bL[2][2];
#pragma unroll
            for (int mi = 0; mi < 2; mi++) {
                int row = wm * 32 + mi * 16 + a_roff;
                uint32_t ad = kp * 8192u + swz(row, k2 + a_koff);
                ldsm_x4(aH[mi][0], aH[mi][1], aH[mi][2], aH[mi][3], sb + C3_CPH + ad);
                ldsm_x4(aL[mi][0], aL[mi][1], aL[mi][2], aL[mi][3], sb + C3_CPL + ad);
            }
            {
                int row = wn * 16 + b_roff;
                uint32_t bd = kp * 8192u + swz(row, k2 + b_koff);
                uint32_t r0, r1, r2, r3;
                ldsm_x4(r0, r1, r2, r3, sb + C3_H0H + bd);
                bH[0][0] = r0; bH[0][1] = r1; bH[1][0] = r2; bH[1][1] = r3;
                ldsm_x4(r0, r1, r2, r3, sb + C3_H0L + bd);
                bL[0][0] = r0; bL[0][1] = r1; bL[1][0] = r2; bL[1][1] = r3;
            }
#pragma unroll
            for (int mi = 0; mi < 2; mi++)
#pragma unroll
                for (int ni = 0; ni < 2; ni++) {
                    mma_bf16(acc[mi][ni], aH[mi], bH[ni][0], bH[ni][1]);
                    mma_bf16(acc[mi][ni], aH[mi], bL[ni][0], bL[ni][1]);
                    mma_bf16(acc[mi][ni], aL[mi], bH[ni][0], bH[ni][1]);
                }
        }
    }

#pragma unroll
    for (int mi = 0; mi < 2; mi++)
#pragma unroll
        for (int ni = 0; ni < 2; ni++) {
            int t = wm * 32 + mi * 16 + quad;
            int p = wn * 16 + ni * 8 + qt * 2;
            {
                float rt = s_r[t];
                size_t o = ((size_t)b * SEQLEN + t0 + t) * DINNER + hh * HEADDIM + p;
                float2 v = *(float2*)&g_y[o];
                v.x += rt * acc[mi][ni][0];
                v.y += rt * acc[mi][ni][1];
                *(float2*)&g_y[o] = v;
            }
            {
                float rt = s_r[t + 8];
                size_t o = ((size_t)b * SEQLEN + t0 + t + 8) * DINNER + hh * HEADDIM + p;
                float2 v = *(float2*)&g_y[o];
                v.x += rt * acc[mi][ni][2];
                v.y += rt * acc[mi][ni][3];
                *(float2*)&g_y[o] = v;
            }
        }
}

// =====================================================================
// skip + gate + RMSNorm -> bf16 hi/lo
// =====================================================================
__global__ __launch_bounds__(256)
void gate_norm_kernel(const float* __restrict__ Dw, const float* __restrict__ norm_w)
{
    const int t = blockIdx.x;
    const int b = blockIdx.y;
    const size_t row = (size_t)b * SEQLEN + t;
    const float4* __restrict__ z4 = (const float4*)&g_zx [row * DINPROJ];
    const float4* __restrict__ x4 = (const float4*)&g_xbc[row * CONVDIM];
    const float4* __restrict__ y4 = (const float4*)&g_y  [row * DINNER];

    float4 vals[2];
    float ss = 0.f;
#pragma unroll
    for (int r = 0; r < 2; r++) {
        int f = r * 256 + threadIdx.x;
        float dv = Dw[f >> 4];
        float4 a = y4[f], xv = x4[f], zv = z4[f];
        float4 v;
        v.x = a.x + dv * xv.x;
        v.y = a.y + dv * xv.y;
        v.z = a.z + dv * xv.z;
        v.w = a.w + dv * xv.w;
        v.x *= zv.x / (1.f + expf(-zv.x));
        v.y *= zv.y / (1.f + expf(-zv.y));
        v.z *= zv.z / (1.f + expf(-zv.z));
        v.w *= zv.w / (1.f + expf(-zv.w));
        vals[r] = v;
        ss += v.x * v.x + v.y * v.y + v.z * v.z + v.w * v.w;
    }
    __shared__ float red[256];
    red[threadIdx.x] = ss;
    __syncthreads();
    for (int off = 128; off > 0; off >>= 1) {
        if (threadIdx.x < off) red[threadIdx.x] += red[threadIdx.x + off];
        __syncthreads();
    }
    float scale = rsqrtf(red[0] / (float)DINNER + EPS);
    __nv_bfloat162* outh = (__nv_bfloat162*)&g_ynh[row * DINNER];
    __nv_bfloat162* outl = (__nv_bfloat162*)&g_ynl[row * DINNER];
    const float4* nw4 = (const float4*)norm_w;
#pragma unroll
    for (int r = 0; r < 2; r++) {
        int f = r * 256 + threadIdx.x;
        float4 w = nw4[f];
        float4 v = vals[r];
        v.x *= scale * w.x; v.y *= scale * w.y; v.z *= scale * w.z; v.w *= scale * w.w;
        split4(v, outh, outl, f);
    }
}

// =====================================================================
extern "C" void kernel_launch(void* const* d_in, const int* in_sizes, int n_in,
                              void* d_out, int out_size)
{
    const float* x          = (const float*)d_in[0];
    const float* in_proj_w  = (const float*)d_in[1];
    const float* conv_w     = (const float*)d_in[2];
    const float* conv_b     = (const float*)d_in[3];
    const float* dt_bias    = (const float*)d_in[4];
    const float* A_log      = (const float*)d_in[5];
    const float* Dw         = (const float*)d_in[6];
    const float* norm_w     = (const float*)d_in[7];
    const float* out_proj_w = (const float*)d_in[8];
    float* out = (float*)d_out;

    float *p_zx = nullptr;
    void *p_xh, *p_xl, *p_w1h, *p_w1l, *p_w2h, *p_w2l, *p_ynh, *p_ynl;
    cudaGetSymbolAddress((void**)&p_zx, g_zx);
    cudaGetSymbolAddress(&p_xh,  g_xh);  cudaGetSymbolAddress(&p_xl,  g_xl);
    cudaGetSymbolAddress(&p_w1h, g_w1h); cudaGetSymbolAddress(&p_w1l, g_w1l);
    cudaGetSymbolAddress(&p_w2h, g_w2h); cudaGetSymbolAddress(&p_w2l, g_w2l);
    cudaGetSymbolAddress(&p_ynh, g_ynh); cudaGetSymbolAddress(&p_ynl, g_ynl);

    cudaFuncSetAttribute(gemm_mma<false>, cudaFuncAttributeMaxDynamicSharedMemorySize, SMEM_GEMM);
    cudaFuncSetAttribute(gemm_mma<true>,  cudaFuncAttributeMaxDynamicSharedMemorySize, SMEM_GEMM);
    cudaFuncSetAttribute(ssd_chunk_kernel, cudaFuncAttributeMaxDynamicSharedMemorySize, SMEM_SSD1);
    cudaFuncSetAttribute(ssd_carry_kernel, cudaFuncAttributeMaxDynamicSharedMemorySize, SMEM_SSD3);

    // 0) fp32 -> bf16 hi/lo conversions
    {
        int total4 = N4_X + N4_W1 + N4_W2;
        cvt_all<<<(total4 + 255)/256, 256>>>(
            (const float4*)x, (const float4*)in_proj_w, (const float4*)out_proj_w);
    }

    // 1) zxbcdt = x @ in_proj_w^T
    gemm_mma<false><<<dim3((DINPROJ + BN - 1)/BN, ROWS/BM), 256, SMEM_GEMM>>>(
        (const __nv_bfloat16*)p_xh, (const __nv_bfloat16*)p_xl,
        (const __nv_bfloat16*)p_w1h, (const __nv_bfloat16*)p_w1l,
        nullptr, p_zx, DINPROJ, DMODEL);

    // 2) conv + SiLU; dt softplus
    conv_act_kernel<<<dim3(CONVDIM/256, SEQLEN/4, BATCH), 256>>>(conv_w, conv_b, dt_bias);

    // 2b) pack B/C once (shared across all heads)
    pack_bc_kernel<<<512, 256>>>();

    // 3) SSD scan
    ssd_chunk_kernel<<<dim3(NCH, BATCH, NHEADS), 256, SMEM_SSD1>>>(A_log);
    ssd_prop_kernel<<<dim3(BATCH * NHEADS, 4), 256>>>(A_log);
    ssd_carry_kernel<<<dim3(NCH - 1, BATCH, NHEADS), 256, SMEM_SSD3>>>(A_log);

    // 4) skip + gate + RMSNorm
    gate_norm_kernel<<<dim3(SEQLEN, BATCH), 256>>>(Dw, norm_w);

    // 5) out = x + yn @ out_proj_w^T
    gemm_mma<true><<<dim3(DMODEL/BN, ROWS/BM), 256, SMEM_GEMM>>>(
        (const __nv_bfloat16*)p_ynh, (const __nv_bfloat16*)p_ynl,
        (const __nv_bfloat16*)p_w2h, (const __nv_bfloat16*)p_w2l,
        x, out, DMODEL, DINNER);
}

// round 11
// speedup vs baseline: 1.2914x; 1.2138x over previous
#include <cuda_runtime.h>
#include <cuda_bf16.h>
#include <cuda_fp16.h>
#include <math.h>
#include <stdint.h>

// ---------------- problem constants ----------------
#define BATCH    2
#define SEQLEN   1024
#define DMODEL   1024
#define DINNER   2048
#define NHEADS   32
#define HEADDIM  64
#define DSTATE   128
#define DCONV    4
#define CONVDIM  2304
#define DINPROJ  4384
#define ROWS     (BATCH*SEQLEN)
#define EPS      1e-5f
#define CLEN     64
#define NCH      (SEQLEN/CLEN)     // 16 chunks

// ---------------- scratch ----------------
__device__ __align__(1024) float g_zx [ROWS*DINPROJ];
__device__ __align__(1024) float g_xbc[ROWS*CONVDIM];
__device__ __align__(1024) float g_dt [ROWS*NHEADS];
__device__ __align__(1024) float g_y  [ROWS*DINNER];
__device__ __align__(1024) float g_hc [BATCH*NHEADS*NCH*HEADDIM*DSTATE];
__device__ __align__(1024) float g_h0 [BATCH*NHEADS*NCH*HEADDIM*DSTATE];
__device__ __align__(1024) float g_pi [BATCH*NHEADS*NCH];
// pre-swizzled bf16 hi/lo B and C panel tiles (SSD path)
#define PTILES (BATCH*NCH*2)
__device__ __align__(1024) __nv_bfloat16 g_pBh[PTILES*4096];
__device__ __align__(1024) __nv_bfloat16 g_pBl[PTILES*4096];
__device__ __align__(1024) __nv_bfloat16 g_pCh[PTILES*4096];
__device__ __align__(1024) __nv_bfloat16 g_pCl[PTILES*4096];
// fp16 operands for the two big GEMMs (A split hi/lo, W single)
__device__ __align__(1024) __half g_xh [ROWS*DMODEL];
__device__ __align__(1024) __half g_xl [ROWS*DMODEL];
__device__ __align__(1024) __half g_w1h[DINPROJ*DMODEL];
__device__ __align__(1024) __half g_w2h[DMODEL*DINNER];
__device__ __align__(1024) __half g_ynh[ROWS*DINNER];
__device__ __align__(1024) __half g_ynl[ROWS*DINNER];

// ---------------- primitives ----------------
__device__ __forceinline__ uint32_t smem_u32(const void* p) {
    uint32_t a;
    asm("{ .reg .u64 t; cvta.to.shared.u64 t, %1; cvt.u32.u64 %0, t; }" : "=r"(a) : "l"(p));
    return a;
}
__device__ __forceinline__ void cp16(uint32_t dst, const void* src) {
    asm volatile("cp.async.cg.shared.global [%0], [%1], 16;" :: "r"(dst), "l"(src));
}
__device__ __forceinline__ void cp_commit() { asm volatile("cp.async.commit_group;" ::: "memory"); }
template<int W> __device__ __forceinline__ void cp_wait() {
    asm volatile("cp.async.wait_group %0;" :: "n"(W) : "memory");
}
__device__ __forceinline__ void ldsm_x4(uint32_t& r0, uint32_t& r1, uint32_t& r2, uint32_t& r3, uint32_t a) {
    asm volatile("ldmatrix.sync.aligned.m8n8.x4.shared.b16 {%0,%1,%2,%3}, [%4];"
                 : "=r"(r0), "=r"(r1), "=r"(r2), "=r"(r3) : "r"(a));
}
__device__ __forceinline__ void ldsm_x4_t(uint32_t& r0, uint32_t& r1, uint32_t& r2, uint32_t& r3, uint32_t a) {
    asm volatile("ldmatrix.sync.aligned.m8n8.x4.trans.shared.b16 {%0,%1,%2,%3}, [%4];"
                 : "=r"(r0), "=r"(r1), "=r"(r2), "=r"(r3) : "r"(a));
}
__device__ __forceinline__ void mma_bf16(float* c, const uint32_t* a, uint32_t b0, uint32_t b1) {
    asm volatile(
        "mma.sync.aligned.m16n8k16.row.col.f32.bf16.bf16.f32 "
        "{%0,%1,%2,%3}, {%4,%5,%6,%7}, {%8,%9}, {%0,%1,%2,%3};"
        : "+f"(c[0]), "+f"(c[1]), "+f"(c[2]), "+f"(c[3])
        : "r"(a[0]), "r"(a[1]), "r"(a[2]), "r"(a[3]), "r"(b0), "r"(b1));
}
__device__ __forceinline__ void mma_fp16(float* c, const uint32_t* a, uint32_t b0, uint32_t b1) {
    asm volatile(
        "mma.sync.aligned.m16n8k16.row.col.f32.f16.f16.f32 "
        "{%0,%1,%2,%3}, {%4,%5,%6,%7}, {%8,%9}, {%0,%1,%2,%3};"
        : "+f"(c[0]), "+f"(c[1]), "+f"(c[2]), "+f"(c[3])
        : "r"(a[0]), "r"(a[1]), "r"(a[2]), "r"(a[3]), "r"(b0), "r"(b1));
}
__device__ __forceinline__ uint32_t swz(int row, int seg) {
    return (uint32_t)(row * 128 + ((seg ^ (row & 7)) << 4));
}
__device__ __forceinline__ uint32_t swzb(int row, int colb) {
    return (uint32_t)(row * 128 + (((colb >> 4) ^ (row & 7)) << 4) + (colb & 15));
}
__device__ __forceinline__ void hilo(float v, __nv_bfloat16& h, __nv_bfloat16& l) {
    h = __float2bfloat16(v);
    l = __float2bfloat16(v - __bfloat162float(h));
}
__device__ __forceinline__ void hilo_h(float v, __half& h, __half& l) {
    h = __float2half_rn(v);
    l = __float2half_rn(v - __half2float(h));
}

// =====================================================================
// Tensor-core GEMM, fp16 2-pass: C = (Ah+Al) @ Wh^T (+residual)
// BM128/BN128, K-chunk 64, 3 tiles/stage (Ah, Al, Wh), 3-stage pipeline.
// =====================================================================
#define BM 128
#define BN 128
#define KC 64
#define TILE_B   16384u
#define STAGE_B  (3u*TILE_B)
#define NSTAGE   3
#define SMEM_GEMM (NSTAGE*STAGE_B)     // 147456

template<bool RES>
__global__ __launch_bounds__(256, 1)
void gemm_mma(const __half* __restrict__ Ahp, const __half* __restrict__ Alp,
              const __half* __restrict__ Bhp,
              const float* __restrict__ resid, float* __restrict__ C,
              int N, int K)
{
    extern __shared__ __align__(1024) char smem[];
    const uint32_t sb = smem_u32(smem);

    const int tid = threadIdx.x;
    const int wid = tid >> 5, lane = tid & 31;
    const int wm = wid & 1, wn = wid >> 1;
    const int m0 = blockIdx.y * BM, n0 = blockIdx.x * BN;
    const int NC = K / KC;

    int lrow[4], lseg[4];
#pragma unroll
    for (int it = 0; it < 4; it++) {
        int idx = tid + it * 256;
        lrow[it] = idx >> 3;
        lseg[it] = idx & 7;
    }

    auto load_chunk = [&](int stage, int k0) {
        uint32_t s = sb + stage * STAGE_B;
#pragma unroll
        for (int it = 0; it < 4; it++) {
            int row = lrow[it], seg = lseg[it];
            uint32_t d = swz(row, seg);
            size_t aoff = (size_t)(m0 + row) * K + k0 + seg * 8;
            cp16(s + d,          Ahp + aoff);
            cp16(s + TILE_B + d, Alp + aoff);
            int brow = n0 + row; if (brow >= N) brow = N - 1;
            size_t boff = (size_t)brow * K + k0 + seg * 8;
            cp16(s + 2 * TILE_B + d, Bhp + boff);
        }
        cp_commit();
    };

    float acc[4][4][4];
#pragma unroll
    for (int mi = 0; mi < 4; mi++)
#pragma unroll
        for (int ni = 0; ni < 4; ni++)
#pragma unroll
            for (int q = 0; q < 4; q++) acc[mi][ni][q] = 0.f;

    const int lgrp = lane >> 3, lr = lane & 7;
    const int a_roff = lr + (lgrp & 1) * 8;
    const int a_koff = lgrp >> 1;
    const int b_roff = lr + (lgrp >> 1) * 8;
    const int b_koff = lgrp & 1;

    load_chunk(0, 0);
    load_chunk(1, KC);

    for (int c = 0; c < NC; c++) {
        if (c + 2 < NC) load_chunk((c + 2) % NSTAGE, (c + 2) * KC);
        else            cp_commit();
        cp_wait<2>();
        __syncthreads();

        uint32_t s = sb + (c % NSTAGE) * STAGE_B;
#pragma unroll
        for (int k16 = 0; k16 < 4; k16++) {
            int k2 = k16 * 2;
            uint32_t ah[4][4], al[4][4], bh[4][2];
#pragma unroll
            for (int mi = 0; mi < 4; mi++) {
                int row = wm * 64 + mi * 16 + a_roff;
                uint32_t ad = swz(row, k2 + a_koff);
                ldsm_x4(ah[mi][0], ah[mi][1], ah[mi][2], ah[mi][3], s + ad);
                ldsm_x4(al[mi][0], al[mi][1], al[mi][2], al[mi][3], s + TILE_B + ad);
            }
#pragma unroll
            for (int nj = 0; nj < 2; nj++) {
                int row = wn * 32 + nj * 16 + b_roff;
                uint32_t bd = swz(row, k2 + b_koff);
                uint32_t r0, r1, r2, r3;
                ldsm_x4(r0, r1, r2, r3, s + 2 * TILE_B + bd);
                bh[nj * 2][0] = r0; bh[nj * 2][1] = r1;
                bh[nj * 2 + 1][0] = r2; bh[nj * 2 + 1][1] = r3;
            }
#pragma unroll
            for (int mi = 0; mi < 4; mi++)
#pragma unroll
                for (int ni = 0; ni < 4; ni++) {
                    mma_fp16(acc[mi][ni], ah[mi], bh[ni][0], bh[ni][1]);
                    mma_fp16(acc[mi][ni], al[mi], bh[ni][0], bh[ni][1]);
                }
        }
        __syncthreads();
    }

    const int quad = lane >> 2, qt = lane & 3;
#pragma unroll
    for (int mi = 0; mi < 4; mi++) {
#pragma unroll
        for (int ni = 0; ni < 4; ni++) {
            int gm = m0 + wm * 64 + mi * 16 + quad;
            int gn = n0 + wn * 32 + ni * 8 + qt * 2;
            if (gn < N) {
                {
                    float2 v = make_float2(acc[mi][ni][0], acc[mi][ni][1]);
                    size_t o = (size_t)gm * N + gn;
                    if (RES) { float2 rv = *(const float2*)(resid + o); v.x += rv.x; v.y += rv.y; }
                    *(float2*)(C + o) = v;
                }
                {
                    float2 v = make_float2(acc[mi][ni][2], acc[mi][ni][3]);
                    size_t o = (size_t)(gm + 8) * N + gn;
                    if (RES) { float2 rv = *(const float2*)(resid + o); v.x += rv.x; v.y += rv.y; }
                    *(float2*)(C + o) = v;
                }
            }
        }
    }
}

// =====================================================================
// fp32 -> fp16 conversions: x split hi/lo; w1/w2 single fp16
// =====================================================================
#define N4_X  (ROWS*DMODEL/4)
#define N4_W1 (DINPROJ*DMODEL/4)
#define N4_W2 (DMODEL*DINNER/4)

__device__ __forceinline__ void split4h(float4 v, __half2* hi, __half2* lo, int i) {
    __half hx, lx, hy, ly, hz, lz, hw, lw;
    hilo_h(v.x, hx, lx); hilo_h(v.y, hy, ly); hilo_h(v.z, hz, lz); hilo_h(v.w, hw, lw);
    hi[i * 2]     = __halves2half2(hx, hy);
    hi[i * 2 + 1] = __halves2half2(hz, hw);
    lo[i * 2]     = __halves2half2(lx, ly);
    lo[i * 2 + 1] = __halves2half2(lz, lw);
}
__device__ __forceinline__ void cvt4h(float4 v, __half2* hi, int i) {
    hi[i * 2]     = __halves2half2(__float2half_rn(v.x), __float2half_rn(v.y));
    hi[i * 2 + 1] = __halves2half2(__float2half_rn(v.z), __float2half_rn(v.w));
}

__global__ __launch_bounds__(256)
void cvt_all(const float4* __restrict__ x, const float4* __restrict__ w1,
             const float4* __restrict__ w2)
{
    int i = blockIdx.x * 256 + threadIdx.x;
    if (i < N4_X) {
        split4h(x[i], (__half2*)g_xh, (__half2*)g_xl, i);
    } else if (i < N4_X + N4_W1) {
        int j = i - N4_X;
        cvt4h(w1[j], (__half2*)g_w1h, j);
    } else if (i < N4_X + N4_W1 + N4_W2) {
        int j = i - N4_X - N4_W1;
        cvt4h(w2[j], (__half2*)g_w2h, j);
    }
}

// =====================================================================
// Causal depthwise conv + SiLU; dt softplus
// =====================================================================
__global__ __launch_bounds__(256)
void conv_act_kernel(const float* __restrict__ conv_w, const float* __restrict__ conv_b,
                     const float* __restrict__ dt_bias)
{
    const int c  = blockIdx.x * 256 + threadIdx.x;
    const int tb = blockIdx.y * 4;
    const int b  = blockIdx.z;

    float w0 = conv_w[c * 4 + 0], w1 = conv_w[c * 4 + 1];
    float w2 = conv_w[c * 4 + 2], w3 = conv_w[c * 4 + 3];
    float bias = conv_b[c];

    float v[7];
#pragma unroll
    for (int k = 0; k < 7; k++) {
        int tt = tb - 3 + k;
        v[k] = (tt >= 0) ? g_zx[((size_t)b * SEQLEN + tt) * DINPROJ + DINNER + c] : 0.f;
    }
#pragma unroll
    for (int i = 0; i < 4; i++) {
        float a = bias + v[i] * w0 + v[i + 1] * w1 + v[i + 2] * w2 + v[i + 3] * w3;
        g_xbc[((size_t)b * SEQLEN + tb + i) * CONVDIM + c] = a / (1.f + expf(-a));
    }
    if (blockIdx.x == 0 && threadIdx.x < NHEADS) {
        int hh = threadIdx.x;
        float bth = dt_bias[hh];
#pragma unroll
        for (int i = 0; i < 4; i++) {
            size_t row = (size_t)b * SEQLEN + tb + i;
            float raw = g_zx[row * DINPROJ + (DINNER + CONVDIM) + hh] + bth;
            g_dt[row * NHEADS + hh] = (raw > 20.f) ? raw : log1pf(expf(raw));
        }
    }
}

// =====================================================================
// pack B/C into pre-swizzled bf16 hi/lo tiles (shared by all heads)
// =====================================================================
__global__ __launch_bounds__(256)
void pack_bc_kernel()
{
    int u = blockIdx.x * 256 + threadIdx.x;
    int s   = u & 7;
    int t   = (u >> 3) & 63;
    int kp  = (u >> 9) & 1;
    int ch  = (u >> 10) & 15;
    int b   = (u >> 14) & 1;
    int isC = (u >> 15);

    size_t src = ((size_t)b * SEQLEN + ch * 64 + t) * CONVDIM
               + DINNER + (isC ? DSTATE : 0) + kp * 64 + s * 8;
    float4 v0 = *(const float4*)&g_xbc[src];
    float4 v1 = *(const float4*)&g_xbc[src + 4];

    __nv_bfloat16 h[8], l[8];
    hilo(v0.x, h[0], l[0]); hilo(v0.y, h[1], l[1]);
    hilo(v0.z, h[2], l[2]); hilo(v0.w, h[3], l[3]);
    hilo(v1.x, h[4], l[4]); hilo(v1.y, h[5], l[5]);
    hilo(v1.z, h[6], l[6]); hilo(v1.w, h[7], l[7]);

    __nv_bfloat162 ph[4], pl[4];
#pragma unroll
    for (int j = 0; j < 4; j++) {
        ph[j] = __halves2bfloat162(h[j * 2], h[j * 2 + 1]);
        pl[j] = __halves2bfloat162(l[j * 2], l[j * 2 + 1]);
    }

    size_t off = (size_t)(((b * NCH + ch) * 2) + kp) * 4096 + t * 64 + ((s ^ (t & 7)) * 8);
    __nv_bfloat16* dh = (isC ? g_pCh : g_pBh) + off;
    __nv_bfloat16* dl = (isC ? g_pCl : g_pBl) + off;
    *(uint4*)dh = *(uint4*)ph;
    *(uint4*)dl = *(uint4*)pl;
}

// =====================================================================
// SSD phase 1 (unchanged from R10)
// =====================================================================
#define OFF_CPH 0u
#define OFF_CPL 16384u
#define OFF_BPH 32768u
#define OFF_BPL 49152u
#define OFF_UTH 65536u
#define OFF_UTL 73728u
#define OFF_UWH 81920u
#define OFF_UWL 90112u
#define OFF_GH  OFF_CPH
#define OFF_GL  (OFF_CPH + 8192u)
#define OFF_SDT 98304u
#define OFF_DTS 98560u
#define OFF_WS  98816u
#define SMEM_SSD1 99072u

__global__ __launch_bounds__(256, 2)
void ssd_chunk_kernel(const float* __restrict__ A_log)
{
    extern __shared__ __align__(1024) char smem[];
    const uint32_t sb = smem_u32(smem);
    const int c = blockIdx.x, b = blockIdx.y, hh = blockIdx.z;
    const int tid = threadIdx.x;
    const int wid = tid >> 5, lane = tid & 31;
    const int wm = wid & 1, wn = wid >> 1;
    const int t0 = c * CLEN;
    const float Ah = -expf(A_log[hh]);

    {
        size_t tb = (size_t)((b * NCH + c) * 2) * 4096;
#pragma unroll
        for (int i = 0; i < 4; i++) {
            int idx = tid + i * 256;
            cp16(sb + OFF_BPH + idx * 16, g_pBh + tb + idx * 8);
            cp16(sb + OFF_BPL + idx * 16, g_pBl + tb + idx * 8);
            cp16(sb + OFF_CPH + idx * 16, g_pCh + tb + idx * 8);
            cp16(sb + OFF_CPL + idx * 16, g_pCl + tb + idx * 8);
        }
        cp_commit();
    }

    float* s_sdt = (float*)(smem + OFF_SDT);
    float* s_dt  = (float*)(smem + OFF_DTS);
    float* s_w   = (float*)(smem + OFF_WS);

    if (tid < 64) {
        float d = g_dt[((size_t)b * SEQLEN + t0 + tid) * NHEADS + hh];
        s_dt[tid] = d;
        s_sdt[tid] = d;
    }
    __syncthreads();
#pragma unroll
    for (int off = 1; off < 64; off <<= 1) {
        float v = 0.f;
        if (tid < 64 && tid >= off) v = s_sdt[tid - off];
        __syncthreads();
        if (tid < 64) s_sdt[tid] += v;
        __syncthreads();
    }
    float sdtTOT = s_sdt[63];
    if (tid < 64) s_w[tid] = expf(Ah * (sdtTOT - s_sdt[tid]));
    if (tid == 0) g_pi[((size_t)b * NHEADS + hh) * NCH + c] = sdtTOT;
    __syncthreads();

#pragma unroll
    for (int i = 0; i < 4; i++) {
        int idx = tid + i * 256;
        int t = idx >> 4, p4 = idx & 15;
        size_t row = ((size_t)b * SEQLEN + t0 + t) * CONVDIM;
        float4 xv = *(const float4*)&g_xbc[row + hh * HEADDIM + p4 * 4];
        float dtv = s_dt[t], wv = s_w[t];
        float u0 = dtv*xv.x, u1 = dtv*xv.y, u2 = dtv*xv.z, u3 = dtv*xv.w;
        uint32_t off = swzb(t, p4 * 8);
        __nv_bfloat16 h0,l0,h1,l1,h2,l2,h3,l3;
        hilo(u0,h0,l0); hilo(u1,h1,l1); hilo(u2,h2,l2); hilo(u3,h3,l3);
        *(__nv_bfloat162*)(smem + OFF_UTH + off)     = __halves2bfloat162(h0,h1);
        *(__nv_bfloat162*)(smem + OFF_UTH + off + 4) = __halves2bfloat162(h2,h3);
        *(__nv_bfloat162*)(smem + OFF_UTL + off)     = __halves2bfloat162(l0,l1);
        *(__nv_bfloat162*)(smem + OFF_UTL + off + 4) = __halves2bfloat162(l2,l3);
        hilo(u0*wv,h0,l0); hilo(u1*wv,h1,l1); hilo(u2*wv,h2,l2); hilo(u3*wv,h3,l3);
        *(__nv_bfloat162*)(smem + OFF_UWH + off)     = __halves2bfloat162(h0,h1);
        *(__nv_bfloat162*)(smem + OFF_UWH + off + 4) = __halves2bfloat162(h2,h3);
        *(__nv_bfloat162*)(smem + OFF_UWL + off)     = __halves2bfloat162(l0,l1);
        *(__nv_bfloat162*)(smem + OFF_UWL + off + 4) = __halves2bfloat162(l2,l3);
    }
    cp_wait<0>();
    __syncthreads();

    const int lgrp = lane >> 3, lr = lane & 7;
    const int a_roff = lr + (lgrp & 1) * 8;
    const int a_koff = lgrp >> 1;
    const int b_roff = lr + (lgrp >> 1) * 8;
    const int b_koff = lgrp & 1;
    const int quad = lane >> 2, qt = lane & 3;
    const int bt_row = lr + (lgrp & 1) * 8;
    const int bt_col = (lgrp >> 1) * 8;
    const int at_row = lr + (lgrp >> 1) * 8;
    const int at_col = (lgrp & 1) * 8;

    // GEMM2: G = C @ B^T
    float accG[2][2][4];
#pragma unroll
    for (int mi = 0; mi < 2; mi++)
#pragma unroll
        for (int ni = 0; ni < 2; ni++)
#pragma unroll
            for (int q = 0; q < 4; q++) accG[mi][ni][q] = 0.f;

#pragma unroll
    for (int kp = 0; kp < 2; kp++) {
#pragma unroll
        for (int k16 = 0; k16 < 4; k16++) {
            int k2 = k16 * 2;
            uint32_t aH[2][4], aL[2][4], bH[2][2], bL[2][2];
#pragma unroll
            for (int mi = 0; mi < 2; mi++) {
                int row = wm * 32 + mi * 16 + a_roff;
                uint32_t ad = kp * 8192u + swz(row, k2 + a_koff);
                ldsm_x4(aH[mi][0], aH[mi][1], aH[mi][2], aH[mi][3], sb + OFF_CPH + ad);
                ldsm_x4(aL[mi][0], aL[mi][1], aL[mi][2], aL[mi][3], sb + OFF_CPL + ad);
            }
            {
                int row = wn * 16 + b_roff;
                uint32_t bd = kp * 8192u + swz(row, k2 + b_koff);
                uint32_t r0, r1, r2, r3;
                ldsm_x4(r0, r1, r2, r3, sb + OFF_BPH + bd);
                bH[0][0] = r0; bH[0][1] = r1; bH[1][0] = r2; bH[1][1] = r3;
                ldsm_x4(r0, r1, r2, r3, sb + OFF_BPL + bd);
                bL[0][0] = r0; bL[0][1] = r1; bL[1][0] = r2; bL[1][1] = r3;
            }
#pragma unroll
            for (int mi = 0; mi < 2; mi++)
#pragma unroll
                for (int ni = 0; ni < 2; ni++) {
                    mma_bf16(accG[mi][ni], aH[mi], bH[ni][0], bH[ni][1]);
                    mma_bf16(accG[mi][ni], aH[mi], bL[ni][0], bL[ni][1]);
                    mma_bf16(accG[mi][ni], aL[mi], bH[ni][0], bH[ni][1]);
                }
        }
    }
    __syncthreads();

#pragma unroll
    for (int mi = 0; mi < 2; mi++)
#pragma unroll
        for (int ni = 0; ni < 2; ni++)
#pragma unroll
            for (int half = 0; half < 2; half++) {
                int t = wm * 32 + mi * 16 + quad + half * 8;
                int s = wn * 16 + ni * 8 + qt * 2;
                float sdt_t = s_sdt[t];
                float v0 = accG[mi][ni][half * 2 + 0];
                float v1 = accG[mi][ni][half * 2 + 1];
                v0 = (t >= s)     ? v0 * expf(Ah * (sdt_t - s_sdt[s]))     : 0.f;
                v1 = (t >= s + 1) ? v1 * expf(Ah * (sdt_t - s_sdt[s + 1])) : 0.f;
                __nv_bfloat16 h0,l0,h1,l1;
                hilo(v0,h0,l0); hilo(v1,h1,l1);
                uint32_t off = swzb(t, s * 2);
                *(__nv_bfloat162*)(smem + OFF_GH + off) = __halves2bfloat162(h0,h1);
                *(__nv_bfloat162*)(smem + OFF_GL + off) = __halves2bfloat162(l0,l1);
            }
    __syncthreads();

    // GEMM4: Y = G @ U
    {
        float accY[2][2][4];
#pragma unroll
        for (int mi = 0; mi < 2; mi++)
#pragma unroll
            for (int ni = 0; ni < 2; ni++)
#pragma unroll
                for (int q = 0; q < 4; q++) accY[mi][ni][q] = 0.f;

#pragma unroll
        for (int k16 = 0; k16 < 4; k16++) {
            int k2 = k16 * 2, kb = k16 * 16;
            uint32_t aH[2][4], aL[2][4], bH[2][2], bL[2][2];
#pragma unroll
            for (int mi = 0; mi < 2; mi++) {
                int row = wm * 32 + mi * 16 + a_roff;
                uint32_t ad = swz(row, k2 + a_koff);
                ldsm_x4(aH[mi][0], aH[mi][1], aH[mi][2], aH[mi][3], sb + OFF_GH + ad);
                ldsm_x4(aL[mi][0], aL[mi][1], aL[mi][2], aL[mi][3], sb + OFF_GL + ad);
            }
            {
                int row = kb + bt_row;
                int col = wn * 16 + bt_col;
                uint32_t bd = swzb(row, col * 2);
                uint32_t r0, r1, r2, r3;
                ldsm_x4_t(r0, r1, r2, r3, sb + OFF_UTH + bd);
                bH[0][0] = r0; bH[0][1] = r1; bH[1][0] = r2; bH[1][1] = r3;
                ldsm_x4_t(r0, r1, r2, r3, sb + OFF_UTL + bd);
                bL[0][0] = r0; bL[0][1] = r1; bL[1][0] = r2; bL[1][1] = r3;
            }
#pragma unroll
            for (int mi = 0; mi < 2; mi++)
#pragma unroll
                for (int ni = 0; ni < 2; ni++) {
                    mma_bf16(accY[mi][ni], aH[mi], bH[ni][0], bH[ni][1]);
                    mma_bf16(accY[mi][ni], aH[mi], bL[ni][0], bL[ni][1]);
                    mma_bf16(accY[mi][ni], aL[mi], bH[ni][0], bH[ni][1]);
                }
        }
#pragma unroll
        for (int mi = 0; mi < 2; mi++)
#pragma unroll
            for (int ni = 0; ni < 2; ni++) {
                int t = wm * 32 + mi * 16 + quad;
                int p = wn * 16 + ni * 8 + qt * 2;
                size_t o = ((size_t)b * SEQLEN + t0 + t) * DINNER + hh * HEADDIM + p;
                *(float2*)&g_y[o] = make_float2(accY[mi][ni][0], accY[mi][ni][1]);
                o += (size_t)8 * DINNER;
                *(float2*)&g_y[o] = make_float2(accY[mi][ni][2], accY[mi][ni][3]);
            }
    }

    // GEMM5: Hc = Uw^T-form @ B
    {
        float accH[2][4][4];
#pragma unroll
        for (int mi = 0; mi < 2; mi++)
#pragma unroll
            for (int ni = 0; ni < 4; ni++)
#pragma unroll
                for (int q = 0; q < 4; q++) accH[mi][ni][q] = 0.f;

#pragma unroll
        for (int k16 = 0; k16 < 4; k16++) {
            int kb = k16 * 16;
            uint32_t aH[2][4], aL[2][4], bH[4][2], bL[4][2];
#pragma unroll
            for (int mi = 0; mi < 2; mi++) {
                int row = kb + at_row;
                int col = wm * 32 + mi * 16 + at_col;
                uint32_t ad = swzb(row, col * 2);
                ldsm_x4_t(aH[mi][0], aH[mi][1], aH[mi][2], aH[mi][3], sb + OFF_UWH + ad);
                ldsm_x4_t(aL[mi][0], aL[mi][1], aL[mi][2], aL[mi][3], sb + OFF_UWL + ad);
            }
#pragma unroll
            for (int nj = 0; nj < 2; nj++) {
                int n0 = wn * 32 + nj * 16;
                int kp = n0 >> 6, ncol = n0 & 63;
                int row = kb + bt_row;
                int col = ncol + bt_col;
                uint32_t bd = kp * 8192u + swzb(row, col * 2);
                uint32_t r0, r1, r2, r3;
                ldsm_x4_t(r0, r1, r2, r3, sb + OFF_BPH + bd);
                bH[nj*2][0] = r0; bH[nj*2][1] = r1; bH[nj*2+1][0] = r2; bH[nj*2+1][1] = r3;
                ldsm_x4_t(r0, r1, r2, r3, sb + OFF_BPL + bd);
                bL[nj*2][0] = r0; bL[nj*2][1] = r1; bL[nj*2+1][0] = r2; bL[nj*2+1][1] = r3;
            }
#pragma unroll
            for (int mi = 0; mi < 2; mi++)
#pragma unroll
                for (int ni = 0; ni < 4; ni++) {
                    mma_bf16(accH[mi][ni], aH[mi], bH[ni][0], bH[ni][1]);
                    mma_bf16(accH[mi][ni], aH[mi], bL[ni][0], bL[ni][1]);
                    mma_bf16(accH[mi][ni], aL[mi], bH[ni][0], bH[ni][1]);
                }
        }
        float* hc = &g_hc[(((size_t)b * NHEADS + hh) * NCH + c) * (HEADDIM * DSTATE)];
#pragma unroll
        for (int mi = 0; mi < 2; mi++)
#pragma unroll
            for (int ni = 0; ni < 4; ni++) {
                int p = wm * 32 + mi * 16 + quad;
                int n = wn * 32 + ni * 8 + qt * 2;
                *(float2*)&hc[p * DSTATE + n] = make_float2(accH[mi][ni][0], accH[mi][ni][1]);
                *(float2*)&hc[(p + 8) * DSTATE + n] = make_float2(accH[mi][ni][2], accH[mi][ni][3]);
            }
    }
}

// =====================================================================
// SSD phase 2
// =====================================================================
__global__ __launch_bounds__(256)
void ssd_prop_kernel(const float* __restrict__ A_log)
{
    const int bh = blockIdx.x;
    const int q  = blockIdx.y;
    const int hh = bh & (NHEADS - 1);
    const int tid = threadIdx.x;
    const float Ah = -expf(A_log[hh]);
    const int base = q * 512 + tid * 2;

    float4 acc[2];
    acc[0] = make_float4(0.f, 0.f, 0.f, 0.f);
    acc[1] = make_float4(0.f, 0.f, 0.f, 0.f);

    for (int c = 1; c < NCH; c++) {
        float Pi = expf(Ah * g_pi[(size_t)bh * NCH + c - 1]);
        const float4* hc = (const float4*)&g_hc[((size_t)bh * NCH + c - 1) * (HEADDIM * DSTATE)];
        float4* h0 = (float4*)&g_h0[((size_t)bh * NCH + c) * (HEADDIM * DSTATE)];
#pragma unroll
        for (int j = 0; j < 2; j++) {
            float4 v = hc[base + j];
            acc[j].x = Pi * acc[j].x + v.x;
            acc[j].y = Pi * acc[j].y + v.y;
            acc[j].z = Pi * acc[j].z + v.z;
            acc[j].w = Pi * acc[j].w + v.w;
            h0[base + j] = acc[j];
        }
    }
}

// =====================================================================
// SSD phase 3
// =====================================================================
#define C3_CPH 0u
#define C3_CPL 16384u
#define C3_H0H 32768u
#define C3_H0L 49152u
#define C3_SDT 65536u
#define C3_R   65792u
#define SMEM_SSD3 66560u

__global__ __launch_bounds__(256, 2)
void ssd_carry_kernel(const float* __restrict__ A_log)
{
    extern __shared__ __align__(1024) char smem[];
    const uint32_t sb = smem_u32(smem);
    const int c = blockIdx.x + 1, b = blockIdx.y, hh = blockIdx.z;
    const int tid = threadIdx.x;
    const int wid = tid >> 5, lane = tid & 31;
    const int wm = wid & 1, wn = wid >> 1;
    const int t0 = c * CLEN;
    const float Ah = -expf(A_log[hh]);

    {
        size_t tb = (size_t)((b * NCH + c) * 2) * 4096;
#pragma unroll
        for (int i = 0; i < 4; i++) {
            int idx = tid + i * 256;
            cp16(sb + C3_CPH + idx * 16, g_pCh + tb + idx * 8);
            cp16(sb + C3_CPL + idx * 16, g_pCl + tb + idx * 8);
        }
        cp_commit();
    }

    float* s_sdt = (float*)(smem + C3_SDT);
    float* s_r   = (float*)(smem + C3_R);

    if (tid < 64)
        s_sdt[tid] = g_dt[((size_t)b * SEQLEN + t0 + tid) * NHEADS + hh];
    __syncthreads();
#pragma unroll
    for (int off = 1; off < 64; off <<= 1) {
        float v = 0.f;
        if (tid < 64 && tid >= off) v = s_sdt[tid - off];
        __syncthreads();
        if (tid < 64) s_sdt[tid] += v;
        __syncthreads();
    }
    if (tid < 64) s_r[tid] = expf(Ah * s_sdt[tid]);

    const float* h0src = &g_h0[(((size_t)b * NHEADS + hh) * NCH + c) * (HEADDIM * DSTATE)];
#pragma unroll
    for (int i = 0; i < 8; i++) {
        int idx = tid + i * 256;
        int r = idx >> 5, n4 = idx & 31;
        int kp = n4 >> 4, cb = n4 & 15;
        uint32_t off = (uint32_t)kp * 8192u + (uint32_t)r * 128u
                     + ((((uint32_t)cb >> 1) ^ (r & 7)) << 4) + (cb & 1) * 8;
        float4 v = *(const float4*)&h0src[r * DSTATE + n4 * 4];
        __nv_bfloat16 h0b,l0,h1,l1,h2,l2,h3,l3;
        hilo(v.x,h0b,l0); hilo(v.y,h1,l1); hilo(v.z,h2,l2); hilo(v.w,h3,l3);
        *(__nv_bfloat162*)(smem + C3_H0H + off)     = __halves2bfloat162(h0b,h1);
        *(__nv_bfloat162*)(smem + C3_H0H + off + 4) = __halves2bfloat162(h2,h3);
        *(__nv_bfloat162*)(smem + C3_H0L + off)     = __halves2bfloat162(l0,l1);
        *(__nv_bfloat162*)(smem + C3_H0L + off + 4) = __halves2bfloat162(l2,l3);
    }
    cp_wait<0>();
    __syncthreads();

    const int lgrp = lane >> 3, lr = lane & 7;
    const int a_roff = lr + (lgrp & 1) * 8;
    const int a_koff = lgrp >> 1;
    const int b_roff = lr + (lgrp >> 1) * 8;
    const int b_koff = lgrp & 1;
    const int quad = lane >> 2, qt = lane & 3;

    float acc[2][2][4];
#pragma unroll
    for (int mi = 0; mi < 2; mi++)
#pragma unroll
        for (int ni = 0; ni < 2; ni++)
#pragma unroll
            for (int q = 0; q < 4; q++) acc[mi][ni][q] = 0.f;

#pragma unroll
    for (int kp = 0; kp < 2; kp++) {
#pragma unroll
        for (int k16 = 0; k16 < 4; k16++) {
            int k2 = k16 * 2;
            uint32_t aH[2][4], aL[2][4], bH[2][2], bL[2][2];
#pragma unroll
            for (int mi = 0; mi < 2; mi++) {
                int row = wm * 32 + mi * 16 + a_roff;
                uint32_t ad = kp * 8192u + swz(row, k2 + a_koff);
                ldsm_x4(aH[mi][0], aH[mi][1], aH[mi][2], aH[mi][3], sb + C3_CPH + ad);
                ldsm_x4(aL[mi][0], aL[mi][1], aL[mi][2], aL[mi][3], sb + C3_CPL + ad);
            }
            {
                int row = wn * 16 + b_roff;
                uint32_t bd = kp * 8192u + swz(row, k2 + b_koff);
                uint32_t r0, r1, r2, r3;
                ldsm_x4(r0, r1, r2, r3, sb + C3_H0H + bd);
                bH[0][0] = r0; bH[0][1] = r1; bH[1][0] = r2; bH[1][1] = r3;
                ldsm_x4(r0, r1, r2, r3, sb + C3_H0L + bd);
                bL[0][0] = r0; bL[0][1] = r1; bL[1][0] = r2; bL[1][1] = r3;
            }
#pragma unroll
            for (int mi = 0; mi < 2; mi++)
#pragma unroll
                for (int ni = 0; ni < 2; ni++) {
                    mma_bf16(acc[mi][ni], aH[mi], bH[ni][0], bH[ni][1]);
                    mma_bf16(acc[mi][ni], aH[mi], bL[ni][0], bL[ni][1]);
                    mma_bf16(acc[mi][ni], aL[mi], bH[ni][0], bH[ni][1]);
                }
        }
    }

#pragma unroll
    for (int mi = 0; mi < 2; mi++)
#pragma unroll
        for (int ni = 0; ni < 2; ni++) {
            int t = wm * 32 + mi * 16 + quad;
            int p = wn * 16 + ni * 8 + qt * 2;
            {
                float rt = s_r[t];
                size_t o = ((size_t)b * SEQLEN + t0 + t) * DINNER + hh * HEADDIM + p;
                float2 v = *(float2*)&g_y[o];
                v.x += rt * acc[mi][ni][0];
                v.y += rt * acc[mi][ni][1];
                *(float2*)&g_y[o] = v;
            }
            {
                float rt = s_r[t + 8];
                size_t o = ((size_t)b * SEQLEN + t0 + t + 8) * DINNER + hh * HEADDIM + p;
                float2 v = *(float2*)&g_y[o];
                v.x += rt * acc[mi][ni][2];
                v.y += rt * acc[mi][ni][3];
                *(float2*)&g_y[o] = v;
            }
        }
}

// =====================================================================
// skip + gate + RMSNorm -> fp16 hi/lo for GEMM2
// =====================================================================
__global__ __launch_bounds__(256)
void gate_norm_kernel(const float* __restrict__ Dw, const float* __restrict__ norm_w)
{
    const int t = blockIdx.x;
    const int b = blockIdx.y;
    const size_t row = (size_t)b * SEQLEN + t;
    const float4* __restrict__ z4 = (const float4*)&g_zx [row * DINPROJ];
    const float4* __restrict__ x4 = (const float4*)&g_xbc[row * CONVDIM];
    const float4* __restrict__ y4 = (const float4*)&g_y  [row * DINNER];

    float4 vals[2];
    float ss = 0.f;
#pragma unroll
    for (int r = 0; r < 2; r++) {
        int f = r * 256 + threadIdx.x;
        float dv = Dw[f >> 4];
        float4 a = y4[f], xv = x4[f], zv = z4[f];
        float4 v;
        v.x = a.x + dv * xv.x;
        v.y = a.y + dv * xv.y;
        v.z = a.z + dv * xv.z;
        v.w = a.w + dv * xv.w;
        v.x *= zv.x / (1.f + expf(-zv.x));
        v.y *= zv.y / (1.f + expf(-zv.y));
        v.z *= zv.z / (1.f + expf(-zv.z));
        v.w *= zv.w / (1.f + expf(-zv.w));
        vals[r] = v;
        ss += v.x * v.x + v.y * v.y + v.z * v.z + v.w * v.w;
    }
    __shared__ float red[256];
    red[threadIdx.x] = ss;
    __syncthreads();
    for (int off = 128; off > 0; off >>= 1) {
        if (threadIdx.x < off) red[threadIdx.x] += red[threadIdx.x + off];
        __syncthreads();
    }
    float scale = rsqrtf(red[0] / (float)DINNER + EPS);
    __half2* outh = (__half2*)&g_ynh[row * DINNER];
    __half2* outl = (__half2*)&g_ynl[row * DINNER];
    const float4* nw4 = (const float4*)norm_w;
#pragma unroll
    for (int r = 0; r < 2; r++) {
        int f = r * 256 + threadIdx.x;
        float4 w = nw4[f];
        float4 v = vals[r];
        v.x *= scale * w.x; v.y *= scale * w.y; v.z *= scale * w.z; v.w *= scale * w.w;
        split4h(v, outh, outl, f);
    }
}

// =====================================================================
extern "C" void kernel_launch(void* const* d_in, const int* in_sizes, int n_in,
                              void* d_out, int out_size)
{
    const float* x          = (const float*)d_in[0];
    const float* in_proj_w  = (const float*)d_in[1];
    const float* conv_w     = (const float*)d_in[2];
    const float* conv_b     = (const float*)d_in[3];
    const float* dt_bias    = (const float*)d_in[4];
    const float* A_log      = (const float*)d_in[5];
    const float* Dw         = (const float*)d_in[6];
    const float* norm_w     = (const float*)d_in[7];
    const float* out_proj_w = (const float*)d_in[8];
    float* out = (float*)d_out;

    float *p_zx = nullptr;
    void *p_xh, *p_xl, *p_w1h, *p_w2h, *p_ynh, *p_ynl;
    cudaGetSymbolAddress((void**)&p_zx, g_zx);
    cudaGetSymbolAddress(&p_xh,  g_xh);  cudaGetSymbolAddress(&p_xl,  g_xl);
    cudaGetSymbolAddress(&p_w1h, g_w1h); cudaGetSymbolAddress(&p_w2h, g_w2h);
    cudaGetSymbolAddress(&p_ynh, g_ynh); cudaGetSymbolAddress(&p_ynl, g_ynl);

    cudaFuncSetAttribute(gemm_mma<false>, cudaFuncAttributeMaxDynamicSharedMemorySize, SMEM_GEMM);
    cudaFuncSetAttribute(gemm_mma<true>,  cudaFuncAttributeMaxDynamicSharedMemorySize, SMEM_GEMM);
    cudaFuncSetAttribute(ssd_chunk_kernel, cudaFuncAttributeMaxDynamicSharedMemorySize, SMEM_SSD1);
    cudaFuncSetAttribute(ssd_carry_kernel, cudaFuncAttributeMaxDynamicSharedMemorySize, SMEM_SSD3);

    // 0) fp32 -> fp16 conversions (x hi/lo; weights single)
    {
        int total4 = N4_X + N4_W1 + N4_W2;
        cvt_all<<<(total4 + 255)/256, 256>>>(
            (const float4*)x, (const float4*)in_proj_w, (const float4*)out_proj_w);
    }

    // 1) zxbcdt = x @ in_proj_w^T
    gemm_mma<false><<<dim3((DINPROJ + BN - 1)/BN, ROWS/BM), 256, SMEM_GEMM>>>(
        (const __half*)p_xh, (const __half*)p_xl, (const __half*)p_w1h,
        nullptr, p_zx, DINPROJ, DMODEL);

    // 2) conv + SiLU; dt softplus
    conv_act_kernel<<<dim3(CONVDIM/256, SEQLEN/4, BATCH), 256>>>(conv_w, conv_b, dt_bias);

    // 2b) pack B/C once (shared across all heads)
    pack_bc_kernel<<<512, 256>>>();

    // 3) SSD scan
    ssd_chunk_kernel<<<dim3(NCH, BATCH, NHEADS), 256, SMEM_SSD1>>>(A_log);
    ssd_prop_kernel<<<dim3(BATCH * NHEADS, 4), 256>>>(A_log);
    ssd_carry_kernel<<<dim3(NCH - 1, BATCH, NHEADS), 256, SMEM_SSD3>>>(A_log);

    // 4) skip + gate + RMSNorm
    gate_norm_kernel<<<dim3(SEQLEN, BATCH), 256>>>(Dw, norm_w);

    // 5) out = x + yn @ out_proj_w^T
    gemm_mma<true><<<dim3(DMODEL/BN, ROWS/BM), 256, SMEM_GEMM>>>(
        (const __half*)p_ynh, (const __half*)p_ynl, (const __half*)p_w2h,
        x, out, DMODEL, DINNER);
}

// round 12
// speedup vs baseline: 1.6437x; 1.2728x over previous
#include <cuda_runtime.h>
#include <cuda_bf16.h>
#include <cuda_fp16.h>
#include <math.h>
#include <stdint.h>

// ---------------- problem constants ----------------
#define BATCH    2
#define SEQLEN   1024
#define DMODEL   1024
#define DINNER   2048
#define NHEADS   32
#define HEADDIM  64
#define DSTATE   128
#define DCONV    4
#define CONVDIM  2304
#define DINPROJ  4384
#define ROWS     (BATCH*SEQLEN)
#define EPS      1e-5f
#define CLEN     64
#define NCH      (SEQLEN/CLEN)     // 16 chunks

// ---------------- scratch ----------------
__device__ __align__(1024) float g_zx [ROWS*DINPROJ];
__device__ __align__(1024) float g_xbc[ROWS*CONVDIM];
__device__ __align__(1024) float g_dt [ROWS*NHEADS];
__device__ __align__(1024) float g_y  [ROWS*DINNER];
__device__ __align__(1024) float g_hc [BATCH*NHEADS*NCH*HEADDIM*DSTATE];
__device__ __align__(1024) float g_h0 [BATCH*NHEADS*NCH*HEADDIM*DSTATE];
__device__ __align__(1024) float g_pi [BATCH*NHEADS*NCH];
// pre-swizzled bf16 hi/lo B and C panel tiles (SSD path)
#define PTILES (BATCH*NCH*2)
__device__ __align__(1024) __nv_bfloat16 g_pBh[PTILES*4096];
__device__ __align__(1024) __nv_bfloat16 g_pBl[PTILES*4096];
__device__ __align__(1024) __nv_bfloat16 g_pCh[PTILES*4096];
__device__ __align__(1024) __nv_bfloat16 g_pCl[PTILES*4096];
// fp16 operands for the two big GEMMs (single-precision fp16, 1-pass)
__device__ __align__(1024) __half g_xh [ROWS*DMODEL];
__device__ __align__(1024) __half g_w1h[DINPROJ*DMODEL];
__device__ __align__(1024) __half g_w2h[DMODEL*DINNER];
__device__ __align__(1024) __half g_ynh[ROWS*DINNER];

// ---------------- primitives ----------------
__device__ __forceinline__ uint32_t smem_u32(const void* p) {
    uint32_t a;
    asm("{ .reg .u64 t; cvta.to.shared.u64 t, %1; cvt.u32.u64 %0, t; }" : "=r"(a) : "l"(p));
    return a;
}
__device__ __forceinline__ void cp16(uint32_t dst, const void* src) {
    asm volatile("cp.async.cg.shared.global [%0], [%1], 16;" :: "r"(dst), "l"(src));
}
__device__ __forceinline__ void cp_commit() { asm volatile("cp.async.commit_group;" ::: "memory"); }
template<int W> __device__ __forceinline__ void cp_wait() {
    asm volatile("cp.async.wait_group %0;" :: "n"(W) : "memory");
}
__device__ __forceinline__ void ldsm_x4(uint32_t& r0, uint32_t& r1, uint32_t& r2, uint32_t& r3, uint32_t a) {
    asm volatile("ldmatrix.sync.aligned.m8n8.x4.shared.b16 {%0,%1,%2,%3}, [%4];"
                 : "=r"(r0), "=r"(r1), "=r"(r2), "=r"(r3) : "r"(a));
}
__device__ __forceinline__ void ldsm_x4_t(uint32_t& r0, uint32_t& r1, uint32_t& r2, uint32_t& r3, uint32_t a) {
    asm volatile("ldmatrix.sync.aligned.m8n8.x4.trans.shared.b16 {%0,%1,%2,%3}, [%4];"
                 : "=r"(r0), "=r"(r1), "=r"(r2), "=r"(r3) : "r"(a));
}
__device__ __forceinline__ void mma_bf16(float* c, const uint32_t* a, uint32_t b0, uint32_t b1) {
    asm volatile(
        "mma.sync.aligned.m16n8k16.row.col.f32.bf16.bf16.f32 "
        "{%0,%1,%2,%3}, {%4,%5,%6,%7}, {%8,%9}, {%0,%1,%2,%3};"
        : "+f"(c[0]), "+f"(c[1]), "+f"(c[2]), "+f"(c[3])
        : "r"(a[0]), "r"(a[1]), "r"(a[2]), "r"(a[3]), "r"(b0), "r"(b1));
}
__device__ __forceinline__ void mma_fp16(float* c, const uint32_t* a, uint32_t b0, uint32_t b1) {
    asm volatile(
        "mma.sync.aligned.m16n8k16.row.col.f32.f16.f16.f32 "
        "{%0,%1,%2,%3}, {%4,%5,%6,%7}, {%8,%9}, {%0,%1,%2,%3};"
        : "+f"(c[0]), "+f"(c[1]), "+f"(c[2]), "+f"(c[3])
        : "r"(a[0]), "r"(a[1]), "r"(a[2]), "r"(a[3]), "r"(b0), "r"(b1));
}
__device__ __forceinline__ uint32_t swz(int row, int seg) {
    return (uint32_t)(row * 128 + ((seg ^ (row & 7)) << 4));
}
__device__ __forceinline__ uint32_t swzb(int row, int colb) {
    return (uint32_t)(row * 128 + (((colb >> 4) ^ (row & 7)) << 4) + (colb & 15));
}
__device__ __forceinline__ void hilo(float v, __nv_bfloat16& h, __nv_bfloat16& l) {
    h = __float2bfloat16(v);
    l = __float2bfloat16(v - __bfloat162float(h));
}

// =====================================================================
// Tensor-core GEMM, fp16 1-pass: C = Ah @ Wh^T (+residual)
// BM128/BN128, K-chunk 64, 2 tiles/stage (A, W), 3-stage pipeline (96KB).
// =====================================================================
#define BM 128
#define BN 128
#define KC 64
#define TILE_B   16384u
#define STAGE_B  (2u*TILE_B)
#define NSTAGE   3
#define SMEM_GEMM (NSTAGE*STAGE_B)     // 98304

template<bool RES>
__global__ __launch_bounds__(256, 1)
void gemm_mma(const __half* __restrict__ Ahp, const __half* __restrict__ Bhp,
              const float* __restrict__ resid, float* __restrict__ C,
              int N, int K)
{
    extern __shared__ __align__(1024) char smem[];
    const uint32_t sb = smem_u32(smem);

    const int tid = threadIdx.x;
    const int wid = tid >> 5, lane = tid & 31;
    const int wm = wid & 1, wn = wid >> 1;
    const int m0 = blockIdx.y * BM, n0 = blockIdx.x * BN;
    const int NC = K / KC;

    int lrow[4], lseg[4];
#pragma unroll
    for (int it = 0; it < 4; it++) {
        int idx = tid + it * 256;
        lrow[it] = idx >> 3;
        lseg[it] = idx & 7;
    }

    auto load_chunk = [&](int stage, int k0) {
        uint32_t s = sb + stage * STAGE_B;
#pragma unroll
        for (int it = 0; it < 4; it++) {
            int row = lrow[it], seg = lseg[it];
            uint32_t d = swz(row, seg);
            size_t aoff = (size_t)(m0 + row) * K + k0 + seg * 8;
            cp16(s + d, Ahp + aoff);
            int brow = n0 + row; if (brow >= N) brow = N - 1;
            size_t boff = (size_t)brow * K + k0 + seg * 8;
            cp16(s + TILE_B + d, Bhp + boff);
        }
        cp_commit();
    };

    float acc[4][4][4];
#pragma unroll
    for (int mi = 0; mi < 4; mi++)
#pragma unroll
        for (int ni = 0; ni < 4; ni++)
#pragma unroll
            for (int q = 0; q < 4; q++) acc[mi][ni][q] = 0.f;

    const int lgrp = lane >> 3, lr = lane & 7;
    const int a_roff = lr + (lgrp & 1) * 8;
    const int a_koff = lgrp >> 1;
    const int b_roff = lr + (lgrp >> 1) * 8;
    const int b_koff = lgrp & 1;

    load_chunk(0, 0);
    load_chunk(1, KC);

    for (int c = 0; c < NC; c++) {
        if (c + 2 < NC) load_chunk((c + 2) % NSTAGE, (c + 2) * KC);
        else            cp_commit();
        cp_wait<2>();
        __syncthreads();

        uint32_t s = sb + (c % NSTAGE) * STAGE_B;
#pragma unroll
        for (int k16 = 0; k16 < 4; k16++) {
            int k2 = k16 * 2;
            uint32_t ah[4][4], bh[4][2];
#pragma unroll
            for (int mi = 0; mi < 4; mi++) {
                int row = wm * 64 + mi * 16 + a_roff;
                uint32_t ad = swz(row, k2 + a_koff);
                ldsm_x4(ah[mi][0], ah[mi][1], ah[mi][2], ah[mi][3], s + ad);
            }
#pragma unroll
            for (int nj = 0; nj < 2; nj++) {
                int row = wn * 32 + nj * 16 + b_roff;
                uint32_t bd = swz(row, k2 + b_koff);
                uint32_t r0, r1, r2, r3;
                ldsm_x4(r0, r1, r2, r3, s + TILE_B + bd);
                bh[nj * 2][0] = r0; bh[nj * 2][1] = r1;
                bh[nj * 2 + 1][0] = r2; bh[nj * 2 + 1][1] = r3;
            }
#pragma unroll
            for (int mi = 0; mi < 4; mi++)
#pragma unroll
                for (int ni = 0; ni < 4; ni++)
                    mma_fp16(acc[mi][ni], ah[mi], bh[ni][0], bh[ni][1]);
        }
        __syncthreads();
    }

    const int quad = lane >> 2, qt = lane & 3;
#pragma unroll
    for (int mi = 0; mi < 4; mi++) {
#pragma unroll
        for (int ni = 0; ni < 4; ni++) {
            int gm = m0 + wm * 64 + mi * 16 + quad;
            int gn = n0 + wn * 32 + ni * 8 + qt * 2;
            if (gn < N) {
                {
                    float2 v = make_float2(acc[mi][ni][0], acc[mi][ni][1]);
                    size_t o = (size_t)gm * N + gn;
                    if (RES) { float2 rv = *(const float2*)(resid + o); v.x += rv.x; v.y += rv.y; }
                    *(float2*)(C + o) = v;
                }
                {
                    float2 v = make_float2(acc[mi][ni][2], acc[mi][ni][3]);
                    size_t o = (size_t)(gm + 8) * N + gn;
                    if (RES) { float2 rv = *(const float2*)(resid + o); v.x += rv.x; v.y += rv.y; }
                    *(float2*)(C + o) = v;
                }
            }
        }
    }
}

// =====================================================================
// fp32 -> fp16 conversions (all single fp16)
// =====================================================================
#define N4_X  (ROWS*DMODEL/4)
#define N4_W1 (DINPROJ*DMODEL/4)
#define N4_W2 (DMODEL*DINNER/4)

__device__ __forceinline__ void cvt4h(float4 v, __half2* hi, int i) {
    hi[i * 2]     = __halves2half2(__float2half_rn(v.x), __float2half_rn(v.y));
    hi[i * 2 + 1] = __halves2half2(__float2half_rn(v.z), __float2half_rn(v.w));
}

__global__ __launch_bounds__(256)
void cvt_all(const float4* __restrict__ x, const float4* __restrict__ w1,
             const float4* __restrict__ w2)
{
    int i = blockIdx.x * 256 + threadIdx.x;
    if (i < N4_X) {
        cvt4h(x[i], (__half2*)g_xh, i);
    } else if (i < N4_X + N4_W1) {
        int j = i - N4_X;
        cvt4h(w1[j], (__half2*)g_w1h, j);
    } else if (i < N4_X + N4_W1 + N4_W2) {
        int j = i - N4_X - N4_W1;
        cvt4h(w2[j], (__half2*)g_w2h, j);
    }
}

// =====================================================================
// Causal depthwise conv + SiLU; dt softplus
// =====================================================================
__global__ __launch_bounds__(256)
void conv_act_kernel(const float* __restrict__ conv_w, const float* __restrict__ conv_b,
                     const float* __restrict__ dt_bias)
{
    const int c  = blockIdx.x * 256 + threadIdx.x;
    const int tb = blockIdx.y * 4;
    const int b  = blockIdx.z;

    float w0 = conv_w[c * 4 + 0], w1 = conv_w[c * 4 + 1];
    float w2 = conv_w[c * 4 + 2], w3 = conv_w[c * 4 + 3];
    float bias = conv_b[c];

    float v[7];
#pragma unroll
    for (int k = 0; k < 7; k++) {
        int tt = tb - 3 + k;
        v[k] = (tt >= 0) ? g_zx[((size_t)b * SEQLEN + tt) * DINPROJ + DINNER + c] : 0.f;
    }
#pragma unroll
    for (int i = 0; i < 4; i++) {
        float a = bias + v[i] * w0 + v[i + 1] * w1 + v[i + 2] * w2 + v[i + 3] * w3;
        g_xbc[((size_t)b * SEQLEN + tb + i) * CONVDIM + c] = a / (1.f + expf(-a));
    }
    if (blockIdx.x == 0 && threadIdx.x < NHEADS) {
        int hh = threadIdx.x;
        float bth = dt_bias[hh];
#pragma unroll
        for (int i = 0; i < 4; i++) {
            size_t row = (size_t)b * SEQLEN + tb + i;
            float raw = g_zx[row * DINPROJ + (DINNER + CONVDIM) + hh] + bth;
            g_dt[row * NHEADS + hh] = (raw > 20.f) ? raw : log1pf(expf(raw));
        }
    }
}

// =====================================================================
// pack B/C into pre-swizzled bf16 hi/lo tiles (shared by all heads)
// =====================================================================
__global__ __launch_bounds__(256)
void pack_bc_kernel()
{
    int u = blockIdx.x * 256 + threadIdx.x;
    int s   = u & 7;
    int t   = (u >> 3) & 63;
    int kp  = (u >> 9) & 1;
    int ch  = (u >> 10) & 15;
    int b   = (u >> 14) & 1;
    int isC = (u >> 15);

    size_t src = ((size_t)b * SEQLEN + ch * 64 + t) * CONVDIM
               + DINNER + (isC ? DSTATE : 0) + kp * 64 + s * 8;
    float4 v0 = *(const float4*)&g_xbc[src];
    float4 v1 = *(const float4*)&g_xbc[src + 4];

    __nv_bfloat16 h[8], l[8];
    hilo(v0.x, h[0], l[0]); hilo(v0.y, h[1], l[1]);
    hilo(v0.z, h[2], l[2]); hilo(v0.w, h[3], l[3]);
    hilo(v1.x, h[4], l[4]); hilo(v1.y, h[5], l[5]);
    hilo(v1.z, h[6], l[6]); hilo(v1.w, h[7], l[7]);

    __nv_bfloat162 ph[4], pl[4];
#pragma unroll
    for (int j = 0; j < 4; j++) {
        ph[j] = __halves2bfloat162(h[j * 2], h[j * 2 + 1]);
        pl[j] = __halves2bfloat162(l[j * 2], l[j * 2 + 1]);
    }

    size_t off = (size_t)(((b * NCH + ch) * 2) + kp) * 4096 + t * 64 + ((s ^ (t & 7)) * 8);
    __nv_bfloat16* dh = (isC ? g_pCh : g_pBh) + off;
    __nv_bfloat16* dl = (isC ? g_pCl : g_pBl) + off;
    *(uint4*)dh = *(uint4*)ph;
    *(uint4*)dl = *(uint4*)pl;
}

// =====================================================================
// SSD phase 1 (unchanged)
// =====================================================================
#define OFF_CPH 0u
#define OFF_CPL 16384u
#define OFF_BPH 32768u
#define OFF_BPL 49152u
#define OFF_UTH 65536u
#define OFF_UTL 73728u
#define OFF_UWH 81920u
#define OFF_UWL 90112u
#define OFF_GH  OFF_CPH
#define OFF_GL  (OFF_CPH + 8192u)
#define OFF_SDT 98304u
#define OFF_DTS 98560u
#define OFF_WS  98816u
#define SMEM_SSD1 99072u

__global__ __launch_bounds__(256, 2)
void ssd_chunk_kernel(const float* __restrict__ A_log)
{
    extern __shared__ __align__(1024) char smem[];
    const uint32_t sb = smem_u32(smem);
    const int c = blockIdx.x, b = blockIdx.y, hh = blockIdx.z;
    const int tid = threadIdx.x;
    const int wid = tid >> 5, lane = tid & 31;
    const int wm = wid & 1, wn = wid >> 1;
    const int t0 = c * CLEN;
    const float Ah = -expf(A_log[hh]);

    {
        size_t tb = (size_t)((b * NCH + c) * 2) * 4096;
#pragma unroll
        for (int i = 0; i < 4; i++) {
            int idx = tid + i * 256;
            cp16(sb + OFF_BPH + idx * 16, g_pBh + tb + idx * 8);
            cp16(sb + OFF_BPL + idx * 16, g_pBl + tb + idx * 8);
            cp16(sb + OFF_CPH + idx * 16, g_pCh + tb + idx * 8);
            cp16(sb + OFF_CPL + idx * 16, g_pCl + tb + idx * 8);
        }
        cp_commit();
    }

    float* s_sdt = (float*)(smem + OFF_SDT);
    float* s_dt  = (float*)(smem + OFF_DTS);
    float* s_w   = (float*)(smem + OFF_WS);

    if (tid < 64) {
        float d = g_dt[((size_t)b * SEQLEN + t0 + tid) * NHEADS + hh];
        s_dt[tid] = d;
        s_sdt[tid] = d;
    }
    __syncthreads();
#pragma unroll
    for (int off = 1; off < 64; off <<= 1) {
        float v = 0.f;
        if (tid < 64 && tid >= off) v = s_sdt[tid - off];
        __syncthreads();
        if (tid < 64) s_sdt[tid] += v;
        __syncthreads();
    }
    float sdtTOT = s_sdt[63];
    if (tid < 64) s_w[tid] = expf(Ah * (sdtTOT - s_sdt[tid]));
    if (tid == 0) g_pi[((size_t)b * NHEADS + hh) * NCH + c] = sdtTOT;
    __syncthreads();

#pragma unroll
    for (int i = 0; i < 4; i++) {
        int idx = tid + i * 256;
        int t = idx >> 4, p4 = idx & 15;
        size_t row = ((size_t)b * SEQLEN + t0 + t) * CONVDIM;
        float4 xv = *(const float4*)&g_xbc[row + hh * HEADDIM + p4 * 4];
        float dtv = s_dt[t], wv = s_w[t];
        float u0 = dtv*xv.x, u1 = dtv*xv.y, u2 = dtv*xv.z, u3 = dtv*xv.w;
        uint32_t off = swzb(t, p4 * 8);
        __nv_bfloat16 h0,l0,h1,l1,h2,l2,h3,l3;
        hilo(u0,h0,l0); hilo(u1,h1,l1); hilo(u2,h2,l2); hilo(u3,h3,l3);
        *(__nv_bfloat162*)(smem + OFF_UTH + off)     = __halves2bfloat162(h0,h1);
        *(__nv_bfloat162*)(smem + OFF_UTH + off + 4) = __halves2bfloat162(h2,h3);
        *(__nv_bfloat162*)(smem + OFF_UTL + off)     = __halves2bfloat162(l0,l1);
        *(__nv_bfloat162*)(smem + OFF_UTL + off + 4) = __halves2bfloat162(l2,l3);
        hilo(u0*wv,h0,l0); hilo(u1*wv,h1,l1); hilo(u2*wv,h2,l2); hilo(u3*wv,h3,l3);
        *(__nv_bfloat162*)(smem + OFF_UWH + off)     = __halves2bfloat162(h0,h1);
        *(__nv_bfloat162*)(smem + OFF_UWH + off + 4) = __halves2bfloat162(h2,h3);
        *(__nv_bfloat162*)(smem + OFF_UWL + off)     = __halves2bfloat162(l0,l1);
        *(__nv_bfloat162*)(smem + OFF_UWL + off + 4) = __halves2bfloat162(l2,l3);
    }
    cp_wait<0>();
    __syncthreads();

    const int lgrp = lane >> 3, lr = lane & 7;
    const int a_roff = lr + (lgrp & 1) * 8;
    const int a_koff = lgrp >> 1;
    const int b_roff = lr + (lgrp >> 1) * 8;
    const int b_koff = lgrp & 1;
    const int quad = lane >> 2, qt = lane & 3;
    const int bt_row = lr + (lgrp & 1) * 8;
    const int bt_col = (lgrp >> 1) * 8;
    const int at_row = lr + (lgrp >> 1) * 8;
    const int at_col = (lgrp & 1) * 8;

    // GEMM2: G = C @ B^T
    float accG[2][2][4];
#pragma unroll
    for (int mi = 0; mi < 2; mi++)
#pragma unroll
        for (int ni = 0; ni < 2; ni++)
#pragma unroll
            for (int q = 0; q < 4; q++) accG[mi][ni][q] = 0.f;

#pragma unroll
    for (int kp = 0; kp < 2; kp++) {
#pragma unroll
        for (int k16 = 0; k16 < 4; k16++) {
            int k2 = k16 * 2;
            uint32_t aH[2][4], aL[2][4], bH[2][2], bL[2][2];
#pragma unroll
            for (int mi = 0; mi < 2; mi++) {
                int row = wm * 32 + mi * 16 + a_roff;
                uint32_t ad = kp * 8192u + swz(row, k2 + a_koff);
                ldsm_x4(aH[mi][0], aH[mi][1], aH[mi][2], aH[mi][3], sb + OFF_CPH + ad);
                ldsm_x4(aL[mi][0], aL[mi][1], aL[mi][2], aL[mi][3], sb + OFF_CPL + ad);
            }
            {
                int row = wn * 16 + b_roff;
                uint32_t bd = kp * 8192u + swz(row, k2 + b_koff);
                uint32_t r0, r1, r2, r3;
                ldsm_x4(r0, r1, r2, r3, sb + OFF_BPH + bd);
                bH[0][0] = r0; bH[0][1] = r1; bH[1][0] = r2; bH[1][1] = r3;
                ldsm_x4(r0, r1, r2, r3, sb + OFF_BPL + bd);
                bL[0][0] = r0; bL[0][1] = r1; bL[1][0] = r2; bL[1][1] = r3;
            }
#pragma unroll
            for (int mi = 0; mi < 2; mi++)
#pragma unroll
                for (int ni = 0; ni < 2; ni++) {
                    mma_bf16(accG[mi][ni], aH[mi], bH[ni][0], bH[ni][1]);
                    mma_bf16(accG[mi][ni], aH[mi], bL[ni][0], bL[ni][1]);
                    mma_bf16(accG[mi][ni], aL[mi], bH[ni][0], bH[ni][1]);
                }
        }
    }
    __syncthreads();

#pragma unroll
    for (int mi = 0; mi < 2; mi++)
#pragma unroll
        for (int ni = 0; ni < 2; ni++)
#pragma unroll
            for (int half = 0; half < 2; half++) {
                int t = wm * 32 + mi * 16 + quad + half * 8;
                int s = wn * 16 + ni * 8 + qt * 2;
                float sdt_t = s_sdt[t];
                float v0 = accG[mi][ni][half * 2 + 0];
                float v1 = accG[mi][ni][half * 2 + 1];
                v0 = (t >= s)     ? v0 * expf(Ah * (sdt_t - s_sdt[s]))     : 0.f;
                v1 = (t >= s + 1) ? v1 * expf(Ah * (sdt_t - s_sdt[s + 1])) : 0.f;
                __nv_bfloat16 h0,l0,h1,l1;
                hilo(v0,h0,l0); hilo(v1,h1,l1);
                uint32_t off = swzb(t, s * 2);
                *(__nv_bfloat162*)(smem + OFF_GH + off) = __halves2bfloat162(h0,h1);
                *(__nv_bfloat162*)(smem + OFF_GL + off) = __halves2bfloat162(l0,l1);
            }
    __syncthreads();

    // GEMM4: Y = G @ U
    {
        float accY[2][2][4];
#pragma unroll
        for (int mi = 0; mi < 2; mi++)
#pragma unroll
            for (int ni = 0; ni < 2; ni++)
#pragma unroll
                for (int q = 0; q < 4; q++) accY[mi][ni][q] = 0.f;

#pragma unroll
        for (int k16 = 0; k16 < 4; k16++) {
            int k2 = k16 * 2, kb = k16 * 16;
            uint32_t aH[2][4], aL[2][4], bH[2][2], bL[2][2];
#pragma unroll
            for (int mi = 0; mi < 2; mi++) {
                int row = wm * 32 + mi * 16 + a_roff;
                uint32_t ad = swz(row, k2 + a_koff);
                ldsm_x4(aH[mi][0], aH[mi][1], aH[mi][2], aH[mi][3], sb + OFF_GH + ad);
                ldsm_x4(aL[mi][0], aL[mi][1], aL[mi][2], aL[mi][3], sb + OFF_GL + ad);
            }
            {
                int row = kb + bt_row;
                int col = wn * 16 + bt_col;
                uint32_t bd = swzb(row, col * 2);
                uint32_t r0, r1, r2, r3;
                ldsm_x4_t(r0, r1, r2, r3, sb + OFF_UTH + bd);
                bH[0][0] = r0; bH[0][1] = r1; bH[1][0] = r2; bH[1][1] = r3;
                ldsm_x4_t(r0, r1, r2, r3, sb + OFF_UTL + bd);
                bL[0][0] = r0; bL[0][1] = r1; bL[1][0] = r2; bL[1][1] = r3;
            }
#pragma unroll
            for (int mi = 0; mi < 2; mi++)
#pragma unroll
                for (int ni = 0; ni < 2; ni++) {
                    mma_bf16(accY[mi][ni], aH[mi], bH[ni][0], bH[ni][1]);
                    mma_bf16(accY[mi][ni], aH[mi], bL[ni][0], bL[ni][1]);
                    mma_bf16(accY[mi][ni], aL[mi], bH[ni][0], bH[ni][1]);
                }
        }
#pragma unroll
        for (int mi = 0; mi < 2; mi++)
#pragma unroll
            for (int ni = 0; ni < 2; ni++) {
                int t = wm * 32 + mi * 16 + quad;
                int p = wn * 16 + ni * 8 + qt * 2;
                size_t o = ((size_t)b * SEQLEN + t0 + t) * DINNER + hh * HEADDIM + p;
                *(float2*)&g_y[o] = make_float2(accY[mi][ni][0], accY[mi][ni][1]);
                o += (size_t)8 * DINNER;
                *(float2*)&g_y[o] = make_float2(accY[mi][ni][2], accY[mi][ni][3]);
            }
    }

    // GEMM5: Hc = Uw^T-form @ B
    {
        float accH[2][4][4];
#pragma unroll
        for (int mi = 0; mi < 2; mi++)
#pragma unroll
            for (int ni = 0; ni < 4; ni++)
#pragma unroll
                for (int q = 0; q < 4; q++) accH[mi][ni][q] = 0.f;

#pragma unroll
        for (int k16 = 0; k16 < 4; k16++) {
            int kb = k16 * 16;
            uint32_t aH[2][4], aL[2][4], bH[4][2], bL[4][2];
#pragma unroll
            for (int mi = 0; mi < 2; mi++) {
                int row = kb + at_row;
                int col = wm * 32 + mi * 16 + at_col;
                uint32_t ad = swzb(row, col * 2);
                ldsm_x4_t(aH[mi][0], aH[mi][1], aH[mi][2], aH[mi][3], sb + OFF_UWH + ad);
                ldsm_x4_t(aL[mi][0], aL[mi][1], aL[mi][2], aL[mi][3], sb + OFF_UWL + ad);
            }
#pragma unroll
            for (int nj = 0; nj < 2; nj++) {
                int n0 = wn * 32 + nj * 16;
                int kp = n0 >> 6, ncol = n0 & 63;
                int row = kb + bt_row;
                int col = ncol + bt_col;
                uint32_t bd = kp * 8192u + swzb(row, col * 2);
                uint32_t r0, r1, r2, r3;
                ldsm_x4_t(r0, r1, r2, r3, sb + OFF_BPH + bd);
                bH[nj*2][0] = r0; bH[nj*2][1] = r1; bH[nj*2+1][0] = r2; bH[nj*2+1][1] = r3;
                ldsm_x4_t(r0, r1, r2, r3, sb + OFF_BPL + bd);
                bL[nj*2][0] = r0; bL[nj*2][1] = r1; bL[nj*2+1][0] = r2; bL[nj*2+1][1] = r3;
            }
#pragma unroll
            for (int mi = 0; mi < 2; mi++)
#pragma unroll
                for (int ni = 0; ni < 4; ni++) {
                    mma_bf16(accH[mi][ni], aH[mi], bH[ni][0], bH[ni][1]);
                    mma_bf16(accH[mi][ni], aH[mi], bL[ni][0], bL[ni][1]);
                    mma_bf16(accH[mi][ni], aL[mi], bH[ni][0], bH[ni][1]);
                }
        }
        float* hc = &g_hc[(((size_t)b * NHEADS + hh) * NCH + c) * (HEADDIM * DSTATE)];
#pragma unroll
        for (int mi = 0; mi < 2; mi++)
#pragma unroll
            for (int ni = 0; ni < 4; ni++) {
                int p = wm * 32 + mi * 16 + quad;
                int n = wn * 32 + ni * 8 + qt * 2;
                *(float2*)&hc[p * DSTATE + n] = make_float2(accH[mi][ni][0], accH[mi][ni][1]);
                *(float2*)&hc[(p + 8) * DSTATE + n] = make_float2(accH[mi][ni][2], accH[mi][ni][3]);
            }
    }
}

// =====================================================================
// SSD phase 2
// =====================================================================
__global__ __launch_bounds__(256)
void ssd_prop_kernel(const float* __restrict__ A_log)
{
    const int bh = blockIdx.x;
    const int q  = blockIdx.y;
    const int hh = bh & (NHEADS - 1);
    const int tid = threadIdx.x;
    const float Ah = -expf(A_log[hh]);
    const int base = q * 512 + tid * 2;

    float4 acc[2];
    acc[0] = make_float4(0.f, 0.f, 0.f, 0.f);
    acc[1] = make_float4(0.f, 0.f, 0.f, 0.f);

    for (int c = 1; c < NCH; c++) {
        float Pi = expf(Ah * g_pi[(size_t)bh * NCH + c - 1]);
        const float4* hc = (const float4*)&g_hc[((size_t)bh * NCH + c - 1) * (HEADDIM * DSTATE)];
        float4* h0 = (float4*)&g_h0[((size_t)bh * NCH + c) * (HEADDIM * DSTATE)];
#pragma unroll
        for (int j = 0; j < 2; j++) {
            float4 v = hc[base + j];
            acc[j].x = Pi * acc[j].x + v.x;
            acc[j].y = Pi * acc[j].y + v.y;
            acc[j].z = Pi * acc[j].z + v.z;
            acc[j].w = Pi * acc[j].w + v.w;
            h0[base + j] = acc[j];
        }
    }
}

// =====================================================================
// SSD phase 3
// =====================================================================
#define C3_CPH 0u
#define C3_CPL 16384u
#define C3_H0H 32768u
#define C3_H0L 49152u
#define C3_SDT 65536u
#define C3_R   65792u
#define SMEM_SSD3 66560u

__global__ __launch_bounds__(256, 2)
void ssd_carry_kernel(const float* __restrict__ A_log)
{
    extern __shared__ __align__(1024) char smem[];
    const uint32_t sb = smem_u32(smem);
    const int c = blockIdx.x + 1, b = blockIdx.y, hh = blockIdx.z;
    const int tid = threadIdx.x;
    const int wid = tid >> 5, lane = tid & 31;
    const int wm = wid & 1, wn = wid >> 1;
    const int t0 = c * CLEN;
    const float Ah = -expf(A_log[hh]);

    {
        size_t tb = (size_t)((b * NCH + c) * 2) * 4096;
#pragma unroll
        for (int i = 0; i < 4; i++) {
            int idx = tid + i * 256;
            cp16(sb + C3_CPH + idx * 16, g_pCh + tb + idx * 8);
            cp16(sb + C3_CPL + idx * 16, g_pCl + tb + idx * 8);
        }
        cp_commit();
    }

    float* s_sdt = (float*)(smem + C3_SDT);
    float* s_r   = (float*)(smem + C3_R);

    if (tid < 64)
        s_sdt[tid] = g_dt[((size_t)b * SEQLEN + t0 + tid) * NHEADS + hh];
    __syncthreads();
#pragma unroll
    for (int off = 1; off < 64; off <<= 1) {
        float v = 0.f;
        if (tid < 64 && tid >= off) v = s_sdt[tid - off];
        __syncthreads();
        if (tid < 64) s_sdt[tid] += v;
        __syncthreads();
    }
    if (tid < 64) s_r[tid] = expf(Ah * s_sdt[tid]);

    const float* h0src = &g_h0[(((size_t)b * NHEADS + hh) * NCH + c) * (HEADDIM * DSTATE)];
#pragma unroll
    for (int i = 0; i < 8; i++) {
        int idx = tid + i * 256;
        int r = idx >> 5, n4 = idx & 31;
        int kp = n4 >> 4, cb = n4 & 15;
        uint32_t off = (uint32_t)kp * 8192u + (uint32_t)r * 128u
                     + ((((uint32_t)cb >> 1) ^ (r & 7)) << 4) + (cb & 1) * 8;
        float4 v = *(const float4*)&h0src[r * DSTATE + n4 * 4];
        __nv_bfloat16 h0b,l0,h1,l1,h2,l2,h3,l3;
        hilo(v.x,h0b,l0); hilo(v.y,h1,l1); hilo(v.z,h2,l2); hilo(v.w,h3,l3);
        *(__nv_bfloat162*)(smem + C3_H0H + off)     = __halves2bfloat162(h0b,h1);
        *(__nv_bfloat162*)(smem + C3_H0H + off + 4) = __halves2bfloat162(h2,h3);
        *(__nv_bfloat162*)(smem + C3_H0L + off)     = __halves2bfloat162(l0,l1);
        *(__nv_bfloat162*)(smem + C3_H0L + off + 4) = __halves2bfloat162(l2,l3);
    }
    cp_wait<0>();
    __syncthreads();

    const int lgrp = lane >> 3, lr = lane & 7;
    const int a_roff = lr + (lgrp & 1) * 8;
    const int a_koff = lgrp >> 1;
    const int b_roff = lr + (lgrp >> 1) * 8;
    const int b_koff = lgrp & 1;
    const int quad = lane >> 2, qt = lane & 3;

    float acc[2][2][4];
#pragma unroll
    for (int mi = 0; mi < 2; mi++)
#pragma unroll
        for (int ni = 0; ni < 2; ni++)
#pragma unroll
            for (int q = 0; q < 4; q++) acc[mi][ni][q] = 0.f;

#pragma unroll
    for (int kp = 0; kp < 2; kp++) {
#pragma unroll
        for (int k16 = 0; k16 < 4; k16++) {
            int k2 = k16 * 2;
            uint32_t aH[2][4], aL[2][4], bH[2][2], bL[2][2];
#pragma unroll
            for (int mi = 0; mi < 2; mi++) {
                int row = wm * 32 + mi * 16 + a_roff;
                uint32_t ad = kp * 8192u + swz(row, k2 + a_koff);
                ldsm_x4(aH[mi][0], aH[mi][1], aH[mi][2], aH[mi][3], sb + C3_CPH + ad);
                ldsm_x4(aL[mi][0], aL[mi][1], aL[mi][2], aL[mi][3], sb + C3_CPL + ad);
            }
            {
                int row = wn * 16 + b_roff;
                uint32_t bd = kp * 8192u + swz(row, k2 + b_koff);
                uint32_t r0, r1, r2, r3;
                ldsm_x4(r0, r1, r2, r3, sb + C3_H0H + bd);
                bH[0][0] = r0; bH[0][1] = r1; bH[1][0] = r2; bH[1][1] = r3;
                ldsm_x4(r0, r1, r2, r3, sb + C3_H0L + bd);
                bL[0][0] = r0; bL[0][1] = r1; bL[1][0] = r2; bL[1][1] = r3;
            }
#pragma unroll
            for (int mi = 0; mi < 2; mi++)
#pragma unroll
                for (int ni = 0; ni < 2; ni++) {
                    mma_bf16(acc[mi][ni], aH[mi], bH[ni][0], bH[ni][1]);
                    mma_bf16(acc[mi][ni], aH[mi], bL[ni][0], bL[ni][1]);
                    mma_bf16(acc[mi][ni], aL[mi], bH[ni][0], bH[ni][1]);
                }
        }
    }

#pragma unroll
    for (int mi = 0; mi < 2; mi++)
#pragma unroll
        for (int ni = 0; ni < 2; ni++) {
            int t = wm * 32 + mi * 16 + quad;
            int p = wn * 16 + ni * 8 + qt * 2;
            {
                float rt = s_r[t];
                size_t o = ((size_t)b * SEQLEN + t0 + t) * DINNER + hh * HEADDIM + p;
                float2 v = *(float2*)&g_y[o];
                v.x += rt * acc[mi][ni][0];
                v.y += rt * acc[mi][ni][1];
                *(float2*)&g_y[o] = v;
            }
            {
                float rt = s_r[t + 8];
                size_t o = ((size_t)b * SEQLEN + t0 + t + 8) * DINNER + hh * HEADDIM + p;
                float2 v = *(float2*)&g_y[o];
                v.x += rt * acc[mi][ni][2];
                v.y += rt * acc[mi][ni][3];
                *(float2*)&g_y[o] = v;
            }
        }
}

// =====================================================================
// skip + gate + RMSNorm -> fp16 for GEMM2
// =====================================================================
__global__ __launch_bounds__(256)
void gate_norm_kernel(const float* __restrict__ Dw, const float* __restrict__ norm_w)
{
    const int t = blockIdx.x;
    const int b = blockIdx.y;
    const size_t row = (size_t)b * SEQLEN + t;
    const float4* __restrict__ z4 = (const float4*)&g_zx [row * DINPROJ];
    const float4* __restrict__ x4 = (const float4*)&g_xbc[row * CONVDIM];
    const float4* __restrict__ y4 = (const float4*)&g_y  [row * DINNER];

    float4 vals[2];
    float ss = 0.f;
#pragma unroll
    for (int r = 0; r < 2; r++) {
        int f = r * 256 + threadIdx.x;
        float dv = Dw[f >> 4];
        float4 a = y4[f], xv = x4[f], zv = z4[f];
        float4 v;
        v.x = a.x + dv * xv.x;
        v.y = a.y + dv * xv.y;
        v.z = a.z + dv * xv.z;
        v.w = a.w + dv * xv.w;
        v.x *= zv.x / (1.f + expf(-zv.x));
        v.y *= zv.y / (1.f + expf(-zv.y));
        v.z *= zv.z / (1.f + expf(-zv.z));
        v.w *= zv.w / (1.f + expf(-zv.w));
        vals[r] = v;
        ss += v.x * v.x + v.y * v.y + v.z * v.z + v.w * v.w;
    }
    __shared__ float red[256];
    red[threadIdx.x] = ss;
    __syncthreads();
    for (int off = 128; off > 0; off >>= 1) {
        if (threadIdx.x < off) red[threadIdx.x] += red[threadIdx.x + off];
        __syncthreads();
    }
    float scale = rsqrtf(red[0] / (float)DINNER + EPS);
    __half2* outh = (__half2*)&g_ynh[row * DINNER];
    const float4* nw4 = (const float4*)norm_w;
#pragma unroll
    for (int r = 0; r < 2; r++) {
        int f = r * 256 + threadIdx.x;
        float4 w = nw4[f];
        float4 v = vals[r];
        v.x *= scale * w.x; v.y *= scale * w.y; v.z *= scale * w.z; v.w *= scale * w.w;
        cvt4h(v, outh, f);
    }
}

// =====================================================================
extern "C" void kernel_launch(void* const* d_in, const int* in_sizes, int n_in,
                              void* d_out, int out_size)
{
    const float* x          = (const float*)d_in[0];
    const float* in_proj_w  = (const float*)d_in[1];
    const float* conv_w     = (const float*)d_in[2];
    const float* conv_b     = (const float*)d_in[3];
    const float* dt_bias    = (const float*)d_in[4];
    const float* A_log      = (const float*)d_in[5];
    const float* Dw         = (const float*)d_in[6];
    const float* norm_w     = (const float*)d_in[7];
    const float* out_proj_w = (const float*)d_in[8];
    float* out = (float*)d_out;

    float *p_zx = nullptr;
    void *p_xh, *p_w1h, *p_w2h, *p_ynh;
    cudaGetSymbolAddress((void**)&p_zx, g_zx);
    cudaGetSymbolAddress(&p_xh,  g_xh);
    cudaGetSymbolAddress(&p_w1h, g_w1h); cudaGetSymbolAddress(&p_w2h, g_w2h);
    cudaGetSymbolAddress(&p_ynh, g_ynh);

    cudaFuncSetAttribute(gemm_mma<false>, cudaFuncAttributeMaxDynamicSharedMemorySize, SMEM_GEMM);
    cudaFuncSetAttribute(gemm_mma<true>,  cudaFuncAttributeMaxDynamicSharedMemorySize, SMEM_GEMM);
    cudaFuncSetAttribute(ssd_chunk_kernel, cudaFuncAttributeMaxDynamicSharedMemorySize, SMEM_SSD1);
    cudaFuncSetAttribute(ssd_carry_kernel, cudaFuncAttributeMaxDynamicSharedMemorySize, SMEM_SSD3);

    // 0) fp32 -> fp16 conversions
    {
        int total4 = N4_X + N4_W1 + N4_W2;
        cvt_all<<<(total4 + 255)/256, 256>>>(
            (const float4*)x, (const float4*)in_proj_w, (const float4*)out_proj_w);
    }

    // 1) zxbcdt = x @ in_proj_w^T
    gemm_mma<false><<<dim3((DINPROJ + BN - 1)/BN, ROWS/BM), 256, SMEM_GEMM>>>(
        (const __half*)p_xh, (const __half*)p_w1h, nullptr, p_zx, DINPROJ, DMODEL);

    // 2) conv + SiLU; dt softplus
    conv_act_kernel<<<dim3(CONVDIM/256, SEQLEN/4, BATCH), 256>>>(conv_w, conv_b, dt_bias);

    // 2b) pack B/C once
    pack_bc_kernel<<<512, 256>>>();

    // 3) SSD scan
    ssd_chunk_kernel<<<dim3(NCH, BATCH, NHEADS), 256, SMEM_SSD1>>>(A_log);
    ssd_prop_kernel<<<dim3(BATCH * NHEADS, 4), 256>>>(A_log);
    ssd_carry_kernel<<<dim3(NCH - 1, BATCH, NHEADS), 256, SMEM_SSD3>>>(A_log);

    // 4) skip + gate + RMSNorm
    gate_norm_kernel<<<dim3(SEQLEN, BATCH), 256>>>(Dw, norm_w);

    // 5) out = x + yn @ out_proj_w^T
    gemm_mma<true><<<dim3(DMODEL/BN, ROWS/BM), 256, SMEM_GEMM>>>(
        (const __half*)p_ynh, (const __half*)p_w2h, x, out, DMODEL, DINNER);
}

// round 13
// speedup vs baseline: 1.7818x; 1.0840x over previous
#include <cuda_runtime.h>
#include <cuda_bf16.h>
#include <cuda_fp16.h>
#include <math.h>
#include <stdint.h>

// ---------------- problem constants ----------------
#define BATCH    2
#define SEQLEN   1024
#define DMODEL   1024
#define DINNER   2048
#define NHEADS   32
#define HEADDIM  64
#define DSTATE   128
#define DCONV    4
#define CONVDIM  2304
#define DINPROJ  4384
#define ROWS     (BATCH*SEQLEN)
#define EPS      1e-5f
#define CLEN     64
#define NCH      (SEQLEN/CLEN)     // 16 chunks

// ---------------- scratch ----------------
__device__ __align__(1024) float g_zx [ROWS*DINPROJ];
__device__ __align__(1024) float g_xbc[ROWS*CONVDIM];
__device__ __align__(1024) float g_dt [ROWS*NHEADS];
__device__ __align__(1024) float g_y  [ROWS*DINNER];
__device__ __align__(1024) float g_hc [BATCH*NHEADS*NCH*HEADDIM*DSTATE];
__device__ __align__(1024) float g_h0 [BATCH*NHEADS*NCH*HEADDIM*DSTATE];
__device__ __align__(1024) float g_pi [BATCH*NHEADS*NCH];
// pre-swizzled fp16 B and C panel tiles (SSD path, shared by all heads)
#define PTILES (BATCH*NCH*2)
__device__ __align__(1024) __half g_pB[PTILES*4096];
__device__ __align__(1024) __half g_pC[PTILES*4096];
// fp16 operands for the two big GEMMs
__device__ __align__(1024) __half g_xh [ROWS*DMODEL];
__device__ __align__(1024) __half g_w1h[DINPROJ*DMODEL];
__device__ __align__(1024) __half g_w2h[DMODEL*DINNER];
__device__ __align__(1024) __half g_ynh[ROWS*DINNER];

// ---------------- primitives ----------------
__device__ __forceinline__ uint32_t smem_u32(const void* p) {
    uint32_t a;
    asm("{ .reg .u64 t; cvta.to.shared.u64 t, %1; cvt.u32.u64 %0, t; }" : "=r"(a) : "l"(p));
    return a;
}
__device__ __forceinline__ void cp16(uint32_t dst, const void* src) {
    asm volatile("cp.async.cg.shared.global [%0], [%1], 16;" :: "r"(dst), "l"(src));
}
__device__ __forceinline__ void cp_commit() { asm volatile("cp.async.commit_group;" ::: "memory"); }
template<int W> __device__ __forceinline__ void cp_wait() {
    asm volatile("cp.async.wait_group %0;" :: "n"(W) : "memory");
}
__device__ __forceinline__ void ldsm_x4(uint32_t& r0, uint32_t& r1, uint32_t& r2, uint32_t& r3, uint32_t a) {
    asm volatile("ldmatrix.sync.aligned.m8n8.x4.shared.b16 {%0,%1,%2,%3}, [%4];"
                 : "=r"(r0), "=r"(r1), "=r"(r2), "=r"(r3) : "r"(a));
}
__device__ __forceinline__ void ldsm_x4_t(uint32_t& r0, uint32_t& r1, uint32_t& r2, uint32_t& r3, uint32_t a) {
    asm volatile("ldmatrix.sync.aligned.m8n8.x4.trans.shared.b16 {%0,%1,%2,%3}, [%4];"
                 : "=r"(r0), "=r"(r1), "=r"(r2), "=r"(r3) : "r"(a));
}
__device__ __forceinline__ void mma_fp16(float* c, const uint32_t* a, uint32_t b0, uint32_t b1) {
    asm volatile(
        "mma.sync.aligned.m16n8k16.row.col.f32.f16.f16.f32 "
        "{%0,%1,%2,%3}, {%4,%5,%6,%7}, {%8,%9}, {%0,%1,%2,%3};"
        : "+f"(c[0]), "+f"(c[1]), "+f"(c[2]), "+f"(c[3])
        : "r"(a[0]), "r"(a[1]), "r"(a[2]), "r"(a[3]), "r"(b0), "r"(b1));
}
__device__ __forceinline__ uint32_t swz(int row, int seg) {
    return (uint32_t)(row * 128 + ((seg ^ (row & 7)) << 4));
}
__device__ __forceinline__ uint32_t swzb(int row, int colb) {
    return (uint32_t)(row * 128 + (((colb >> 4) ^ (row & 7)) << 4) + (colb & 15));
}

// =====================================================================
// Tensor-core GEMM, fp16 1-pass (unchanged from R12)
// =====================================================================
#define BM 128
#define BN 128
#define KC 64
#define TILE_B   16384u
#define STAGE_B  (2u*TILE_B)
#define NSTAGE   3
#define SMEM_GEMM (NSTAGE*STAGE_B)     // 98304

template<bool RES>
__global__ __launch_bounds__(256, 1)
void gemm_mma(const __half* __restrict__ Ahp, const __half* __restrict__ Bhp,
              const float* __restrict__ resid, float* __restrict__ C,
              int N, int K)
{
    extern __shared__ __align__(1024) char smem[];
    const uint32_t sb = smem_u32(smem);

    const int tid = threadIdx.x;
    const int wid = tid >> 5, lane = tid & 31;
    const int wm = wid & 1, wn = wid >> 1;
    const int m0 = blockIdx.y * BM, n0 = blockIdx.x * BN;
    const int NC = K / KC;

    int lrow[4], lseg[4];
#pragma unroll
    for (int it = 0; it < 4; it++) {
        int idx = tid + it * 256;
        lrow[it] = idx >> 3;
        lseg[it] = idx & 7;
    }

    auto load_chunk = [&](int stage, int k0) {
        uint32_t s = sb + stage * STAGE_B;
#pragma unroll
        for (int it = 0; it < 4; it++) {
            int row = lrow[it], seg = lseg[it];
            uint32_t d = swz(row, seg);
            size_t aoff = (size_t)(m0 + row) * K + k0 + seg * 8;
            cp16(s + d, Ahp + aoff);
            int brow = n0 + row; if (brow >= N) brow = N - 1;
            size_t boff = (size_t)brow * K + k0 + seg * 8;
            cp16(s + TILE_B + d, Bhp + boff);
        }
        cp_commit();
    };

    float acc[4][4][4];
#pragma unroll
    for (int mi = 0; mi < 4; mi++)
#pragma unroll
        for (int ni = 0; ni < 4; ni++)
#pragma unroll
            for (int q = 0; q < 4; q++) acc[mi][ni][q] = 0.f;

    const int lgrp = lane >> 3, lr = lane & 7;
    const int a_roff = lr + (lgrp & 1) * 8;
    const int a_koff = lgrp >> 1;
    const int b_roff = lr + (lgrp >> 1) * 8;
    const int b_koff = lgrp & 1;

    load_chunk(0, 0);
    load_chunk(1, KC);

    for (int c = 0; c < NC; c++) {
        if (c + 2 < NC) load_chunk((c + 2) % NSTAGE, (c + 2) * KC);
        else            cp_commit();
        cp_wait<2>();
        __syncthreads();

        uint32_t s = sb + (c % NSTAGE) * STAGE_B;
#pragma unroll
        for (int k16 = 0; k16 < 4; k16++) {
            int k2 = k16 * 2;
            uint32_t ah[4][4], bh[4][2];
#pragma unroll
            for (int mi = 0; mi < 4; mi++) {
                int row = wm * 64 + mi * 16 + a_roff;
                uint32_t ad = swz(row, k2 + a_koff);
                ldsm_x4(ah[mi][0], ah[mi][1], ah[mi][2], ah[mi][3], s + ad);
            }
#pragma unroll
            for (int nj = 0; nj < 2; nj++) {
                int row = wn * 32 + nj * 16 + b_roff;
                uint32_t bd = swz(row, k2 + b_koff);
                uint32_t r0, r1, r2, r3;
                ldsm_x4(r0, r1, r2, r3, s + TILE_B + bd);
                bh[nj * 2][0] = r0; bh[nj * 2][1] = r1;
                bh[nj * 2 + 1][0] = r2; bh[nj * 2 + 1][1] = r3;
            }
#pragma unroll
            for (int mi = 0; mi < 4; mi++)
#pragma unroll
                for (int ni = 0; ni < 4; ni++)
                    mma_fp16(acc[mi][ni], ah[mi], bh[ni][0], bh[ni][1]);
        }
        __syncthreads();
    }

    const int quad = lane >> 2, qt = lane & 3;
#pragma unroll
    for (int mi = 0; mi < 4; mi++) {
#pragma unroll
        for (int ni = 0; ni < 4; ni++) {
            int gm = m0 + wm * 64 + mi * 16 + quad;
            int gn = n0 + wn * 32 + ni * 8 + qt * 2;
            if (gn < N) {
                {
                    float2 v = make_float2(acc[mi][ni][0], acc[mi][ni][1]);
                    size_t o = (size_t)gm * N + gn;
                    if (RES) { float2 rv = *(const float2*)(resid + o); v.x += rv.x; v.y += rv.y; }
                    *(float2*)(C + o) = v;
                }
                {
                    float2 v = make_float2(acc[mi][ni][2], acc[mi][ni][3]);
                    size_t o = (size_t)(gm + 8) * N + gn;
                    if (RES) { float2 rv = *(const float2*)(resid + o); v.x += rv.x; v.y += rv.y; }
                    *(float2*)(C + o) = v;
                }
            }
        }
    }
}

// =====================================================================
// fp32 -> fp16 conversions
// =====================================================================
#define N4_X  (ROWS*DMODEL/4)
#define N4_W1 (DINPROJ*DMODEL/4)
#define N4_W2 (DMODEL*DINNER/4)

__device__ __forceinline__ void cvt4h(float4 v, __half2* hi, int i) {
    hi[i * 2]     = __halves2half2(__float2half_rn(v.x), __float2half_rn(v.y));
    hi[i * 2 + 1] = __halves2half2(__float2half_rn(v.z), __float2half_rn(v.w));
}

__global__ __launch_bounds__(256)
void cvt_all(const float4* __restrict__ x, const float4* __restrict__ w1,
             const float4* __restrict__ w2)
{
    int i = blockIdx.x * 256 + threadIdx.x;
    if (i < N4_X) {
        cvt4h(x[i], (__half2*)g_xh, i);
    } else if (i < N4_X + N4_W1) {
        int j = i - N4_X;
        cvt4h(w1[j], (__half2*)g_w1h, j);
    } else if (i < N4_X + N4_W1 + N4_W2) {
        int j = i - N4_X - N4_W1;
        cvt4h(w2[j], (__half2*)g_w2h, j);
    }
}

// =====================================================================
// Causal depthwise conv + SiLU; dt softplus
// =====================================================================
__global__ __launch_bounds__(256)
void conv_act_kernel(const float* __restrict__ conv_w, const float* __restrict__ conv_b,
                     const float* __restrict__ dt_bias)
{
    const int c  = blockIdx.x * 256 + threadIdx.x;
    const int tb = blockIdx.y * 4;
    const int b  = blockIdx.z;

    float w0 = conv_w[c * 4 + 0], w1 = conv_w[c * 4 + 1];
    float w2 = conv_w[c * 4 + 2], w3 = conv_w[c * 4 + 3];
    float bias = conv_b[c];

    float v[7];
#pragma unroll
    for (int k = 0; k < 7; k++) {
        int tt = tb - 3 + k;
        v[k] = (tt >= 0) ? g_zx[((size_t)b * SEQLEN + tt) * DINPROJ + DINNER + c] : 0.f;
    }
#pragma unroll
    for (int i = 0; i < 4; i++) {
        float a = bias + v[i] * w0 + v[i + 1] * w1 + v[i + 2] * w2 + v[i + 3] * w3;
        g_xbc[((size_t)b * SEQLEN + tb + i) * CONVDIM + c] = a / (1.f + expf(-a));
    }
    if (blockIdx.x == 0 && threadIdx.x < NHEADS) {
        int hh = threadIdx.x;
        float bth = dt_bias[hh];
#pragma unroll
        for (int i = 0; i < 4; i++) {
            size_t row = (size_t)b * SEQLEN + tb + i;
            float raw = g_zx[row * DINPROJ + (DINNER + CONVDIM) + hh] + bth;
            g_dt[row * NHEADS + hh] = (raw > 20.f) ? raw : log1pf(expf(raw));
        }
    }
}

// =====================================================================
// pack B/C into pre-swizzled fp16 tiles (shared by all heads)
// =====================================================================
__global__ __launch_bounds__(256)
void pack_bc_kernel()
{
    int u = blockIdx.x * 256 + threadIdx.x;      // 131072 total
    int s   = u & 7;
    int t   = (u >> 3) & 63;
    int kp  = (u >> 9) & 1;
    int ch  = (u >> 10) & 15;
    int b   = (u >> 14) & 1;
    int isC = (u >> 15);

    size_t src = ((size_t)b * SEQLEN + ch * 64 + t) * CONVDIM
               + DINNER + (isC ? DSTATE : 0) + kp * 64 + s * 8;
    float4 v0 = *(const float4*)&g_xbc[src];
    float4 v1 = *(const float4*)&g_xbc[src + 4];

    __half2 ph[4];
    ph[0] = __halves2half2(__float2half_rn(v0.x), __float2half_rn(v0.y));
    ph[1] = __halves2half2(__float2half_rn(v0.z), __float2half_rn(v0.w));
    ph[2] = __halves2half2(__float2half_rn(v1.x), __float2half_rn(v1.y));
    ph[3] = __halves2half2(__float2half_rn(v1.z), __float2half_rn(v1.w));

    size_t off = (size_t)(((b * NCH + ch) * 2) + kp) * 4096 + t * 64 + ((s ^ (t & 7)) * 8);
    __half* dh = (isC ? g_pC : g_pB) + off;
    *(uint4*)dh = *(uint4*)ph;
}

// =====================================================================
// SSD phase 1, fp16 1-pass. smem ~49KB.
//   Cp[2][64t][64n] (16K), Bp[2][64s][64n] (16K), Ut (8K), Uw (8K),
//   G overlays Cp (8K).
// =====================================================================
#define OFF_CP  0u
#define OFF_BP  16384u
#define OFF_UT  32768u
#define OFF_UW  40960u
#define OFF_G   OFF_CP
#define OFF_SDT 49152u
#define OFF_DTS 49408u
#define OFF_WS  49664u
#define SMEM_SSD1 49920u

__global__ __launch_bounds__(256, 2)
void ssd_chunk_kernel(const float* __restrict__ A_log)
{
    extern __shared__ __align__(1024) char smem[];
    const uint32_t sb = smem_u32(smem);
    const int c = blockIdx.x, b = blockIdx.y, hh = blockIdx.z;
    const int tid = threadIdx.x;
    const int wid = tid >> 5, lane = tid & 31;
    const int wm = wid & 1, wn = wid >> 1;
    const int t0 = c * CLEN;
    const float Ah = -expf(A_log[hh]);

    // stage B/C panels via cp.async (16KB each)
    {
        size_t tb = (size_t)((b * NCH + c) * 2) * 4096;
#pragma unroll
        for (int i = 0; i < 4; i++) {
            int idx = tid + i * 256;             // 1024 16B units per region
            cp16(sb + OFF_BP + idx * 16, g_pB + tb + idx * 8);
            cp16(sb + OFF_CP + idx * 16, g_pC + tb + idx * 8);
        }
        cp_commit();
    }

    float* s_sdt = (float*)(smem + OFF_SDT);
    float* s_dt  = (float*)(smem + OFF_DTS);
    float* s_w   = (float*)(smem + OFF_WS);

    // dt load + inclusive scan (overlaps cp.async)
    if (tid < 64) {
        float d = g_dt[((size_t)b * SEQLEN + t0 + tid) * NHEADS + hh];
        s_dt[tid] = d;
        s_sdt[tid] = d;
    }
    __syncthreads();
#pragma unroll
    for (int off = 1; off < 64; off <<= 1) {
        float v = 0.f;
        if (tid < 64 && tid >= off) v = s_sdt[tid - off];
        __syncthreads();
        if (tid < 64) s_sdt[tid] += v;
        __syncthreads();
    }
    float sdtTOT = s_sdt[63];
    if (tid < 64) s_w[tid] = expf(Ah * (sdtTOT - s_sdt[tid]));
    if (tid == 0) g_pi[((size_t)b * NHEADS + hh) * NCH + c] = sdtTOT;
    __syncthreads();

    // convert U = dt*x and Uw = w*U (head-specific, fp16)
#pragma unroll
    for (int i = 0; i < 4; i++) {
        int idx = tid + i * 256;                 // 1024 float4
        int t = idx >> 4, p4 = idx & 15;
        size_t row = ((size_t)b * SEQLEN + t0 + t) * CONVDIM;
        float4 xv = *(const float4*)&g_xbc[row + hh * HEADDIM + p4 * 4];
        float dtv = s_dt[t], wv = s_w[t];
        float u0 = dtv*xv.x, u1 = dtv*xv.y, u2 = dtv*xv.z, u3 = dtv*xv.w;
        uint32_t off = swzb(t, p4 * 8);
        *(__half2*)(smem + OFF_UT + off)     = __halves2half2(__float2half_rn(u0), __float2half_rn(u1));
        *(__half2*)(smem + OFF_UT + off + 4) = __halves2half2(__float2half_rn(u2), __float2half_rn(u3));
        *(__half2*)(smem + OFF_UW + off)     = __halves2half2(__float2half_rn(u0*wv), __float2half_rn(u1*wv));
        *(__half2*)(smem + OFF_UW + off + 4) = __halves2half2(__float2half_rn(u2*wv), __float2half_rn(u3*wv));
    }
    cp_wait<0>();
    __syncthreads();

    const int lgrp = lane >> 3, lr = lane & 7;
    const int a_roff = lr + (lgrp & 1) * 8;
    const int a_koff = lgrp >> 1;
    const int b_roff = lr + (lgrp >> 1) * 8;
    const int b_koff = lgrp & 1;
    const int quad = lane >> 2, qt = lane & 3;
    const int bt_row = lr + (lgrp & 1) * 8;
    const int bt_col = (lgrp >> 1) * 8;
    const int at_row = lr + (lgrp >> 1) * 8;
    const int at_col = (lgrp & 1) * 8;

    // GEMM2: G = C @ B^T   [64t x 64s], K=n=128
    float accG[2][2][4];
#pragma unroll
    for (int mi = 0; mi < 2; mi++)
#pragma unroll
        for (int ni = 0; ni < 2; ni++)
#pragma unroll
            for (int q = 0; q < 4; q++) accG[mi][ni][q] = 0.f;

#pragma unroll
    for (int kp = 0; kp < 2; kp++) {
#pragma unroll
        for (int k16 = 0; k16 < 4; k16++) {
            int k2 = k16 * 2;
            uint32_t aH[2][4], bH[2][2];
#pragma unroll
            for (int mi = 0; mi < 2; mi++) {
                int row = wm * 32 + mi * 16 + a_roff;
                uint32_t ad = kp * 8192u + swz(row, k2 + a_koff);
                ldsm_x4(aH[mi][0], aH[mi][1], aH[mi][2], aH[mi][3], sb + OFF_CP + ad);
            }
            {
                int row = wn * 16 + b_roff;
                uint32_t bd = kp * 8192u + swz(row, k2 + b_koff);
                uint32_t r0, r1, r2, r3;
                ldsm_x4(r0, r1, r2, r3, sb + OFF_BP + bd);
                bH[0][0] = r0; bH[0][1] = r1; bH[1][0] = r2; bH[1][1] = r3;
            }
#pragma unroll
            for (int mi = 0; mi < 2; mi++)
#pragma unroll
                for (int ni = 0; ni < 2; ni++)
                    mma_fp16(accG[mi][ni], aH[mi], bH[ni][0], bH[ni][1]);
        }
    }
    __syncthreads();   // all warps done reading C before G overlays it

#pragma unroll
    for (int mi = 0; mi < 2; mi++)
#pragma unroll
        for (int ni = 0; ni < 2; ni++)
#pragma unroll
            for (int half = 0; half < 2; half++) {
                int t = wm * 32 + mi * 16 + quad + half * 8;
                int s = wn * 16 + ni * 8 + qt * 2;
                float sdt_t = s_sdt[t];
                float v0 = accG[mi][ni][half * 2 + 0];
                float v1 = accG[mi][ni][half * 2 + 1];
                v0 = (t >= s)     ? v0 * expf(Ah * (sdt_t - s_sdt[s]))     : 0.f;
                v1 = (t >= s + 1) ? v1 * expf(Ah * (sdt_t - s_sdt[s + 1])) : 0.f;
                uint32_t off = swzb(t, s * 2);
                *(__half2*)(smem + OFF_G + off) = __halves2half2(__float2half_rn(v0), __float2half_rn(v1));
            }
    __syncthreads();

    // GEMM4: Y = G @ U  [64t x 64p], K=s=64; U via trans
    {
        float accY[2][2][4];
#pragma unroll
        for (int mi = 0; mi < 2; mi++)
#pragma unroll
            for (int ni = 0; ni < 2; ni++)
#pragma unroll
                for (int q = 0; q < 4; q++) accY[mi][ni][q] = 0.f;

#pragma unroll
        for (int k16 = 0; k16 < 4; k16++) {
            int k2 = k16 * 2, kb = k16 * 16;
            uint32_t aH[2][4], bH[2][2];
#pragma unroll
            for (int mi = 0; mi < 2; mi++) {
                int row = wm * 32 + mi * 16 + a_roff;
                uint32_t ad = swz(row, k2 + a_koff);
                ldsm_x4(aH[mi][0], aH[mi][1], aH[mi][2], aH[mi][3], sb + OFF_G + ad);
            }
            {
                int row = kb + bt_row;
                int col = wn * 16 + bt_col;
                uint32_t bd = swzb(row, col * 2);
                uint32_t r0, r1, r2, r3;
                ldsm_x4_t(r0, r1, r2, r3, sb + OFF_UT + bd);
                bH[0][0] = r0; bH[0][1] = r1; bH[1][0] = r2; bH[1][1] = r3;
            }
#pragma unroll
            for (int mi = 0; mi < 2; mi++)
#pragma unroll
                for (int ni = 0; ni < 2; ni++)
                    mma_fp16(accY[mi][ni], aH[mi], bH[ni][0], bH[ni][1]);
        }
#pragma unroll
        for (int mi = 0; mi < 2; mi++)
#pragma unroll
            for (int ni = 0; ni < 2; ni++) {
                int t = wm * 32 + mi * 16 + quad;
                int p = wn * 16 + ni * 8 + qt * 2;
                size_t o = ((size_t)b * SEQLEN + t0 + t) * DINNER + hh * HEADDIM + p;
                *(float2*)&g_y[o] = make_float2(accY[mi][ni][0], accY[mi][ni][1]);
                o += (size_t)8 * DINNER;
                *(float2*)&g_y[o] = make_float2(accY[mi][ni][2], accY[mi][ni][3]);
            }
    }

    // GEMM5: Hc = Uw^T-form @ B  [64p x 128n], K=s=64
    {
        float accH[2][4][4];
#pragma unroll
        for (int mi = 0; mi < 2; mi++)
#pragma unroll
            for (int ni = 0; ni < 4; ni++)
#pragma unroll
                for (int q = 0; q < 4; q++) accH[mi][ni][q] = 0.f;

#pragma unroll
        for (int k16 = 0; k16 < 4; k16++) {
            int kb = k16 * 16;
            uint32_t aH[2][4], bH[4][2];
#pragma unroll
            for (int mi = 0; mi < 2; mi++) {
                int row = kb + at_row;
                int col = wm * 32 + mi * 16 + at_col;
                uint32_t ad = swzb(row, col * 2);
                ldsm_x4_t(aH[mi][0], aH[mi][1], aH[mi][2], aH[mi][3], sb + OFF_UW + ad);
            }
#pragma unroll
            for (int nj = 0; nj < 2; nj++) {
                int n0 = wn * 32 + nj * 16;
                int kp = n0 >> 6, ncol = n0 & 63;
                int row = kb + bt_row;
                int col = ncol + bt_col;
                uint32_t bd = kp * 8192u + swzb(row, col * 2);
                uint32_t r0, r1, r2, r3;
                ldsm_x4_t(r0, r1, r2, r3, sb + OFF_BP + bd);
                bH[nj*2][0] = r0; bH[nj*2][1] = r1; bH[nj*2+1][0] = r2; bH[nj*2+1][1] = r3;
            }
#pragma unroll
            for (int mi = 0; mi < 2; mi++)
#pragma unroll
                for (int ni = 0; ni < 4; ni++)
                    mma_fp16(accH[mi][ni], aH[mi], bH[ni][0], bH[ni][1]);
        }
        float* hc = &g_hc[(((size_t)b * NHEADS + hh) * NCH + c) * (HEADDIM * DSTATE)];
#pragma unroll
        for (int mi = 0; mi < 2; mi++)
#pragma unroll
            for (int ni = 0; ni < 4; ni++) {
                int p = wm * 32 + mi * 16 + quad;
                int n = wn * 32 + ni * 8 + qt * 2;
                *(float2*)&hc[p * DSTATE + n] = make_float2(accH[mi][ni][0], accH[mi][ni][1]);
                *(float2*)&hc[(p + 8) * DSTATE + n] = make_float2(accH[mi][ni][2], accH[mi][ni][3]);
            }
    }
}

// =====================================================================
// SSD phase 2 (fp32, unchanged)
// =====================================================================
__global__ __launch_bounds__(256)
void ssd_prop_kernel(const float* __restrict__ A_log)
{
    const int bh = blockIdx.x;
    const int q  = blockIdx.y;
    const int hh = bh & (NHEADS - 1);
    const int tid = threadIdx.x;
    const float Ah = -expf(A_log[hh]);
    const int base = q * 512 + tid * 2;

    float4 acc[2];
    acc[0] = make_float4(0.f, 0.f, 0.f, 0.f);
    acc[1] = make_float4(0.f, 0.f, 0.f, 0.f);

    for (int c = 1; c < NCH; c++) {
        float Pi = expf(Ah * g_pi[(size_t)bh * NCH + c - 1]);
        const float4* hc = (const float4*)&g_hc[((size_t)bh * NCH + c - 1) * (HEADDIM * DSTATE)];
        float4* h0 = (float4*)&g_h0[((size_t)bh * NCH + c) * (HEADDIM * DSTATE)];
#pragma unroll
        for (int j = 0; j < 2; j++) {
            float4 v = hc[base + j];
            acc[j].x = Pi * acc[j].x + v.x;
            acc[j].y = Pi * acc[j].y + v.y;
            acc[j].z = Pi * acc[j].z + v.z;
            acc[j].w = Pi * acc[j].w + v.w;
            h0[base + j] = acc[j];
        }
    }
}

// =====================================================================
// SSD phase 3, fp16 1-pass. smem ~33KB.
// =====================================================================
#define C3_CP  0u
#define C3_H0  16384u
#define C3_SDT 32768u
#define C3_R   33024u
#define SMEM_SSD3 33280u

__global__ __launch_bounds__(256, 2)
void ssd_carry_kernel(const float* __restrict__ A_log)
{
    extern __shared__ __align__(1024) char smem[];
    const uint32_t sb = smem_u32(smem);
    const int c = blockIdx.x + 1, b = blockIdx.y, hh = blockIdx.z;
    const int tid = threadIdx.x;
    const int wid = tid >> 5, lane = tid & 31;
    const int wm = wid & 1, wn = wid >> 1;
    const int t0 = c * CLEN;
    const float Ah = -expf(A_log[hh]);

    // stage C panels (16KB contiguous)
    {
        size_t tb = (size_t)((b * NCH + c) * 2) * 4096;
#pragma unroll
        for (int i = 0; i < 4; i++) {
            int idx = tid + i * 256;
            cp16(sb + C3_CP + idx * 16, g_pC + tb + idx * 8);
        }
        cp_commit();
    }

    float* s_sdt = (float*)(smem + C3_SDT);
    float* s_r   = (float*)(smem + C3_R);

    if (tid < 64)
        s_sdt[tid] = g_dt[((size_t)b * SEQLEN + t0 + tid) * NHEADS + hh];
    __syncthreads();
#pragma unroll
    for (int off = 1; off < 64; off <<= 1) {
        float v = 0.f;
        if (tid < 64 && tid >= off) v = s_sdt[tid - off];
        __syncthreads();
        if (tid < 64) s_sdt[tid] += v;
        __syncthreads();
    }
    if (tid < 64) s_r[tid] = expf(Ah * s_sdt[tid]);

    // convert h0 (fp32 -> fp16 panels)
    const float* h0src = &g_h0[(((size_t)b * NHEADS + hh) * NCH + c) * (HEADDIM * DSTATE)];
#pragma unroll
    for (int i = 0; i < 8; i++) {
        int idx = tid + i * 256;
        int r = idx >> 5, n4 = idx & 31;
        int kp = n4 >> 4, cb = n4 & 15;
        uint32_t off = (uint32_t)kp * 8192u + (uint32_t)r * 128u
                     + ((((uint32_t)cb >> 1) ^ (r & 7)) << 4) + (cb & 1) * 8;
        float4 v = *(const float4*)&h0src[r * DSTATE + n4 * 4];
        *(__half2*)(smem + C3_H0 + off)     = __halves2half2(__float2half_rn(v.x), __float2half_rn(v.y));
        *(__half2*)(smem + C3_H0 + off + 4) = __halves2half2(__float2half_rn(v.z), __float2half_rn(v.w));
    }
    cp_wait<0>();
    __syncthreads();

    const int lgrp = lane >> 3, lr = lane & 7;
    const int a_roff = lr + (lgrp & 1) * 8;
    const int a_koff = lgrp >> 1;
    const int b_roff = lr + (lgrp >> 1) * 8;
    const int b_koff = lgrp & 1;
    const int quad = lane >> 2, qt = lane & 3;

    float acc[2][2][4];
#pragma unroll
    for (int mi = 0; mi < 2; mi++)
#pragma unroll
        for (int ni = 0; ni < 2; ni++)
#pragma unroll
            for (int q = 0; q < 4; q++) acc[mi][ni][q] = 0.f;

#pragma unroll
    for (int kp = 0; kp < 2; kp++) {
#pragma unroll
        for (int k16 = 0; k16 < 4; k16++) {
            int k2 = k16 * 2;
            uint32_t aH[2][4], bH[2][2];
#pragma unroll
            for (int mi = 0; mi < 2; mi++) {
                int row = wm * 32 + mi * 16 + a_roff;
                uint32_t ad = kp * 8192u + swz(row, k2 + a_koff);
                ldsm_x4(aH[mi][0], aH[mi][1], aH[mi][2], aH[mi][3], sb + C3_CP + ad);
            }
            {
                int row = wn * 16 + b_roff;
                uint32_t bd = kp * 8192u + swz(row, k2 + b_koff);
                uint32_t r0, r1, r2, r3;
                ldsm_x4(r0, r1, r2, r3, sb + C3_H0 + bd);
                bH[0][0] = r0; bH[0][1] = r1; bH[1][0] = r2; bH[1][1] = r3;
            }
#pragma unroll
            for (int mi = 0; mi < 2; mi++)
#pragma unroll
                for (int ni = 0; ni < 2; ni++)
                    mma_fp16(acc[mi][ni], aH[mi], bH[ni][0], bH[ni][1]);
        }
    }

#pragma unroll
    for (int mi = 0; mi < 2; mi++)
#pragma unroll
        for (int ni = 0; ni < 2; ni++) {
            int t = wm * 32 + mi * 16 + quad;
            int p = wn * 16 + ni * 8 + qt * 2;
            {
                float rt = s_r[t];
                size_t o = ((size_t)b * SEQLEN + t0 + t) * DINNER + hh * HEADDIM + p;
                float2 v = *(float2*)&g_y[o];
                v.x += rt * acc[mi][ni][0];
                v.y += rt * acc[mi][ni][1];
                *(float2*)&g_y[o] = v;
            }
            {
                float rt = s_r[t + 8];
                size_t o = ((size_t)b * SEQLEN + t0 + t + 8) * DINNER + hh * HEADDIM + p;
                float2 v = *(float2*)&g_y[o];
                v.x += rt * acc[mi][ni][2];
                v.y += rt * acc[mi][ni][3];
                *(float2*)&g_y[o] = v;
            }
        }
}

// =====================================================================
// skip + gate + RMSNorm -> fp16 for GEMM2
// =====================================================================
__global__ __launch_bounds__(256)
void gate_norm_kernel(const float* __restrict__ Dw, const float* __restrict__ norm_w)
{
    const int t = blockIdx.x;
    const int b = blockIdx.y;
    const size_t row = (size_t)b * SEQLEN + t;
    const float4* __restrict__ z4 = (const float4*)&g_zx [row * DINPROJ];
    const float4* __restrict__ x4 = (const float4*)&g_xbc[row * CONVDIM];
    const float4* __restrict__ y4 = (const float4*)&g_y  [row * DINNER];

    float4 vals[2];
    float ss = 0.f;
#pragma unroll
    for (int r = 0; r < 2; r++) {
        int f = r * 256 + threadIdx.x;
        float dv = Dw[f >> 4];
        float4 a = y4[f], xv = x4[f], zv = z4[f];
        float4 v;
        v.x = a.x + dv * xv.x;
        v.y = a.y + dv * xv.y;
        v.z = a.z + dv * xv.z;
        v.w = a.w + dv * xv.w;
        v.x *= zv.x / (1.f + expf(-zv.x));
        v.y *= zv.y / (1.f + expf(-zv.y));
        v.z *= zv.z / (1.f + expf(-zv.z));
        v.w *= zv.w / (1.f + expf(-zv.w));
        vals[r] = v;
        ss += v.x * v.x + v.y * v.y + v.z * v.z + v.w * v.w;
    }
    __shared__ float red[256];
    red[threadIdx.x] = ss;
    __syncthreads();
    for (int off = 128; off > 0; off >>= 1) {
        if (threadIdx.x < off) red[threadIdx.x] += red[threadIdx.x + off];
        __syncthreads();
    }
    float scale = rsqrtf(red[0] / (float)DINNER + EPS);
    __half2* outh = (__half2*)&g_ynh[row * DINNER];
    const float4* nw4 = (const float4*)norm_w;
#pragma unroll
    for (int r = 0; r < 2; r++) {
        int f = r * 256 + threadIdx.x;
        float4 w = nw4[f];
        float4 v = vals[r];
        v.x *= scale * w.x; v.y *= scale * w.y; v.z *= scale * w.z; v.w *= scale * w.w;
        cvt4h(v, outh, f);
    }
}

// =====================================================================
extern "C" void kernel_launch(void* const* d_in, const int* in_sizes, int n_in,
                              void* d_out, int out_size)
{
    const float* x          = (const float*)d_in[0];
    const float* in_proj_w  = (const float*)d_in[1];
    const float* conv_w     = (const float*)d_in[2];
    const float* conv_b     = (const float*)d_in[3];
    const float* dt_bias    = (const float*)d_in[4];
    const float* A_log      = (const float*)d_in[5];
    const float* Dw         = (const float*)d_in[6];
    const float* norm_w     = (const float*)d_in[7];
    const float* out_proj_w = (const float*)d_in[8];
    float* out = (float*)d_out;

    float *p_zx = nullptr;
    void *p_xh, *p_w1h, *p_w2h, *p_ynh;
    cudaGetSymbolAddress((void**)&p_zx, g_zx);
    cudaGetSymbolAddress(&p_xh,  g_xh);
    cudaGetSymbolAddress(&p_w1h, g_w1h); cudaGetSymbolAddress(&p_w2h, g_w2h);
    cudaGetSymbolAddress(&p_ynh, g_ynh);

    cudaFuncSetAttribute(gemm_mma<false>, cudaFuncAttributeMaxDynamicSharedMemorySize, SMEM_GEMM);
    cudaFuncSetAttribute(gemm_mma<true>,  cudaFuncAttributeMaxDynamicSharedMemorySize, SMEM_GEMM);
    cudaFuncSetAttribute(ssd_chunk_kernel, cudaFuncAttributeMaxDynamicSharedMemorySize, SMEM_SSD1);
    cudaFuncSetAttribute(ssd_carry_kernel, cudaFuncAttributeMaxDynamicSharedMemorySize, SMEM_SSD3);

    // 0) fp32 -> fp16 conversions
    {
        int total4 = N4_X + N4_W1 + N4_W2;
        cvt_all<<<(total4 + 255)/256, 256>>>(
            (const float4*)x, (const float4*)in_proj_w, (const float4*)out_proj_w);
    }

    // 1) zxbcdt = x @ in_proj_w^T
    gemm_mma<false><<<dim3((DINPROJ + BN - 1)/BN, ROWS/BM), 256, SMEM_GEMM>>>(
        (const __half*)p_xh, (const __half*)p_w1h, nullptr, p_zx, DINPROJ, DMODEL);

    // 2) conv + SiLU; dt softplus
    conv_act_kernel<<<dim3(CONVDIM/256, SEQLEN/4, BATCH), 256>>>(conv_w, conv_b, dt_bias);

    // 2b) pack B/C once (fp16)
    pack_bc_kernel<<<512, 256>>>();

    // 3) SSD scan (fp16 1-pass)
    ssd_chunk_kernel<<<dim3(NCH, BATCH, NHEADS), 256, SMEM_SSD1>>>(A_log);
    ssd_prop_kernel<<<dim3(BATCH * NHEADS, 4), 256>>>(A_log);
    ssd_carry_kernel<<<dim3(NCH - 1, BATCH, NHEADS), 256, SMEM_SSD3>>>(A_log);

    // 4) skip + gate + RMSNorm
    gate_norm_kernel<<<dim3(SEQLEN, BATCH), 256>>>(Dw, norm_w);

    // 5) out = x + yn @ out_proj_w^T
    gemm_mma<true><<<dim3(DMODEL/BN, ROWS/BM), 256, SMEM_GEMM>>>(
        (const __half*)p_ynh, (const __half*)p_w2h, x, out, DMODEL, DINNER);
}

// round 14
// speedup vs baseline: 1.8287x; 1.0263x over previous
#include <cuda_runtime.h>
#include <cuda_fp16.h>
#include <math.h>
#include <stdint.h>

// ---------------- problem constants ----------------
#define BATCH    2
#define SEQLEN   1024
#define DMODEL   1024
#define DINNER   2048
#define NHEADS   32
#define HEADDIM  64
#define DSTATE   128
#define DCONV    4
#define CONVDIM  2304
#define DINPROJ  4384
#define ROWS     (BATCH*SEQLEN)
#define EPS      1e-5f
#define CLEN     64
#define NCH      (SEQLEN/CLEN)     // 16 chunks

// ---------------- scratch ----------------
__device__ __align__(1024) float g_zx [ROWS*DINPROJ];
__device__ __align__(1024) float g_xbc[ROWS*CONVDIM];
__device__ __align__(1024) float g_dt [ROWS*NHEADS];
__device__ __align__(1024) float g_y  [ROWS*DINNER];
__device__ __align__(1024) float g_hc [BATCH*NHEADS*NCH*HEADDIM*DSTATE];
__device__ __align__(1024) float g_h0 [BATCH*NHEADS*NCH*HEADDIM*DSTATE];
__device__ __align__(1024) float g_pi [BATCH*NHEADS*NCH];
// pre-swizzled fp16 B and C panel tiles (SSD path, shared by all heads)
#define PTILES (BATCH*NCH*2)
__device__ __align__(1024) __half g_pB[PTILES*4096];
__device__ __align__(1024) __half g_pC[PTILES*4096];
// fp16 operands for the two big GEMMs
__device__ __align__(1024) __half g_xh [ROWS*DMODEL];
__device__ __align__(1024) __half g_w1h[DINPROJ*DMODEL];
__device__ __align__(1024) __half g_w2h[DMODEL*DINNER];
__device__ __align__(1024) __half g_ynh[ROWS*DINNER];

// ---------------- primitives ----------------
__device__ __forceinline__ uint32_t smem_u32(const void* p) {
    uint32_t a;
    asm("{ .reg .u64 t; cvta.to.shared.u64 t, %1; cvt.u32.u64 %0, t; }" : "=r"(a) : "l"(p));
    return a;
}
__device__ __forceinline__ void cp16(uint32_t dst, const void* src) {
    asm volatile("cp.async.cg.shared.global [%0], [%1], 16;" :: "r"(dst), "l"(src));
}
__device__ __forceinline__ void cp_commit() { asm volatile("cp.async.commit_group;" ::: "memory"); }
template<int W> __device__ __forceinline__ void cp_wait() {
    asm volatile("cp.async.wait_group %0;" :: "n"(W) : "memory");
}
__device__ __forceinline__ void ldsm_x4(uint32_t& r0, uint32_t& r1, uint32_t& r2, uint32_t& r3, uint32_t a) {
    asm volatile("ldmatrix.sync.aligned.m8n8.x4.shared.b16 {%0,%1,%2,%3}, [%4];"
                 : "=r"(r0), "=r"(r1), "=r"(r2), "=r"(r3) : "r"(a));
}
__device__ __forceinline__ void ldsm_x4_t(uint32_t& r0, uint32_t& r1, uint32_t& r2, uint32_t& r3, uint32_t a) {
    asm volatile("ldmatrix.sync.aligned.m8n8.x4.trans.shared.b16 {%0,%1,%2,%3}, [%4];"
                 : "=r"(r0), "=r"(r1), "=r"(r2), "=r"(r3) : "r"(a));
}
__device__ __forceinline__ void mma_fp16(float* c, const uint32_t* a, uint32_t b0, uint32_t b1) {
    asm volatile(
        "mma.sync.aligned.m16n8k16.row.col.f32.f16.f16.f32 "
        "{%0,%1,%2,%3}, {%4,%5,%6,%7}, {%8,%9}, {%0,%1,%2,%3};"
        : "+f"(c[0]), "+f"(c[1]), "+f"(c[2]), "+f"(c[3])
        : "r"(a[0]), "r"(a[1]), "r"(a[2]), "r"(a[3]), "r"(b0), "r"(b1));
}
__device__ __forceinline__ uint32_t swz(int row, int seg) {
    return (uint32_t)(row * 128 + ((seg ^ (row & 7)) << 4));
}
__device__ __forceinline__ uint32_t swzb(int row, int colb) {
    return (uint32_t)(row * 128 + (((colb >> 4) ^ (row & 7)) << 4) + (colb & 15));
}

// =====================================================================
// GEMM variant A: 512 threads, tile 128(M) x 256(N), for GEMM1.
// 4 warps/SMSP for issue hiding. smem 48KB/stage x 3 = 144KB.
// =====================================================================
#define KC 64
#define G1_TA   16384u             // A tile bytes (128 x 128B)
#define G1_TB   32768u             // B tile bytes (256 x 128B)
#define G1_STAGE (G1_TA + G1_TB)
#define SMEM_G1  (3u * G1_STAGE)   // 147456

__global__ __launch_bounds__(512, 1)
void gemm_mma512(const __half* __restrict__ Ahp, const __half* __restrict__ Bhp,
                 float* __restrict__ C, int N, int K)
{
    extern __shared__ __align__(1024) char smem[];
    const uint32_t sb = smem_u32(smem);

    const int tid = threadIdx.x;
    const int wid = tid >> 5, lane = tid & 31;
    const int wm = wid & 1, wn = wid >> 1;           // 2 x 8 warps
    const int m0 = blockIdx.y * 128, n0 = blockIdx.x * 256;
    const int NC = K / KC;

    auto load_chunk = [&](int stage, int k0) {
        uint32_t s = sb + stage * G1_STAGE;
#pragma unroll
        for (int it = 0; it < 2; it++) {             // A: 1024 cp16
            int idx = tid + it * 512;
            int row = idx >> 3, seg = idx & 7;
            cp16(s + swz(row, seg), Ahp + (size_t)(m0 + row) * K + k0 + seg * 8);
        }
#pragma unroll
        for (int it = 0; it < 4; it++) {             // B: 2048 cp16
            int idx = tid + it * 512;
            int row = idx >> 3, seg = idx & 7;
            int brow = n0 + row; if (brow >= N) brow = N - 1;
            cp16(s + G1_TA + swz(row, seg), Bhp + (size_t)brow * K + k0 + seg * 8);
        }
        cp_commit();
    };

    float acc[4][4][4];
#pragma unroll
    for (int mi = 0; mi < 4; mi++)
#pragma unroll
        for (int ni = 0; ni < 4; ni++)
#pragma unroll
            for (int q = 0; q < 4; q++) acc[mi][ni][q] = 0.f;

    const int lgrp = lane >> 3, lr = lane & 7;
    const int a_roff = lr + (lgrp & 1) * 8;
    const int a_koff = lgrp >> 1;
    const int b_roff = lr + (lgrp >> 1) * 8;
    const int b_koff = lgrp & 1;

    load_chunk(0, 0);
    load_chunk(1, KC);

    for (int c = 0; c < NC; c++) {
        if (c + 2 < NC) load_chunk((c + 2) % 3, (c + 2) * KC);
        else            cp_commit();
        cp_wait<2>();
        __syncthreads();

        uint32_t s = sb + (c % 3) * G1_STAGE;
#pragma unroll
        for (int k16 = 0; k16 < 4; k16++) {
            int k2 = k16 * 2;
            uint32_t ah[4][4], bh[4][2];
#pragma unroll
            for (int mi = 0; mi < 4; mi++) {
                int row = wm * 64 + mi * 16 + a_roff;
                uint32_t ad = swz(row, k2 + a_koff);
                ldsm_x4(ah[mi][0], ah[mi][1], ah[mi][2], ah[mi][3], s + ad);
            }
#pragma unroll
            for (int nj = 0; nj < 2; nj++) {
                int row = wn * 32 + nj * 16 + b_roff;
                uint32_t bd = swz(row, k2 + b_koff);
                uint32_t r0, r1, r2, r3;
                ldsm_x4(r0, r1, r2, r3, s + G1_TA + bd);
                bh[nj * 2][0] = r0; bh[nj * 2][1] = r1;
                bh[nj * 2 + 1][0] = r2; bh[nj * 2 + 1][1] = r3;
            }
#pragma unroll
            for (int mi = 0; mi < 4; mi++)
#pragma unroll
                for (int ni = 0; ni < 4; ni++)
                    mma_fp16(acc[mi][ni], ah[mi], bh[ni][0], bh[ni][1]);
        }
        __syncthreads();
    }

    const int quad = lane >> 2, qt = lane & 3;
#pragma unroll
    for (int mi = 0; mi < 4; mi++) {
#pragma unroll
        for (int ni = 0; ni < 4; ni++) {
            int gm = m0 + wm * 64 + mi * 16 + quad;
            int gn = n0 + wn * 32 + ni * 8 + qt * 2;
            if (gn < N) {
                *(float2*)(C + (size_t)gm * N + gn) =
                    make_float2(acc[mi][ni][0], acc[mi][ni][1]);
                *(float2*)(C + (size_t)(gm + 8) * N + gn) =
                    make_float2(acc[mi][ni][2], acc[mi][ni][3]);
            }
        }
    }
}

// =====================================================================
// GEMM variant B: 256 threads, tile 128x128 (for GEMM2, N=1024 -> 128 CTAs)
// =====================================================================
#define BM 128
#define BN 128
#define TILE_B   16384u
#define STAGE_B  (2u*TILE_B)
#define SMEM_GEMM (3u*STAGE_B)     // 98304

template<bool RES>
__global__ __launch_bounds__(256, 1)
void gemm_mma(const __half* __restrict__ Ahp, const __half* __restrict__ Bhp,
              const float* __restrict__ resid, float* __restrict__ C,
              int N, int K)
{
    extern __shared__ __align__(1024) char smem[];
    const uint32_t sb = smem_u32(smem);

    const int tid = threadIdx.x;
    const int wid = tid >> 5, lane = tid & 31;
    const int wm = wid & 1, wn = wid >> 1;
    const int m0 = blockIdx.y * BM, n0 = blockIdx.x * BN;
    const int NC = K / KC;

    auto load_chunk = [&](int stage, int k0) {
        uint32_t s = sb + stage * STAGE_B;
#pragma unroll
        for (int it = 0; it < 4; it++) {
            int idx = tid + it * 256;
            int row = idx >> 3, seg = idx & 7;
            uint32_t d = swz(row, seg);
            cp16(s + d, Ahp + (size_t)(m0 + row) * K + k0 + seg * 8);
            int brow = n0 + row; if (brow >= N) brow = N - 1;
            cp16(s + TILE_B + d, Bhp + (size_t)brow * K + k0 + seg * 8);
        }
        cp_commit();
    };

    float acc[4][4][4];
#pragma unroll
    for (int mi = 0; mi < 4; mi++)
#pragma unroll
        for (int ni = 0; ni < 4; ni++)
#pragma unroll
            for (int q = 0; q < 4; q++) acc[mi][ni][q] = 0.f;

    const int lgrp = lane >> 3, lr = lane & 7;
    const int a_roff = lr + (lgrp & 1) * 8;
    const int a_koff = lgrp >> 1;
    const int b_roff = lr + (lgrp >> 1) * 8;
    const int b_koff = lgrp & 1;

    load_chunk(0, 0);
    load_chunk(1, KC);

    for (int c = 0; c < NC; c++) {
        if (c + 2 < NC) load_chunk((c + 2) % 3, (c + 2) * KC);
        else            cp_commit();
        cp_wait<2>();
        __syncthreads();

        uint32_t s = sb + (c % 3) * STAGE_B;
#pragma unroll
        for (int k16 = 0; k16 < 4; k16++) {
            int k2 = k16 * 2;
            uint32_t ah[4][4], bh[4][2];
#pragma unroll
            for (int mi = 0; mi < 4; mi++) {
                int row = wm * 64 + mi * 16 + a_roff;
                uint32_t ad = swz(row, k2 + a_koff);
                ldsm_x4(ah[mi][0], ah[mi][1], ah[mi][2], ah[mi][3], s + ad);
            }
#pragma unroll
            for (int nj = 0; nj < 2; nj++) {
                int row = wn * 32 + nj * 16 + b_roff;
                uint32_t bd = swz(row, k2 + b_koff);
                uint32_t r0, r1, r2, r3;
                ldsm_x4(r0, r1, r2, r3, s + TILE_B + bd);
                bh[nj * 2][0] = r0; bh[nj * 2][1] = r1;
                bh[nj * 2 + 1][0] = r2; bh[nj * 2 + 1][1] = r3;
            }
#pragma unroll
            for (int mi = 0; mi < 4; mi++)
#pragma unroll
                for (int ni = 0; ni < 4; ni++)
                    mma_fp16(acc[mi][ni], ah[mi], bh[ni][0], bh[ni][1]);
        }
        __syncthreads();
    }

    const int quad = lane >> 2, qt = lane & 3;
#pragma unroll
    for (int mi = 0; mi < 4; mi++) {
#pragma unroll
        for (int ni = 0; ni < 4; ni++) {
            int gm = m0 + wm * 64 + mi * 16 + quad;
            int gn = n0 + wn * 32 + ni * 8 + qt * 2;
            if (gn < N) {
                {
                    float2 v = make_float2(acc[mi][ni][0], acc[mi][ni][1]);
                    size_t o = (size_t)gm * N + gn;
                    if (RES) { float2 rv = *(const float2*)(resid + o); v.x += rv.x; v.y += rv.y; }
                    *(float2*)(C + o) = v;
                }
                {
                    float2 v = make_float2(acc[mi][ni][2], acc[mi][ni][3]);
                    size_t o = (size_t)(gm + 8) * N + gn;
                    if (RES) { float2 rv = *(const float2*)(resid + o); v.x += rv.x; v.y += rv.y; }
                    *(float2*)(C + o) = v;
                }
            }
        }
    }
}

// =====================================================================
// fp32 -> fp16 conversions
// =====================================================================
#define N4_X  (ROWS*DMODEL/4)
#define N4_W1 (DINPROJ*DMODEL/4)
#define N4_W2 (DMODEL*DINNER/4)

__device__ __forceinline__ void cvt4h(float4 v, __half2* hi, int i) {
    hi[i * 2]     = __halves2half2(__float2half_rn(v.x), __float2half_rn(v.y));
    hi[i * 2 + 1] = __halves2half2(__float2half_rn(v.z), __float2half_rn(v.w));
}

__global__ __launch_bounds__(256)
void cvt_all(const float4* __restrict__ x, const float4* __restrict__ w1,
             const float4* __restrict__ w2)
{
    int i = blockIdx.x * 256 + threadIdx.x;
    if (i < N4_X) {
        cvt4h(x[i], (__half2*)g_xh, i);
    } else if (i < N4_X + N4_W1) {
        int j = i - N4_X;
        cvt4h(w1[j], (__half2*)g_w1h, j);
    } else if (i < N4_X + N4_W1 + N4_W2) {
        int j = i - N4_X - N4_W1;
        cvt4h(w2[j], (__half2*)g_w2h, j);
    }
}

// =====================================================================
// Causal depthwise conv + SiLU; dt softplus.
// B/C channels are written DIRECTLY into the packed fp16 swizzled tiles
// (they are consumed only by the SSD kernels); x channels go to g_xbc.
// =====================================================================
__global__ __launch_bounds__(256)
void conv_act_kernel(const float* __restrict__ conv_w, const float* __restrict__ conv_b,
                     const float* __restrict__ dt_bias)
{
    const int c  = blockIdx.x * 256 + threadIdx.x;
    const int tb = blockIdx.y * 4;
    const int b  = blockIdx.z;

    float w0 = conv_w[c * 4 + 0], w1 = conv_w[c * 4 + 1];
    float w2 = conv_w[c * 4 + 2], w3 = conv_w[c * 4 + 3];
    float bias = conv_b[c];

    float v[7];
#pragma unroll
    for (int k = 0; k < 7; k++) {
        int tt = tb - 3 + k;
        v[k] = (tt >= 0) ? g_zx[((size_t)b * SEQLEN + tt) * DINPROJ + DINNER + c] : 0.f;
    }

    if (c < DINNER) {
#pragma unroll
        for (int i = 0; i < 4; i++) {
            float a = bias + v[i] * w0 + v[i + 1] * w1 + v[i + 2] * w2 + v[i + 3] * w3;
            g_xbc[((size_t)b * SEQLEN + tb + i) * CONVDIM + c] = a / (1.f + expf(-a));
        }
    } else {
        // packed B/C tile store
        const int isC = (c >= DINNER + DSTATE);
        const int n   = c - DINNER - (isC ? DSTATE : 0);
        const int kp  = n >> 6, nl = n & 63;
        const int sgr = nl >> 3, e = nl & 7;
        const int ch  = tb >> 6;
        __half* dst = (isC ? g_pC : g_pB) + (size_t)(((b * NCH + ch) * 2) + kp) * 4096;
#pragma unroll
        for (int i = 0; i < 4; i++) {
            float a = bias + v[i] * w0 + v[i + 1] * w1 + v[i + 2] * w2 + v[i + 3] * w3;
            float sv = a / (1.f + expf(-a));
            int tloc = (tb & 63) + i;
            dst[tloc * 64 + ((sgr ^ (tloc & 7)) << 3) + e] = __float2half_rn(sv);
        }
    }

    if (blockIdx.x == 0 && threadIdx.x < NHEADS) {
        int hh = threadIdx.x;
        float bth = dt_bias[hh];
#pragma unroll
        for (int i = 0; i < 4; i++) {
            size_t row = (size_t)b * SEQLEN + tb + i;
            float raw = g_zx[row * DINPROJ + (DINNER + CONVDIM) + hh] + bth;
            g_dt[row * NHEADS + hh] = (raw > 20.f) ? raw : log1pf(expf(raw));
        }
    }
}

// =====================================================================
// SSD phase 1, fp16 1-pass (unchanged from R13)
// =====================================================================
#define OFF_CP  0u
#define OFF_BP  16384u
#define OFF_UT  32768u
#define OFF_UW  40960u
#define OFF_G   OFF_CP
#define OFF_SDT 49152u
#define OFF_DTS 49408u
#define OFF_WS  49664u
#define SMEM_SSD1 49920u

__global__ __launch_bounds__(256, 2)
void ssd_chunk_kernel(const float* __restrict__ A_log)
{
    extern __shared__ __align__(1024) char smem[];
    const uint32_t sb = smem_u32(smem);
    const int c = blockIdx.x, b = blockIdx.y, hh = blockIdx.z;
    const int tid = threadIdx.x;
    const int wid = tid >> 5, lane = tid & 31;
    const int wm = wid & 1, wn = wid >> 1;
    const int t0 = c * CLEN;
    const float Ah = -expf(A_log[hh]);

    {
        size_t tb = (size_t)((b * NCH + c) * 2) * 4096;
#pragma unroll
        for (int i = 0; i < 4; i++) {
            int idx = tid + i * 256;
            cp16(sb + OFF_BP + idx * 16, g_pB + tb + idx * 8);
            cp16(sb + OFF_CP + idx * 16, g_pC + tb + idx * 8);
        }
        cp_commit();
    }

    float* s_sdt = (float*)(smem + OFF_SDT);
    float* s_dt  = (float*)(smem + OFF_DTS);
    float* s_w   = (float*)(smem + OFF_WS);

    if (tid < 64) {
        float d = g_dt[((size_t)b * SEQLEN + t0 + tid) * NHEADS + hh];
        s_dt[tid] = d;
        s_sdt[tid] = d;
    }
    __syncthreads();
#pragma unroll
    for (int off = 1; off < 64; off <<= 1) {
        float v = 0.f;
        if (tid < 64 && tid >= off) v = s_sdt[tid - off];
        __syncthreads();
        if (tid < 64) s_sdt[tid] += v;
        __syncthreads();
    }
    float sdtTOT = s_sdt[63];
    if (tid < 64) s_w[tid] = expf(Ah * (sdtTOT - s_sdt[tid]));
    if (tid == 0) g_pi[((size_t)b * NHEADS + hh) * NCH + c] = sdtTOT;
    __syncthreads();

#pragma unroll
    for (int i = 0; i < 4; i++) {
        int idx = tid + i * 256;
        int t = idx >> 4, p4 = idx & 15;
        size_t row = ((size_t)b * SEQLEN + t0 + t) * CONVDIM;
        float4 xv = *(const float4*)&g_xbc[row + hh * HEADDIM + p4 * 4];
        float dtv = s_dt[t], wv = s_w[t];
        float u0 = dtv*xv.x, u1 = dtv*xv.y, u2 = dtv*xv.z, u3 = dtv*xv.w;
        uint32_t off = swzb(t, p4 * 8);
        *(__half2*)(smem + OFF_UT + off)     = __halves2half2(__float2half_rn(u0), __float2half_rn(u1));
        *(__half2*)(smem + OFF_UT + off + 4) = __halves2half2(__float2half_rn(u2), __float2half_rn(u3));
        *(__half2*)(smem + OFF_UW + off)     = __halves2half2(__float2half_rn(u0*wv), __float2half_rn(u1*wv));
        *(__half2*)(smem + OFF_UW + off + 4) = __halves2half2(__float2half_rn(u2*wv), __float2half_rn(u3*wv));
    }
    cp_wait<0>();
    __syncthreads();

    const int lgrp = lane >> 3, lr = lane & 7;
    const int a_roff = lr + (lgrp & 1) * 8;
    const int a_koff = lgrp >> 1;
    const int b_roff = lr + (lgrp >> 1) * 8;
    const int b_koff = lgrp & 1;
    const int quad = lane >> 2, qt = lane & 3;
    const int bt_row = lr + (lgrp & 1) * 8;
    const int bt_col = (lgrp >> 1) * 8;
    const int at_row = lr + (lgrp >> 1) * 8;
    const int at_col = (lgrp & 1) * 8;

    // GEMM2: G = C @ B^T
    float accG[2][2][4];
#pragma unroll
    for (int mi = 0; mi < 2; mi++)
#pragma unroll
        for (int ni = 0; ni < 2; ni++)
#pragma unroll
            for (int q = 0; q < 4; q++) accG[mi][ni][q] = 0.f;

#pragma unroll
    for (int kp = 0; kp < 2; kp++) {
#pragma unroll
        for (int k16 = 0; k16 < 4; k16++) {
            int k2 = k16 * 2;
            uint32_t aH[2][4], bH[2][2];
#pragma unroll
            for (int mi = 0; mi < 2; mi++) {
                int row = wm * 32 + mi * 16 + a_roff;
                uint32_t ad = kp * 8192u + swz(row, k2 + a_koff);
                ldsm_x4(aH[mi][0], aH[mi][1], aH[mi][2], aH[mi][3], sb + OFF_CP + ad);
            }
            {
                int row = wn * 16 + b_roff;
                uint32_t bd = kp * 8192u + swz(row, k2 + b_koff);
                uint32_t r0, r1, r2, r3;
                ldsm_x4(r0, r1, r2, r3, sb + OFF_BP + bd);
                bH[0][0] = r0; bH[0][1] = r1; bH[1][0] = r2; bH[1][1] = r3;
            }
#pragma unroll
            for (int mi = 0; mi < 2; mi++)
#pragma unroll
                for (int ni = 0; ni < 2; ni++)
                    mma_fp16(accG[mi][ni], aH[mi], bH[ni][0], bH[ni][1]);
        }
    }
    __syncthreads();

#pragma unroll
    for (int mi = 0; mi < 2; mi++)
#pragma unroll
        for (int ni = 0; ni < 2; ni++)
#pragma unroll
            for (int half = 0; half < 2; half++) {
                int t = wm * 32 + mi * 16 + quad + half * 8;
                int s = wn * 16 + ni * 8 + qt * 2;
                float sdt_t = s_sdt[t];
                float v0 = accG[mi][ni][half * 2 + 0];
                float v1 = accG[mi][ni][half * 2 + 1];
                v0 = (t >= s)     ? v0 * expf(Ah * (sdt_t - s_sdt[s]))     : 0.f;
                v1 = (t >= s + 1) ? v1 * expf(Ah * (sdt_t - s_sdt[s + 1])) : 0.f;
                uint32_t off = swzb(t, s * 2);
                *(__half2*)(smem + OFF_G + off) = __halves2half2(__float2half_rn(v0), __float2half_rn(v1));
            }
    __syncthreads();

    // GEMM4: Y = G @ U
    {
        float accY[2][2][4];
#pragma unroll
        for (int mi = 0; mi < 2; mi++)
#pragma unroll
            for (int ni = 0; ni < 2; ni++)
#pragma unroll
                for (int q = 0; q < 4; q++) accY[mi][ni][q] = 0.f;

#pragma unroll
        for (int k16 = 0; k16 < 4; k16++) {
            int k2 = k16 * 2, kb = k16 * 16;
            uint32_t aH[2][4], bH[2][2];
#pragma unroll
            for (int mi = 0; mi < 2; mi++) {
                int row = wm * 32 + mi * 16 + a_roff;
                uint32_t ad = swz(row, k2 + a_koff);
                ldsm_x4(aH[mi][0], aH[mi][1], aH[mi][2], aH[mi][3], sb + OFF_G + ad);
            }
            {
                int row = kb + bt_row;
                int col = wn * 16 + bt_col;
                uint32_t bd = swzb(row, col * 2);
                uint32_t r0, r1, r2, r3;
                ldsm_x4_t(r0, r1, r2, r3, sb + OFF_UT + bd);
                bH[0][0] = r0; bH[0][1] = r1; bH[1][0] = r2; bH[1][1] = r3;
            }
#pragma unroll
            for (int mi = 0; mi < 2; mi++)
#pragma unroll
                for (int ni = 0; ni < 2; ni++)
                    mma_fp16(accY[mi][ni], aH[mi], bH[ni][0], bH[ni][1]);
        }
#pragma unroll
        for (int mi = 0; mi < 2; mi++)
#pragma unroll
            for (int ni = 0; ni < 2; ni++) {
                int t = wm * 32 + mi * 16 + quad;
                int p = wn * 16 + ni * 8 + qt * 2;
                size_t o = ((size_t)b * SEQLEN + t0 + t) * DINNER + hh * HEADDIM + p;
                *(float2*)&g_y[o] = make_float2(accY[mi][ni][0], accY[mi][ni][1]);
                o += (size_t)8 * DINNER;
                *(float2*)&g_y[o] = make_float2(accY[mi][ni][2], accY[mi][ni][3]);
            }
    }

    // GEMM5: Hc = Uw^T-form @ B
    {
        float accH[2][4][4];
#pragma unroll
        for (int mi = 0; mi < 2; mi++)
#pragma unroll
            for (int ni = 0; ni < 4; ni++)
#pragma unroll
                for (int q = 0; q < 4; q++) accH[mi][ni][q] = 0.f;

#pragma unroll
        for (int k16 = 0; k16 < 4; k16++) {
            int kb = k16 * 16;
            uint32_t aH[2][4], bH[4][2];
#pragma unroll
            for (int mi = 0; mi < 2; mi++) {
                int row = kb + at_row;
                int col = wm * 32 + mi * 16 + at_col;
                uint32_t ad = swzb(row, col * 2);
                ldsm_x4_t(aH[mi][0], aH[mi][1], aH[mi][2], aH[mi][3], sb + OFF_UW + ad);
            }
#pragma unroll
            for (int nj = 0; nj < 2; nj++) {
                int n0 = wn * 32 + nj * 16;
                int kp = n0 >> 6, ncol = n0 & 63;
                int row = kb + bt_row;
                int col = ncol + bt_col;
                uint32_t bd = kp * 8192u + swzb(row, col * 2);
                uint32_t r0, r1, r2, r3;
                ldsm_x4_t(r0, r1, r2, r3, sb + OFF_BP + bd);
                bH[nj*2][0] = r0; bH[nj*2][1] = r1; bH[nj*2+1][0] = r2; bH[nj*2+1][1] = r3;
            }
#pragma unroll
            for (int mi = 0; mi < 2; mi++)
#pragma unroll
                for (int ni = 0; ni < 4; ni++)
                    mma_fp16(accH[mi][ni], aH[mi], bH[ni][0], bH[ni][1]);
        }
        float* hc = &g_hc[(((size_t)b * NHEADS + hh) * NCH + c) * (HEADDIM * DSTATE)];
#pragma unroll
        for (int mi = 0; mi < 2; mi++)
#pragma unroll
            for (int ni = 0; ni < 4; ni++) {
                int p = wm * 32 + mi * 16 + quad;
                int n = wn * 32 + ni * 8 + qt * 2;
                *(float2*)&hc[p * DSTATE + n] = make_float2(accH[mi][ni][0], accH[mi][ni][1]);
                *(float2*)&hc[(p + 8) * DSTATE + n] = make_float2(accH[mi][ni][2], accH[mi][ni][3]);
            }
    }
}

// =====================================================================
// SSD phase 2 (fp32, unchanged)
// =====================================================================
__global__ __launch_bounds__(256)
void ssd_prop_kernel(const float* __restrict__ A_log)
{
    const int bh = blockIdx.x;
    const int q  = blockIdx.y;
    const int hh = bh & (NHEADS - 1);
    const int tid = threadIdx.x;
    const float Ah = -expf(A_log[hh]);
    const int base = q * 512 + tid * 2;

    float4 acc[2];
    acc[0] = make_float4(0.f, 0.f, 0.f, 0.f);
    acc[1] = make_float4(0.f, 0.f, 0.f, 0.f);

    for (int c = 1; c < NCH; c++) {
        float Pi = expf(Ah * g_pi[(size_t)bh * NCH + c - 1]);
        const float4* hc = (const float4*)&g_hc[((size_t)bh * NCH + c - 1) * (HEADDIM * DSTATE)];
        float4* h0 = (float4*)&g_h0[((size_t)bh * NCH + c) * (HEADDIM * DSTATE)];
#pragma unroll
        for (int j = 0; j < 2; j++) {
            float4 v = hc[base + j];
            acc[j].x = Pi * acc[j].x + v.x;
            acc[j].y = Pi * acc[j].y + v.y;
            acc[j].z = Pi * acc[j].z + v.z;
            acc[j].w = Pi * acc[j].w + v.w;
            h0[base + j] = acc[j];
        }
    }
}

// =====================================================================
// SSD phase 3, fp16 1-pass (unchanged from R13)
// =====================================================================
#define C3_CP  0u
#define C3_H0  16384u
#define C3_SDT 32768u
#define C3_R   33024u
#define SMEM_SSD3 33280u

__global__ __launch_bounds__(256, 2)
void ssd_carry_kernel(const float* __restrict__ A_log)
{
    extern __shared__ __align__(1024) char smem[];
    const uint32_t sb = smem_u32(smem);
    const int c = blockIdx.x + 1, b = blockIdx.y, hh = blockIdx.z;
    const int tid = threadIdx.x;
    const int wid = tid >> 5, lane = tid & 31;
    const int wm = wid & 1, wn = wid >> 1;
    const int t0 = c * CLEN;
    const float Ah = -expf(A_log[hh]);

    {
        size_t tb = (size_t)((b * NCH + c) * 2) * 4096;
#pragma unroll
        for (int i = 0; i < 4; i++) {
            int idx = tid + i * 256;
            cp16(sb + C3_CP + idx * 16, g_pC + tb + idx * 8);
        }
        cp_commit();
    }

    float* s_sdt = (float*)(smem + C3_SDT);
    float* s_r   = (float*)(smem + C3_R);

    if (tid < 64)
        s_sdt[tid] = g_dt[((size_t)b * SEQLEN + t0 + tid) * NHEADS + hh];
    __syncthreads();
#pragma unroll
    for (int off = 1; off < 64; off <<= 1) {
        float v = 0.f;
        if (tid < 64 && tid >= off) v = s_sdt[tid - off];
        __syncthreads();
        if (tid < 64) s_sdt[tid] += v;
        __syncthreads();
    }
    if (tid < 64) s_r[tid] = expf(Ah * s_sdt[tid]);

    const float* h0src = &g_h0[(((size_t)b * NHEADS + hh) * NCH + c) * (HEADDIM * DSTATE)];
#pragma unroll
    for (int i = 0; i < 8; i++) {
        int idx = tid + i * 256;
        int r = idx >> 5, n4 = idx & 31;
        int kp = n4 >> 4, cb = n4 & 15;
        uint32_t off = (uint32_t)kp * 8192u + (uint32_t)r * 128u
                     + ((((uint32_t)cb >> 1) ^ (r & 7)) << 4) + (cb & 1) * 8;
        float4 v = *(const float4*)&h0src[r * DSTATE + n4 * 4];
        *(__half2*)(smem + C3_H0 + off)     = __halves2half2(__float2half_rn(v.x), __float2half_rn(v.y));
        *(__half2*)(smem + C3_H0 + off + 4) = __halves2half2(__float2half_rn(v.z), __float2half_rn(v.w));
    }
    cp_wait<0>();
    __syncthreads();

    const int lgrp = lane >> 3, lr = lane & 7;
    const int a_roff = lr + (lgrp & 1) * 8;
    const int a_koff = lgrp >> 1;
    const int b_roff = lr + (lgrp >> 1) * 8;
    const int b_koff = lgrp & 1;
    const int quad = lane >> 2, qt = lane & 3;

    float acc[2][2][4];
#pragma unroll
    for (int mi = 0; mi < 2; mi++)
#pragma unroll
        for (int ni = 0; ni < 2; ni++)
#pragma unroll
            for (int q = 0; q < 4; q++) acc[mi][ni][q] = 0.f;

#pragma unroll
    for (int kp = 0; kp < 2; kp++) {
#pragma unroll
        for (int k16 = 0; k16 < 4; k16++) {
            int k2 = k16 * 2;
            uint32_t aH[2][4], bH[2][2];
#pragma unroll
            for (int mi = 0; mi < 2; mi++) {
                int row = wm * 32 + mi * 16 + a_roff;
                uint32_t ad = kp * 8192u + swz(row, k2 + a_koff);
                ldsm_x4(aH[mi][0], aH[mi][1], aH[mi][2], aH[mi][3], sb + C3_CP + ad);
            }
            {
                int row = wn * 16 + b_roff;
                uint32_t bd = kp * 8192u + swz(row, k2 + b_koff);
                uint32_t r0, r1, r2, r3;
                ldsm_x4(r0, r1, r2, r3, sb + C3_H0 + bd);
                bH[0][0] = r0; bH[0][1] = r1; bH[1][0] = r2; bH[1][1] = r3;
            }
#pragma unroll
            for (int mi = 0; mi < 2; mi++)
#pragma unroll
                for (int ni = 0; ni < 2; ni++)
                    mma_fp16(acc[mi][ni], aH[mi], bH[ni][0], bH[ni][1]);
        }
    }

#pragma unroll
    for (int mi = 0; mi < 2; mi++)
#pragma unroll
        for (int ni = 0; ni < 2; ni++) {
            int t = wm * 32 + mi * 16 + quad;
            int p = wn * 16 + ni * 8 + qt * 2;
            {
                float rt = s_r[t];
                size_t o = ((size_t)b * SEQLEN + t0 + t) * DINNER + hh * HEADDIM + p;
                float2 v = *(float2*)&g_y[o];
                v.x += rt * acc[mi][ni][0];
                v.y += rt * acc[mi][ni][1];
                *(float2*)&g_y[o] = v;
            }
            {
                float rt = s_r[t + 8];
                size_t o = ((size_t)b * SEQLEN + t0 + t + 8) * DINNER + hh * HEADDIM + p;
                float2 v = *(float2*)&g_y[o];
                v.x += rt * acc[mi][ni][2];
                v.y += rt * acc[mi][ni][3];
                *(float2*)&g_y[o] = v;
            }
        }
}

// =====================================================================
// skip + gate + RMSNorm -> fp16 for GEMM2
// =====================================================================
__global__ __launch_bounds__(256)
void gate_norm_kernel(const float* __restrict__ Dw, const float* __restrict__ norm_w)
{
    const int t = blockIdx.x;
    const int b = blockIdx.y;
    const size_t row = (size_t)b * SEQLEN + t;
    const float4* __restrict__ z4 = (const float4*)&g_zx [row * DINPROJ];
    const float4* __restrict__ x4 = (const float4*)&g_xbc[row * CONVDIM];
    const float4* __restrict__ y4 = (const float4*)&g_y  [row * DINNER];

    float4 vals[2];
    float ss = 0.f;
#pragma unroll
    for (int r = 0; r < 2; r++) {
        int f = r * 256 + threadIdx.x;
        float dv = Dw[f >> 4];
        float4 a = y4[f], xv = x4[f], zv = z4[f];
        float4 v;
        v.x = a.x + dv * xv.x;
        v.y = a.y + dv * xv.y;
        v.z = a.z + dv * xv.z;
        v.w = a.w + dv * xv.w;
        v.x *= zv.x / (1.f + expf(-zv.x));
        v.y *= zv.y / (1.f + expf(-zv.y));
        v.z *= zv.z / (1.f + expf(-zv.z));
        v.w *= zv.w / (1.f + expf(-zv.w));
        vals[r] = v;
        ss += v.x * v.x + v.y * v.y + v.z * v.z + v.w * v.w;
    }
    __shared__ float red[256];
    red[threadIdx.x] = ss;
    __syncthreads();
    for (int off = 128; off > 0; off >>= 1) {
        if (threadIdx.x < off) red[threadIdx.x] += red[threadIdx.x + off];
        __syncthreads();
    }
    float scale = rsqrtf(red[0] / (float)DINNER + EPS);
    __half2* outh = (__half2*)&g_ynh[row * DINNER];
    const float4* nw4 = (const float4*)norm_w;
#pragma unroll
    for (int r = 0; r < 2; r++) {
        int f = r * 256 + threadIdx.x;
        float4 w = nw4[f];
        float4 v = vals[r];
        v.x *= scale * w.x; v.y *= scale * w.y; v.z *= scale * w.z; v.w *= scale * w.w;
        cvt4h(v, outh, f);
    }
}

// =====================================================================
extern "C" void kernel_launch(void* const* d_in, const int* in_sizes, int n_in,
                              void* d_out, int out_size)
{
    const float* x          = (const float*)d_in[0];
    const float* in_proj_w  = (const float*)d_in[1];
    const float* conv_w     = (const float*)d_in[2];
    const float* conv_b     = (const float*)d_in[3];
    const float* dt_bias    = (const float*)d_in[4];
    const float* A_log      = (const float*)d_in[5];
    const float* Dw         = (const float*)d_in[6];
    const float* norm_w     = (const float*)d_in[7];
    const float* out_proj_w = (const float*)d_in[8];
    float* out = (float*)d_out;

    float *p_zx = nullptr;
    void *p_xh, *p_w1h, *p_w2h, *p_ynh;
    cudaGetSymbolAddress((void**)&p_zx, g_zx);
    cudaGetSymbolAddress(&p_xh,  g_xh);
    cudaGetSymbolAddress(&p_w1h, g_w1h); cudaGetSymbolAddress(&p_w2h, g_w2h);
    cudaGetSymbolAddress(&p_ynh, g_ynh);

    cudaFuncSetAttribute(gemm_mma512,    cudaFuncAttributeMaxDynamicSharedMemorySize, SMEM_G1);
    cudaFuncSetAttribute(gemm_mma<true>, cudaFuncAttributeMaxDynamicSharedMemorySize, SMEM_GEMM);
    cudaFuncSetAttribute(ssd_chunk_kernel, cudaFuncAttributeMaxDynamicSharedMemorySize, SMEM_SSD1);
    cudaFuncSetAttribute(ssd_carry_kernel, cudaFuncAttributeMaxDynamicSharedMemorySize, SMEM_SSD3);

    // 0) fp32 -> fp16 conversions
    {
        int total4 = N4_X + N4_W1 + N4_W2;
        cvt_all<<<(total4 + 255)/256, 256>>>(
            (const float4*)x, (const float4*)in_proj_w, (const float4*)out_proj_w);
    }

    // 1) zxbcdt = x @ in_proj_w^T  (512-thread wide-tile GEMM)
    gemm_mma512<<<dim3((DINPROJ + 255)/256, ROWS/128), 512, SMEM_G1>>>(
        (const __half*)p_xh, (const __half*)p_w1h, p_zx, DINPROJ, DMODEL);

    // 2) conv + SiLU (B/C written directly as packed fp16 tiles); dt softplus
    conv_act_kernel<<<dim3(CONVDIM/256, SEQLEN/4, BATCH), 256>>>(conv_w, conv_b, dt_bias);

    // 3) SSD scan
    ssd_chunk_kernel<<<dim3(NCH, BATCH, NHEADS), 256, SMEM_SSD1>>>(A_log);
    ssd_prop_kernel<<<dim3(BATCH * NHEADS, 4), 256>>>(A_log);
    ssd_carry_kernel<<<dim3(NCH - 1, BATCH, NHEADS), 256, SMEM_SSD3>>>(A_log);

    // 4) skip + gate + RMSNorm
    gate_norm_kernel<<<dim3(SEQLEN, BATCH), 256>>>(Dw, norm_w);

    // 5) out = x + yn @ out_proj_w^T
    gemm_mma<true><<<dim3(DMODEL/BN, ROWS/BM), 256, SMEM_GEMM>>>(
        (const __half*)p_ynh, (const __half*)p_w2h, x, out, DMODEL, DINNER);
}

// round 15
// speedup vs baseline: 1.8630x; 1.0188x over previous
#include <cuda_runtime.h>
#include <cuda_fp16.h>
#include <math.h>
#include <stdint.h>

// ---------------- problem constants ----------------
#define BATCH    2
#define SEQLEN   1024
#define DMODEL   1024
#define DINNER   2048
#define NHEADS   32
#define HEADDIM  64
#define DSTATE   128
#define DCONV    4
#define CONVDIM  2304
#define DINPROJ  4384
#define ROWS     (BATCH*SEQLEN)
#define EPS      1e-5f
#define CLEN     64
#define NCH      (SEQLEN/CLEN)     // 16 chunks

// ---------------- scratch ----------------
__device__ __align__(1024) float g_zx [ROWS*DINPROJ];
__device__ __align__(1024) float g_xbc[ROWS*CONVDIM];
__device__ __align__(1024) float g_dt [ROWS*NHEADS];
__device__ __align__(1024) float g_y  [ROWS*DINNER];
__device__ __align__(1024) float g_hc [BATCH*NHEADS*NCH*HEADDIM*DSTATE];
__device__ __align__(1024) float g_h0 [BATCH*NHEADS*NCH*HEADDIM*DSTATE];
__device__ __align__(1024) float g_pi [BATCH*NHEADS*NCH];
// pre-swizzled fp16 B and C panel tiles (SSD path, shared by all heads)
#define PTILES (BATCH*NCH*2)
__device__ __align__(1024) __half g_pB[PTILES*4096];
__device__ __align__(1024) __half g_pC[PTILES*4096];
// fp16 operands for the two big GEMMs
__device__ __align__(1024) __half g_xh [ROWS*DMODEL];
__device__ __align__(1024) __half g_w1h[DINPROJ*DMODEL];
__device__ __align__(1024) __half g_w2h[DMODEL*DINNER];
__device__ __align__(1024) __half g_ynh[ROWS*DINNER];

// ---------------- primitives ----------------
__device__ __forceinline__ uint32_t smem_u32(const void* p) {
    uint32_t a;
    asm("{ .reg .u64 t; cvta.to.shared.u64 t, %1; cvt.u32.u64 %0, t; }" : "=r"(a) : "l"(p));
    return a;
}
__device__ __forceinline__ void cp16(uint32_t dst, const void* src) {
    asm volatile("cp.async.cg.shared.global [%0], [%1], 16;" :: "r"(dst), "l"(src));
}
__device__ __forceinline__ void cp_commit() { asm volatile("cp.async.commit_group;" ::: "memory"); }
template<int W> __device__ __forceinline__ void cp_wait() {
    asm volatile("cp.async.wait_group %0;" :: "n"(W) : "memory");
}
__device__ __forceinline__ void ldsm_x4(uint32_t& r0, uint32_t& r1, uint32_t& r2, uint32_t& r3, uint32_t a) {
    asm volatile("ldmatrix.sync.aligned.m8n8.x4.shared.b16 {%0,%1,%2,%3}, [%4];"
                 : "=r"(r0), "=r"(r1), "=r"(r2), "=r"(r3) : "r"(a));
}
__device__ __forceinline__ void ldsm_x4_t(uint32_t& r0, uint32_t& r1, uint32_t& r2, uint32_t& r3, uint32_t a) {
    asm volatile("ldmatrix.sync.aligned.m8n8.x4.trans.shared.b16 {%0,%1,%2,%3}, [%4];"
                 : "=r"(r0), "=r"(r1), "=r"(r2), "=r"(r3) : "r"(a));
}
__device__ __forceinline__ void mma_fp16(float* c, const uint32_t* a, uint32_t b0, uint32_t b1) {
    asm volatile(
        "mma.sync.aligned.m16n8k16.row.col.f32.f16.f16.f32 "
        "{%0,%1,%2,%3}, {%4,%5,%6,%7}, {%8,%9}, {%0,%1,%2,%3};"
        : "+f"(c[0]), "+f"(c[1]), "+f"(c[2]), "+f"(c[3])
        : "r"(a[0]), "r"(a[1]), "r"(a[2]), "r"(a[3]), "r"(b0), "r"(b1));
}
__device__ __forceinline__ uint32_t swz(int row, int seg) {
    return (uint32_t)(row * 128 + ((seg ^ (row & 7)) << 4));
}
__device__ __forceinline__ uint32_t swzb(int row, int colb) {
    return (uint32_t)(row * 128 + (((colb >> 4) ^ (row & 7)) << 4) + (colb & 15));
}

// =====================================================================
// GEMM variant A: 512 threads, tile 128(M) x 256(N), for GEMM1.
// =====================================================================
#define KC 64
#define G1_TA   16384u
#define G1_TB   32768u
#define G1_STAGE (G1_TA + G1_TB)
#define SMEM_G1  (3u * G1_STAGE)   // 147456

__global__ __launch_bounds__(512, 1)
void gemm_mma512(const __half* __restrict__ Ahp, const __half* __restrict__ Bhp,
                 float* __restrict__ C, int N, int K)
{
    extern __shared__ __align__(1024) char smem[];
    const uint32_t sb = smem_u32(smem);

    const int tid = threadIdx.x;
    const int wid = tid >> 5, lane = tid & 31;
    const int wm = wid & 1, wn = wid >> 1;
    const int m0 = blockIdx.y * 128, n0 = blockIdx.x * 256;
    const int NC = K / KC;

    auto load_chunk = [&](int stage, int k0) {
        uint32_t s = sb + stage * G1_STAGE;
#pragma unroll
        for (int it = 0; it < 2; it++) {
            int idx = tid + it * 512;
            int row = idx >> 3, seg = idx & 7;
            cp16(s + swz(row, seg), Ahp + (size_t)(m0 + row) * K + k0 + seg * 8);
        }
#pragma unroll
        for (int it = 0; it < 4; it++) {
            int idx = tid + it * 512;
            int row = idx >> 3, seg = idx & 7;
            int brow = n0 + row; if (brow >= N) brow = N - 1;
            cp16(s + G1_TA + swz(row, seg), Bhp + (size_t)brow * K + k0 + seg * 8);
        }
        cp_commit();
    };

    float acc[4][4][4];
#pragma unroll
    for (int mi = 0; mi < 4; mi++)
#pragma unroll
        for (int ni = 0; ni < 4; ni++)
#pragma unroll
            for (int q = 0; q < 4; q++) acc[mi][ni][q] = 0.f;

    const int lgrp = lane >> 3, lr = lane & 7;
    const int a_roff = lr + (lgrp & 1) * 8;
    const int a_koff = lgrp >> 1;
    const int b_roff = lr + (lgrp >> 1) * 8;
    const int b_koff = lgrp & 1;

    load_chunk(0, 0);
    load_chunk(1, KC);

    for (int c = 0; c < NC; c++) {
        if (c + 2 < NC) load_chunk((c + 2) % 3, (c + 2) * KC);
        else            cp_commit();
        cp_wait<2>();
        __syncthreads();

        uint32_t s = sb + (c % 3) * G1_STAGE;
#pragma unroll
        for (int k16 = 0; k16 < 4; k16++) {
            int k2 = k16 * 2;
            uint32_t ah[4][4], bh[4][2];
#pragma unroll
            for (int mi = 0; mi < 4; mi++) {
                int row = wm * 64 + mi * 16 + a_roff;
                uint32_t ad = swz(row, k2 + a_koff);
                ldsm_x4(ah[mi][0], ah[mi][1], ah[mi][2], ah[mi][3], s + ad);
            }
#pragma unroll
            for (int nj = 0; nj < 2; nj++) {
                int row = wn * 32 + nj * 16 + b_roff;
                uint32_t bd = swz(row, k2 + b_koff);
                uint32_t r0, r1, r2, r3;
                ldsm_x4(r0, r1, r2, r3, s + G1_TA + bd);
                bh[nj * 2][0] = r0; bh[nj * 2][1] = r1;
                bh[nj * 2 + 1][0] = r2; bh[nj * 2 + 1][1] = r3;
            }
#pragma unroll
            for (int mi = 0; mi < 4; mi++)
#pragma unroll
                for (int ni = 0; ni < 4; ni++)
                    mma_fp16(acc[mi][ni], ah[mi], bh[ni][0], bh[ni][1]);
        }
        __syncthreads();
    }

    const int quad = lane >> 2, qt = lane & 3;
#pragma unroll
    for (int mi = 0; mi < 4; mi++) {
#pragma unroll
        for (int ni = 0; ni < 4; ni++) {
            int gm = m0 + wm * 64 + mi * 16 + quad;
            int gn = n0 + wn * 32 + ni * 8 + qt * 2;
            if (gn < N) {
                *(float2*)(C + (size_t)gm * N + gn) =
                    make_float2(acc[mi][ni][0], acc[mi][ni][1]);
                *(float2*)(C + (size_t)(gm + 8) * N + gn) =
                    make_float2(acc[mi][ni][2], acc[mi][ni][3]);
            }
        }
    }
}

// =====================================================================
// GEMM variant B: 256 threads, tile 128x128 (GEMM2)
// =====================================================================
#define BM 128
#define BN 128
#define TILE_B   16384u
#define STAGE_B  (2u*TILE_B)
#define SMEM_GEMM (3u*STAGE_B)     // 98304

template<bool RES>
__global__ __launch_bounds__(256, 1)
void gemm_mma(const __half* __restrict__ Ahp, const __half* __restrict__ Bhp,
              const float* __restrict__ resid, float* __restrict__ C,
              int N, int K)
{
    extern __shared__ __align__(1024) char smem[];
    const uint32_t sb = smem_u32(smem);

    const int tid = threadIdx.x;
    const int wid = tid >> 5, lane = tid & 31;
    const int wm = wid & 1, wn = wid >> 1;
    const int m0 = blockIdx.y * BM, n0 = blockIdx.x * BN;
    const int NC = K / KC;

    auto load_chunk = [&](int stage, int k0) {
        uint32_t s = sb + stage * STAGE_B;
#pragma unroll
        for (int it = 0; it < 4; it++) {
            int idx = tid + it * 256;
            int row = idx >> 3, seg = idx & 7;
            uint32_t d = swz(row, seg);
            cp16(s + d, Ahp + (size_t)(m0 + row) * K + k0 + seg * 8);
            int brow = n0 + row; if (brow >= N) brow = N - 1;
            cp16(s + TILE_B + d, Bhp + (size_t)brow * K + k0 + seg * 8);
        }
        cp_commit();
    };

    float acc[4][4][4];
#pragma unroll
    for (int mi = 0; mi < 4; mi++)
#pragma unroll
        for (int ni = 0; ni < 4; ni++)
#pragma unroll
            for (int q = 0; q < 4; q++) acc[mi][ni][q] = 0.f;

    const int lgrp = lane >> 3, lr = lane & 7;
    const int a_roff = lr + (lgrp & 1) * 8;
    const int a_koff = lgrp >> 1;
    const int b_roff = lr + (lgrp >> 1) * 8;
    const int b_koff = lgrp & 1;

    load_chunk(0, 0);
    load_chunk(1, KC);

    for (int c = 0; c < NC; c++) {
        if (c + 2 < NC) load_chunk((c + 2) % 3, (c + 2) * KC);
        else            cp_commit();
        cp_wait<2>();
        __syncthreads();

        uint32_t s = sb + (c % 3) * STAGE_B;
#pragma unroll
        for (int k16 = 0; k16 < 4; k16++) {
            int k2 = k16 * 2;
            uint32_t ah[4][4], bh[4][2];
#pragma unroll
            for (int mi = 0; mi < 4; mi++) {
                int row = wm * 64 + mi * 16 + a_roff;
                uint32_t ad = swz(row, k2 + a_koff);
                ldsm_x4(ah[mi][0], ah[mi][1], ah[mi][2], ah[mi][3], s + ad);
            }
#pragma unroll
            for (int nj = 0; nj < 2; nj++) {
                int row = wn * 32 + nj * 16 + b_roff;
                uint32_t bd = swz(row, k2 + b_koff);
                uint32_t r0, r1, r2, r3;
                ldsm_x4(r0, r1, r2, r3, s + TILE_B + bd);
                bh[nj * 2][0] = r0; bh[nj * 2][1] = r1;
                bh[nj * 2 + 1][0] = r2; bh[nj * 2 + 1][1] = r3;
            }
#pragma unroll
            for (int mi = 0; mi < 4; mi++)
#pragma unroll
                for (int ni = 0; ni < 4; ni++)
                    mma_fp16(acc[mi][ni], ah[mi], bh[ni][0], bh[ni][1]);
        }
        __syncthreads();
    }

    const int quad = lane >> 2, qt = lane & 3;
#pragma unroll
    for (int mi = 0; mi < 4; mi++) {
#pragma unroll
        for (int ni = 0; ni < 4; ni++) {
            int gm = m0 + wm * 64 + mi * 16 + quad;
            int gn = n0 + wn * 32 + ni * 8 + qt * 2;
            if (gn < N) {
                {
                    float2 v = make_float2(acc[mi][ni][0], acc[mi][ni][1]);
                    size_t o = (size_t)gm * N + gn;
                    if (RES) { float2 rv = *(const float2*)(resid + o); v.x += rv.x; v.y += rv.y; }
                    *(float2*)(C + o) = v;
                }
                {
                    float2 v = make_float2(acc[mi][ni][2], acc[mi][ni][3]);
                    size_t o = (size_t)(gm + 8) * N + gn;
                    if (RES) { float2 rv = *(const float2*)(resid + o); v.x += rv.x; v.y += rv.y; }
                    *(float2*)(C + o) = v;
                }
            }
        }
    }
}

// =====================================================================
// fp32 -> fp16 conversions
// =====================================================================
#define N4_X  (ROWS*DMODEL/4)
#define N4_W1 (DINPROJ*DMODEL/4)
#define N4_W2 (DMODEL*DINNER/4)

__device__ __forceinline__ void cvt4h(float4 v, __half2* hi, int i) {
    hi[i * 2]     = __halves2half2(__float2half_rn(v.x), __float2half_rn(v.y));
    hi[i * 2 + 1] = __halves2half2(__float2half_rn(v.z), __float2half_rn(v.w));
}

__global__ __launch_bounds__(256)
void cvt_all(const float4* __restrict__ x, const float4* __restrict__ w1,
             const float4* __restrict__ w2)
{
    int i = blockIdx.x * 256 + threadIdx.x;
    if (i < N4_X) {
        cvt4h(x[i], (__half2*)g_xh, i);
    } else if (i < N4_X + N4_W1) {
        int j = i - N4_X;
        cvt4h(w1[j], (__half2*)g_w1h, j);
    } else if (i < N4_X + N4_W1 + N4_W2) {
        int j = i - N4_X - N4_W1;
        cvt4h(w2[j], (__half2*)g_w2h, j);
    }
}

// =====================================================================
// Causal depthwise conv + SiLU; dt softplus.
// B/C channels written directly to packed fp16 swizzled tiles.
// =====================================================================
__global__ __launch_bounds__(256)
void conv_act_kernel(const float* __restrict__ conv_w, const float* __restrict__ conv_b,
                     const float* __restrict__ dt_bias)
{
    const int c  = blockIdx.x * 256 + threadIdx.x;
    const int tb = blockIdx.y * 4;
    const int b  = blockIdx.z;

    float w0 = conv_w[c * 4 + 0], w1 = conv_w[c * 4 + 1];
    float w2 = conv_w[c * 4 + 2], w3 = conv_w[c * 4 + 3];
    float bias = conv_b[c];

    float v[7];
#pragma unroll
    for (int k = 0; k < 7; k++) {
        int tt = tb - 3 + k;
        v[k] = (tt >= 0) ? g_zx[((size_t)b * SEQLEN + tt) * DINPROJ + DINNER + c] : 0.f;
    }

    if (c < DINNER) {
#pragma unroll
        for (int i = 0; i < 4; i++) {
            float a = bias + v[i] * w0 + v[i + 1] * w1 + v[i + 2] * w2 + v[i + 3] * w3;
            g_xbc[((size_t)b * SEQLEN + tb + i) * CONVDIM + c] = a / (1.f + expf(-a));
        }
    } else {
        const int isC = (c >= DINNER + DSTATE);
        const int n   = c - DINNER - (isC ? DSTATE : 0);
        const int kp  = n >> 6, nl = n & 63;
        const int sgr = nl >> 3, e = nl & 7;
        const int ch  = tb >> 6;
        __half* dst = (isC ? g_pC : g_pB) + (size_t)(((b * NCH + ch) * 2) + kp) * 4096;
#pragma unroll
        for (int i = 0; i < 4; i++) {
            float a = bias + v[i] * w0 + v[i + 1] * w1 + v[i + 2] * w2 + v[i + 3] * w3;
            float sv = a / (1.f + expf(-a));
            int tloc = (tb & 63) + i;
            dst[tloc * 64 + ((sgr ^ (tloc & 7)) << 3) + e] = __float2half_rn(sv);
        }
    }

    if (blockIdx.x == 0 && threadIdx.x < NHEADS) {
        int hh = threadIdx.x;
        float bth = dt_bias[hh];
#pragma unroll
        for (int i = 0; i < 4; i++) {
            size_t row = (size_t)b * SEQLEN + tb + i;
            float raw = g_zx[row * DINPROJ + (DINNER + CONVDIM) + hh] + bth;
            g_dt[row * NHEADS + hh] = (raw > 20.f) ? raw : log1pf(expf(raw));
        }
    }
}

// =====================================================================
// SSD phase 1, fp16 1-pass. Warp-shuffle dt scan (1 sync vs 13).
// =====================================================================
#define OFF_CP  0u
#define OFF_BP  16384u
#define OFF_UT  32768u
#define OFF_UW  40960u
#define OFF_G   OFF_CP
#define OFF_SDT 49152u
#define OFF_DTS 49408u
#define OFF_WS  49664u
#define SMEM_SSD1 49920u

__global__ __launch_bounds__(256, 2)
void ssd_chunk_kernel(const float* __restrict__ A_log)
{
    extern __shared__ __align__(1024) char smem[];
    const uint32_t sb = smem_u32(smem);
    const int c = blockIdx.x, b = blockIdx.y, hh = blockIdx.z;
    const int tid = threadIdx.x;
    const int wid = tid >> 5, lane = tid & 31;
    const int wm = wid & 1, wn = wid >> 1;
    const int t0 = c * CLEN;
    const float Ah = -expf(A_log[hh]);

    // stage B/C panels via cp.async
    {
        size_t tb = (size_t)((b * NCH + c) * 2) * 4096;
#pragma unroll
        for (int i = 0; i < 4; i++) {
            int idx = tid + i * 256;
            cp16(sb + OFF_BP + idx * 16, g_pB + tb + idx * 8);
            cp16(sb + OFF_CP + idx * 16, g_pC + tb + idx * 8);
        }
        cp_commit();
    }

    float* s_sdt = (float*)(smem + OFF_SDT);
    float* s_dt  = (float*)(smem + OFF_DTS);
    float* s_w   = (float*)(smem + OFF_WS);

    // ---- dt load + inclusive scan: single warp, shfl-based ----
    if (wid == 0) {
        size_t r = ((size_t)b * SEQLEN + t0 + lane * 2) * NHEADS + hh;
        float d0 = g_dt[r];
        float d1 = g_dt[r + NHEADS];
        float s = d0 + d1;
#pragma unroll
        for (int off = 1; off < 32; off <<= 1) {
            float n = __shfl_up_sync(0xffffffffu, s, off);
            if (lane >= off) s += n;
        }
        float tot  = __shfl_sync(0xffffffffu, s, 31);
        float sdt1 = s;
        float sdt0 = s - d1;
        s_dt[lane * 2] = d0;      s_dt[lane * 2 + 1] = d1;
        s_sdt[lane * 2] = sdt0;   s_sdt[lane * 2 + 1] = sdt1;
        s_w[lane * 2]     = expf(Ah * (tot - sdt0));
        s_w[lane * 2 + 1] = expf(Ah * (tot - sdt1));
        if (lane == 0) g_pi[((size_t)b * NHEADS + hh) * NCH + c] = tot;
    }
    __syncthreads();

    // convert U = dt*x and Uw = w*U (head-specific, fp16)
#pragma unroll
    for (int i = 0; i < 4; i++) {
        int idx = tid + i * 256;
        int t = idx >> 4, p4 = idx & 15;
        size_t row = ((size_t)b * SEQLEN + t0 + t) * CONVDIM;
        float4 xv = *(const float4*)&g_xbc[row + hh * HEADDIM + p4 * 4];
        float dtv = s_dt[t], wv = s_w[t];
        float u0 = dtv*xv.x, u1 = dtv*xv.y, u2 = dtv*xv.z, u3 = dtv*xv.w;
        uint32_t off = swzb(t, p4 * 8);
        *(__half2*)(smem + OFF_UT + off)     = __halves2half2(__float2half_rn(u0), __float2half_rn(u1));
        *(__half2*)(smem + OFF_UT + off + 4) = __halves2half2(__float2half_rn(u2), __float2half_rn(u3));
        *(__half2*)(smem + OFF_UW + off)     = __halves2half2(__float2half_rn(u0*wv), __float2half_rn(u1*wv));
        *(__half2*)(smem + OFF_UW + off + 4) = __halves2half2(__float2half_rn(u2*wv), __float2half_rn(u3*wv));
    }
    cp_wait<0>();
    __syncthreads();

    const int lgrp = lane >> 3, lr = lane & 7;
    const int a_roff = lr + (lgrp & 1) * 8;
    const int a_koff = lgrp >> 1;
    const int b_roff = lr + (lgrp >> 1) * 8;
    const int b_koff = lgrp & 1;
    const int quad = lane >> 2, qt = lane & 3;
    const int bt_row = lr + (lgrp & 1) * 8;
    const int bt_col = (lgrp >> 1) * 8;
    const int at_row = lr + (lgrp >> 1) * 8;
    const int at_col = (lgrp & 1) * 8;

    // GEMM2: G = C @ B^T
    float accG[2][2][4];
#pragma unroll
    for (int mi = 0; mi < 2; mi++)
#pragma unroll
        for (int ni = 0; ni < 2; ni++)
#pragma unroll
            for (int q = 0; q < 4; q++) accG[mi][ni][q] = 0.f;

#pragma unroll
    for (int kp = 0; kp < 2; kp++) {
#pragma unroll
        for (int k16 = 0; k16 < 4; k16++) {
            int k2 = k16 * 2;
            uint32_t aH[2][4], bH[2][2];
#pragma unroll
            for (int mi = 0; mi < 2; mi++) {
                int row = wm * 32 + mi * 16 + a_roff;
                uint32_t ad = kp * 8192u + swz(row, k2 + a_koff);
                ldsm_x4(aH[mi][0], aH[mi][1], aH[mi][2], aH[mi][3], sb + OFF_CP + ad);
            }
            {
                int row = wn * 16 + b_roff;
                uint32_t bd = kp * 8192u + swz(row, k2 + b_koff);
                uint32_t r0, r1, r2, r3;
                ldsm_x4(r0, r1, r2, r3, sb + OFF_BP + bd);
                bH[0][0] = r0; bH[0][1] = r1; bH[1][0] = r2; bH[1][1] = r3;
            }
#pragma unroll
            for (int mi = 0; mi < 2; mi++)
#pragma unroll
                for (int ni = 0; ni < 2; ni++)
                    mma_fp16(accG[mi][ni], aH[mi], bH[ni][0], bH[ni][1]);
        }
    }
    __syncthreads();

#pragma unroll
    for (int mi = 0; mi < 2; mi++)
#pragma unroll
        for (int ni = 0; ni < 2; ni++)
#pragma unroll
            for (int half = 0; half < 2; half++) {
                int t = wm * 32 + mi * 16 + quad + half * 8;
                int s = wn * 16 + ni * 8 + qt * 2;
                float sdt_t = s_sdt[t];
                float v0 = accG[mi][ni][half * 2 + 0];
                float v1 = accG[mi][ni][half * 2 + 1];
                v0 = (t >= s)     ? v0 * expf(Ah * (sdt_t - s_sdt[s]))     : 0.f;
                v1 = (t >= s + 1) ? v1 * expf(Ah * (sdt_t - s_sdt[s + 1])) : 0.f;
                uint32_t off = swzb(t, s * 2);
                *(__half2*)(smem + OFF_G + off) = __halves2half2(__float2half_rn(v0), __float2half_rn(v1));
            }
    __syncthreads();

    // GEMM4: Y = G @ U
    {
        float accY[2][2][4];
#pragma unroll
        for (int mi = 0; mi < 2; mi++)
#pragma unroll
            for (int ni = 0; ni < 2; ni++)
#pragma unroll
                for (int q = 0; q < 4; q++) accY[mi][ni][q] = 0.f;

#pragma unroll
        for (int k16 = 0; k16 < 4; k16++) {
            int k2 = k16 * 2, kb = k16 * 16;
            uint32_t aH[2][4], bH[2][2];
#pragma unroll
            for (int mi = 0; mi < 2; mi++) {
                int row = wm * 32 + mi * 16 + a_roff;
                uint32_t ad = swz(row, k2 + a_koff);
                ldsm_x4(aH[mi][0], aH[mi][1], aH[mi][2], aH[mi][3], sb + OFF_G + ad);
            }
            {
                int row = kb + bt_row;
                int col = wn * 16 + bt_col;
                uint32_t bd = swzb(row, col * 2);
                uint32_t r0, r1, r2, r3;
                ldsm_x4_t(r0, r1, r2, r3, sb + OFF_UT + bd);
                bH[0][0] = r0; bH[0][1] = r1; bH[1][0] = r2; bH[1][1] = r3;
            }
#pragma unroll
            for (int mi = 0; mi < 2; mi++)
#pragma unroll
                for (int ni = 0; ni < 2; ni++)
                    mma_fp16(accY[mi][ni], aH[mi], bH[ni][0], bH[ni][1]);
        }
#pragma unroll
        for (int mi = 0; mi < 2; mi++)
#pragma unroll
            for (int ni = 0; ni < 2; ni++) {
                int t = wm * 32 + mi * 16 + quad;
                int p = wn * 16 + ni * 8 + qt * 2;
                size_t o = ((size_t)b * SEQLEN + t0 + t) * DINNER + hh * HEADDIM + p;
                *(float2*)&g_y[o] = make_float2(accY[mi][ni][0], accY[mi][ni][1]);
                o += (size_t)8 * DINNER;
                *(float2*)&g_y[o] = make_float2(accY[mi][ni][2], accY[mi][ni][3]);
            }
    }

    // GEMM5: Hc = Uw^T-form @ B
    {
        float accH[2][4][4];
#pragma unroll
        for (int mi = 0; mi < 2; mi++)
#pragma unroll
            for (int ni = 0; ni < 4; ni++)
#pragma unroll
                for (int q = 0; q < 4; q++) accH[mi][ni][q] = 0.f;

#pragma unroll
        for (int k16 = 0; k16 < 4; k16++) {
            int kb = k16 * 16;
            uint32_t aH[2][4], bH[4][2];
#pragma unroll
            for (int mi = 0; mi < 2; mi++) {
                int row = kb + at_row;
                int col = wm * 32 + mi * 16 + at_col;
                uint32_t ad = swzb(row, col * 2);
                ldsm_x4_t(aH[mi][0], aH[mi][1], aH[mi][2], aH[mi][3], sb + OFF_UW + ad);
            }
#pragma unroll
            for (int nj = 0; nj < 2; nj++) {
                int n0 = wn * 32 + nj * 16;
                int kp = n0 >> 6, ncol = n0 & 63;
                int row = kb + bt_row;
                int col = ncol + bt_col;
                uint32_t bd = kp * 8192u + swzb(row, col * 2);
                uint32_t r0, r1, r2, r3;
                ldsm_x4_t(r0, r1, r2, r3, sb + OFF_BP + bd);
                bH[nj*2][0] = r0; bH[nj*2][1] = r1; bH[nj*2+1][0] = r2; bH[nj*2+1][1] = r3;
            }
#pragma unroll
            for (int mi = 0; mi < 2; mi++)
#pragma unroll
                for (int ni = 0; ni < 4; ni++)
                    mma_fp16(accH[mi][ni], aH[mi], bH[ni][0], bH[ni][1]);
        }
        float* hc = &g_hc[(((size_t)b * NHEADS + hh) * NCH + c) * (HEADDIM * DSTATE)];
#pragma unroll
        for (int mi = 0; mi < 2; mi++)
#pragma unroll
            for (int ni = 0; ni < 4; ni++) {
                int p = wm * 32 + mi * 16 + quad;
                int n = wn * 32 + ni * 8 + qt * 2;
                *(float2*)&hc[p * DSTATE + n] = make_float2(accH[mi][ni][0], accH[mi][ni][1]);
                *(float2*)&hc[(p + 8) * DSTATE + n] = make_float2(accH[mi][ni][2], accH[mi][ni][3]);
            }
    }
}

// =====================================================================
// SSD phase 2 (fp32, unchanged)
// =====================================================================
__global__ __launch_bounds__(256)
void ssd_prop_kernel(const float* __restrict__ A_log)
{
    const int bh = blockIdx.x;
    const int q  = blockIdx.y;
    const int hh = bh & (NHEADS - 1);
    const int tid = threadIdx.x;
    const float Ah = -expf(A_log[hh]);
    const int base = q * 512 + tid * 2;

    float4 acc[2];
    acc[0] = make_float4(0.f, 0.f, 0.f, 0.f);
    acc[1] = make_float4(0.f, 0.f, 0.f, 0.f);

    for (int c = 1; c < NCH; c++) {
        float Pi = expf(Ah * g_pi[(size_t)bh * NCH + c - 1]);
        const float4* hc = (const float4*)&g_hc[((size_t)bh * NCH + c - 1) * (HEADDIM * DSTATE)];
        float4* h0 = (float4*)&g_h0[((size_t)bh * NCH + c) * (HEADDIM * DSTATE)];
#pragma unroll
        for (int j = 0; j < 2; j++) {
            float4 v = hc[base + j];
            acc[j].x = Pi * acc[j].x + v.x;
            acc[j].y = Pi * acc[j].y + v.y;
            acc[j].z = Pi * acc[j].z + v.z;
            acc[j].w = Pi * acc[j].w + v.w;
            h0[base + j] = acc[j];
        }
    }
}

// =====================================================================
// SSD phase 3, fp16 1-pass; warp-shuffle dt scan
// =====================================================================
#define C3_CP  0u
#define C3_H0  16384u
#define C3_R   32768u
#define SMEM_SSD3 33024u

__global__ __launch_bounds__(256, 2)
void ssd_carry_kernel(const float* __restrict__ A_log)
{
    extern __shared__ __align__(1024) char smem[];
    const uint32_t sb = smem_u32(smem);
    const int c = blockIdx.x + 1, b = blockIdx.y, hh = blockIdx.z;
    const int tid = threadIdx.x;
    const int wid = tid >> 5, lane = tid & 31;
    const int wm = wid & 1, wn = wid >> 1;
    const int t0 = c * CLEN;
    const float Ah = -expf(A_log[hh]);

    {
        size_t tb = (size_t)((b * NCH + c) * 2) * 4096;
#pragma unroll
        for (int i = 0; i < 4; i++) {
            int idx = tid + i * 256;
            cp16(sb + C3_CP + idx * 16, g_pC + tb + idx * 8);
        }
        cp_commit();
    }

    float* s_r = (float*)(smem + C3_R);

    if (wid == 0) {
        size_t r = ((size_t)b * SEQLEN + t0 + lane * 2) * NHEADS + hh;
        float d0 = g_dt[r];
        float d1 = g_dt[r + NHEADS];
        float s = d0 + d1;
#pragma unroll
        for (int off = 1; off < 32; off <<= 1) {
            float n = __shfl_up_sync(0xffffffffu, s, off);
            if (lane >= off) s += n;
        }
        float sdt1 = s;
        float sdt0 = s - d1;
        s_r[lane * 2]     = expf(Ah * sdt0);
        s_r[lane * 2 + 1] = expf(Ah * sdt1);
    }

    // convert h0 (fp32 -> fp16 panels)
    const float* h0src = &g_h0[(((size_t)b * NHEADS + hh) * NCH + c) * (HEADDIM * DSTATE)];
#pragma unroll
    for (int i = 0; i < 8; i++) {
        int idx = tid + i * 256;
        int r = idx >> 5, n4 = idx & 31;
        int kp = n4 >> 4, cb = n4 & 15;
        uint32_t off = (uint32_t)kp * 8192u + (uint32_t)r * 128u
                     + ((((uint32_t)cb >> 1) ^ (r & 7)) << 4) + (cb & 1) * 8;
        float4 v = *(const float4*)&h0src[r * DSTATE + n4 * 4];
        *(__half2*)(smem + C3_H0 + off)     = __halves2half2(__float2half_rn(v.x), __float2half_rn(v.y));
        *(__half2*)(smem + C3_H0 + off + 4) = __halves2half2(__float2half_rn(v.z), __float2half_rn(v.w));
    }
    cp_wait<0>();
    __syncthreads();

    const int lgrp = lane >> 3, lr = lane & 7;
    const int a_roff = lr + (lgrp & 1) * 8;
    const int a_koff = lgrp >> 1;
    const int b_roff = lr + (lgrp >> 1) * 8;
    const int b_koff = lgrp & 1;
    const int quad = lane >> 2, qt = lane & 3;

    float acc[2][2][4];
#pragma unroll
    for (int mi = 0; mi < 2; mi++)
#pragma unroll
        for (int ni = 0; ni < 2; ni++)
#pragma unroll
            for (int q = 0; q < 4; q++) acc[mi][ni][q] = 0.f;

#pragma unroll
    for (int kp = 0; kp < 2; kp++) {
#pragma unroll
        for (int k16 = 0; k16 < 4; k16++) {
            int k2 = k16 * 2;
            uint32_t aH[2][4], bH[2][2];
#pragma unroll
            for (int mi = 0; mi < 2; mi++) {
                int row = wm * 32 + mi * 16 + a_roff;
                uint32_t ad = kp * 8192u + swz(row, k2 + a_koff);
                ldsm_x4(aH[mi][0], aH[mi][1], aH[mi][2], aH[mi][3], sb + C3_CP + ad);
            }
            {
                int row = wn * 16 + b_roff;
                uint32_t bd = kp * 8192u + swz(row, k2 + b_koff);
                uint32_t r0, r1, r2, r3;
                ldsm_x4(r0, r1, r2, r3, sb + C3_H0 + bd);
                bH[0][0] = r0; bH[0][1] = r1; bH[1][0] = r2; bH[1][1] = r3;
            }
#pragma unroll
            for (int mi = 0; mi < 2; mi++)
#pragma unroll
                for (int ni = 0; ni < 2; ni++)
                    mma_fp16(acc[mi][ni], aH[mi], bH[ni][0], bH[ni][1]);
        }
    }

#pragma unroll
    for (int mi = 0; mi < 2; mi++)
#pragma unroll
        for (int ni = 0; ni < 2; ni++) {
            int t = wm * 32 + mi * 16 + quad;
            int p = wn * 16 + ni * 8 + qt * 2;
            {
                float rt = s_r[t];
                size_t o = ((size_t)b * SEQLEN + t0 + t) * DINNER + hh * HEADDIM + p;
                float2 v = *(float2*)&g_y[o];
                v.x += rt * acc[mi][ni][0];
                v.y += rt * acc[mi][ni][1];
                *(float2*)&g_y[o] = v;
            }
            {
                float rt = s_r[t + 8];
                size_t o = ((size_t)b * SEQLEN + t0 + t + 8) * DINNER + hh * HEADDIM + p;
                float2 v = *(float2*)&g_y[o];
                v.x += rt * acc[mi][ni][2];
                v.y += rt * acc[mi][ni][3];
                *(float2*)&g_y[o] = v;
            }
        }
}

// =====================================================================
// skip + gate + RMSNorm -> fp16; warp-shuffle reduction (2 syncs)
// =====================================================================
__global__ __launch_bounds__(256)
void gate_norm_kernel(const float* __restrict__ Dw, const float* __restrict__ norm_w)
{
    const int t = blockIdx.x;
    const int b = blockIdx.y;
    const size_t row = (size_t)b * SEQLEN + t;
    const float4* __restrict__ z4 = (const float4*)&g_zx [row * DINPROJ];
    const float4* __restrict__ x4 = (const float4*)&g_xbc[row * CONVDIM];
    const float4* __restrict__ y4 = (const float4*)&g_y  [row * DINNER];
    const int tid = threadIdx.x;
    const int wid = tid >> 5, lane = tid & 31;

    float4 vals[2];
    float ss = 0.f;
#pragma unroll
    for (int r = 0; r < 2; r++) {
        int f = r * 256 + tid;
        float dv = Dw[f >> 4];
        float4 a = y4[f], xv = x4[f], zv = z4[f];
        float4 v;
        v.x = a.x + dv * xv.x;
        v.y = a.y + dv * xv.y;
        v.z = a.z + dv * xv.z;
        v.w = a.w + dv * xv.w;
        v.x *= zv.x / (1.f + expf(-zv.x));
        v.y *= zv.y / (1.f + expf(-zv.y));
        v.z *= zv.z / (1.f + expf(-zv.z));
        v.w *= zv.w / (1.f + expf(-zv.w));
        vals[r] = v;
        ss += v.x * v.x + v.y * v.y + v.z * v.z + v.w * v.w;
    }
#pragma unroll
    for (int off = 16; off > 0; off >>= 1)
        ss += __shfl_xor_sync(0xffffffffu, ss, off);
    __shared__ float red[8];
    __shared__ float s_scale;
    if (lane == 0) red[wid] = ss;
    __syncthreads();
    if (tid == 0) {
        float tot = red[0] + red[1] + red[2] + red[3]
                  + red[4] + red[5] + red[6] + red[7];
        s_scale = rsqrtf(tot / (float)DINNER + EPS);
    }
    __syncthreads();
    float scale = s_scale;
    __half2* outh = (__half2*)&g_ynh[row * DINNER];
    const float4* nw4 = (const float4*)norm_w;
#pragma unroll
    for (int r = 0; r < 2; r++) {
        int f = r * 256 + tid;
        float4 w = nw4[f];
        float4 v = vals[r];
        v.x *= scale * w.x; v.y *= scale * w.y; v.z *= scale * w.z; v.w *= scale * w.w;
        cvt4h(v, outh, f);
    }
}

// =====================================================================
extern "C" void kernel_launch(void* const* d_in, const int* in_sizes, int n_in,
                              void* d_out, int out_size)
{
    const float* x          = (const float*)d_in[0];
    const float* in_proj_w  = (const float*)d_in[1];
    const float* conv_w     = (const float*)d_in[2];
    const float* conv_b     = (const float*)d_in[3];
    const float* dt_bias    = (const float*)d_in[4];
    const float* A_log      = (const float*)d_in[5];
    const float* Dw         = (const float*)d_in[6];
    const float* norm_w     = (const float*)d_in[7];
    const float* out_proj_w = (const float*)d_in[8];
    float* out = (float*)d_out;

    float *p_zx = nullptr;
    void *p_xh, *p_w1h, *p_w2h, *p_ynh;
    cudaGetSymbolAddress((void**)&p_zx, g_zx);
    cudaGetSymbolAddress(&p_xh,  g_xh);
    cudaGetSymbolAddress(&p_w1h, g_w1h); cudaGetSymbolAddress(&p_w2h, g_w2h);
    cudaGetSymbolAddress(&p_ynh, g_ynh);

    cudaFuncSetAttribute(gemm_mma512,    cudaFuncAttributeMaxDynamicSharedMemorySize, SMEM_G1);
    cudaFuncSetAttribute(gemm_mma<true>, cudaFuncAttributeMaxDynamicSharedMemorySize, SMEM_GEMM);
    cudaFuncSetAttribute(ssd_chunk_kernel, cudaFuncAttributeMaxDynamicSharedMemorySize, SMEM_SSD1);
    cudaFuncSetAttribute(ssd_carry_kernel, cudaFuncAttributeMaxDynamicSharedMemorySize, SMEM_SSD3);

    // 0) fp32 -> fp16 conversions
    {
        int total4 = N4_X + N4_W1 + N4_W2;
        cvt_all<<<(total4 + 255)/256, 256>>>(
            (const float4*)x, (const float4*)in_proj_w, (const float4*)out_proj_w);
    }

    // 1) zxbcdt = x @ in_proj_w^T
    gemm_mma512<<<dim3((DINPROJ + 255)/256, ROWS/128), 512, SMEM_G1>>>(
        (const __half*)p_xh, (const __half*)p_w1h, p_zx, DINPROJ, DMODEL);

    // 2) conv + SiLU (B/C packed fp16); dt softplus
    conv_act_kernel<<<dim3(CONVDIM/256, SEQLEN/4, BATCH), 256>>>(conv_w, conv_b, dt_bias);

    // 3) SSD scan
    ssd_chunk_kernel<<<dim3(NCH, BATCH, NHEADS), 256, SMEM_SSD1>>>(A_log);
    ssd_prop_kernel<<<dim3(BATCH * NHEADS, 4), 256>>>(A_log);
    ssd_carry_kernel<<<dim3(NCH - 1, BATCH, NHEADS), 256, SMEM_SSD3>>>(A_log);

    // 4) skip + gate + RMSNorm
    gate_norm_kernel<<<dim3(SEQLEN, BATCH), 256>>>(Dw, norm_w);

    // 5) out = x + yn @ out_proj_w^T
    gemm_mma<true><<<dim3(DMODEL/BN, ROWS/BM), 256, SMEM_GEMM>>>(
        (const __half*)p_ynh, (const __half*)p_w2h, x, out, DMODEL, DINNER);
}

// round 16
// speedup vs baseline: 1.9165x; 1.0287x over previous
#include <cuda_runtime.h>
#include <cuda_fp16.h>
#include <math.h>
#include <stdint.h>

// ---------------- problem constants ----------------
#define BATCH    2
#define SEQLEN   1024
#define DMODEL   1024
#define DINNER   2048
#define NHEADS   32
#define HEADDIM  64
#define DSTATE   128
#define DCONV    4
#define CONVDIM  2304
#define DINPROJ  4384
#define ROWS     (BATCH*SEQLEN)
#define EPS      1e-5f
#define CLEN     64
#define NCH      (SEQLEN/CLEN)     // 16 chunks

// ---------------- scratch ----------------
__device__ __align__(1024) float g_zx [ROWS*DINPROJ];
__device__ __align__(1024) float g_xbc[ROWS*CONVDIM];
__device__ __align__(1024) float g_dt [ROWS*NHEADS];
__device__ __align__(1024) float g_y  [ROWS*DINNER];
__device__ __align__(1024) float g_yc [ROWS*DINNER];   // carry contribution (chunks>=1)
__device__ __align__(1024) float g_hc [BATCH*NHEADS*NCH*HEADDIM*DSTATE];
__device__ __align__(1024) float g_h0 [BATCH*NHEADS*NCH*HEADDIM*DSTATE];
__device__ __align__(1024) float g_pi [BATCH*NHEADS*NCH];
#define PTILES (BATCH*NCH*2)
__device__ __align__(1024) __half g_pB[PTILES*4096];
__device__ __align__(1024) __half g_pC[PTILES*4096];
__device__ __align__(1024) __half g_xh [ROWS*DMODEL];
__device__ __align__(1024) __half g_w1h[DINPROJ*DMODEL];
__device__ __align__(1024) __half g_w2h[DMODEL*DINNER];
__device__ __align__(1024) __half g_ynh[ROWS*DINNER];

// ---------------- primitives ----------------
__device__ __forceinline__ uint32_t smem_u32(const void* p) {
    uint32_t a;
    asm("{ .reg .u64 t; cvta.to.shared.u64 t, %1; cvt.u32.u64 %0, t; }" : "=r"(a) : "l"(p));
    return a;
}
__device__ __forceinline__ void cp16(uint32_t dst, const void* src) {
    asm volatile("cp.async.cg.shared.global [%0], [%1], 16;" :: "r"(dst), "l"(src));
}
__device__ __forceinline__ void cp_commit() { asm volatile("cp.async.commit_group;" ::: "memory"); }
template<int W> __device__ __forceinline__ void cp_wait() {
    asm volatile("cp.async.wait_group %0;" :: "n"(W) : "memory");
}
__device__ __forceinline__ void ldsm_x4(uint32_t& r0, uint32_t& r1, uint32_t& r2, uint32_t& r3, uint32_t a) {
    asm volatile("ldmatrix.sync.aligned.m8n8.x4.shared.b16 {%0,%1,%2,%3}, [%4];"
                 : "=r"(r0), "=r"(r1), "=r"(r2), "=r"(r3) : "r"(a));
}
__device__ __forceinline__ void ldsm_x4_t(uint32_t& r0, uint32_t& r1, uint32_t& r2, uint32_t& r3, uint32_t a) {
    asm volatile("ldmatrix.sync.aligned.m8n8.x4.trans.shared.b16 {%0,%1,%2,%3}, [%4];"
                 : "=r"(r0), "=r"(r1), "=r"(r2), "=r"(r3) : "r"(a));
}
__device__ __forceinline__ void mma_fp16(float* c, const uint32_t* a, uint32_t b0, uint32_t b1) {
    asm volatile(
        "mma.sync.aligned.m16n8k16.row.col.f32.f16.f16.f32 "
        "{%0,%1,%2,%3}, {%4,%5,%6,%7}, {%8,%9}, {%0,%1,%2,%3};"
        : "+f"(c[0]), "+f"(c[1]), "+f"(c[2]), "+f"(c[3])
        : "r"(a[0]), "r"(a[1]), "r"(a[2]), "r"(a[3]), "r"(b0), "r"(b1));
}
__device__ __forceinline__ uint32_t swz(int row, int seg) {
    return (uint32_t)(row * 128 + ((seg ^ (row & 7)) << 4));
}
__device__ __forceinline__ uint32_t swzb(int row, int colb) {
    return (uint32_t)(row * 128 + (((colb >> 4) ^ (row & 7)) << 4) + (colb & 15));
}

// =====================================================================
// GEMM variant A: 512 threads, tile 128x256 (GEMM1) — unchanged
// =====================================================================
#define KC 64
#define G1_TA   16384u
#define G1_TB   32768u
#define G1_STAGE (G1_TA + G1_TB)
#define SMEM_G1  (3u * G1_STAGE)

__global__ __launch_bounds__(512, 1)
void gemm_mma512(const __half* __restrict__ Ahp, const __half* __restrict__ Bhp,
                 float* __restrict__ C, int N, int K)
{
    extern __shared__ __align__(1024) char smem[];
    const uint32_t sb = smem_u32(smem);

    const int tid = threadIdx.x;
    const int wid = tid >> 5, lane = tid & 31;
    const int wm = wid & 1, wn = wid >> 1;
    const int m0 = blockIdx.y * 128, n0 = blockIdx.x * 256;
    const int NC = K / KC;

    auto load_chunk = [&](int stage, int k0) {
        uint32_t s = sb + stage * G1_STAGE;
#pragma unroll
        for (int it = 0; it < 2; it++) {
            int idx = tid + it * 512;
            int row = idx >> 3, seg = idx & 7;
            cp16(s + swz(row, seg), Ahp + (size_t)(m0 + row) * K + k0 + seg * 8);
        }
#pragma unroll
        for (int it = 0; it < 4; it++) {
            int idx = tid + it * 512;
            int row = idx >> 3, seg = idx & 7;
            int brow = n0 + row; if (brow >= N) brow = N - 1;
            cp16(s + G1_TA + swz(row, seg), Bhp + (size_t)brow * K + k0 + seg * 8);
        }
        cp_commit();
    };

    float acc[4][4][4];
#pragma unroll
    for (int mi = 0; mi < 4; mi++)
#pragma unroll
        for (int ni = 0; ni < 4; ni++)
#pragma unroll
            for (int q = 0; q < 4; q++) acc[mi][ni][q] = 0.f;

    const int lgrp = lane >> 3, lr = lane & 7;
    const int a_roff = lr + (lgrp & 1) * 8;
    const int a_koff = lgrp >> 1;
    const int b_roff = lr + (lgrp >> 1) * 8;
    const int b_koff = lgrp & 1;

    load_chunk(0, 0);
    load_chunk(1, KC);

    for (int c = 0; c < NC; c++) {
        if (c + 2 < NC) load_chunk((c + 2) % 3, (c + 2) * KC);
        else            cp_commit();
        cp_wait<2>();
        __syncthreads();

        uint32_t s = sb + (c % 3) * G1_STAGE;
#pragma unroll
        for (int k16 = 0; k16 < 4; k16++) {
            int k2 = k16 * 2;
            uint32_t ah[4][4], bh[4][2];
#pragma unroll
            for (int mi = 0; mi < 4; mi++) {
                int row = wm * 64 + mi * 16 + a_roff;
                uint32_t ad = swz(row, k2 + a_koff);
                ldsm_x4(ah[mi][0], ah[mi][1], ah[mi][2], ah[mi][3], s + ad);
            }
#pragma unroll
            for (int nj = 0; nj < 2; nj++) {
                int row = wn * 32 + nj * 16 + b_roff;
                uint32_t bd = swz(row, k2 + b_koff);
                uint32_t r0, r1, r2, r3;
                ldsm_x4(r0, r1, r2, r3, s + G1_TA + bd);
                bh[nj * 2][0] = r0; bh[nj * 2][1] = r1;
                bh[nj * 2 + 1][0] = r2; bh[nj * 2 + 1][1] = r3;
            }
#pragma unroll
            for (int mi = 0; mi < 4; mi++)
#pragma unroll
                for (int ni = 0; ni < 4; ni++)
                    mma_fp16(acc[mi][ni], ah[mi], bh[ni][0], bh[ni][1]);
        }
        __syncthreads();
    }

    const int quad = lane >> 2, qt = lane & 3;
#pragma unroll
    for (int mi = 0; mi < 4; mi++) {
#pragma unroll
        for (int ni = 0; ni < 4; ni++) {
            int gm = m0 + wm * 64 + mi * 16 + quad;
            int gn = n0 + wn * 32 + ni * 8 + qt * 2;
            if (gn < N) {
                *(float2*)(C + (size_t)gm * N + gn) =
                    make_float2(acc[mi][ni][0], acc[mi][ni][1]);
                *(float2*)(C + (size_t)(gm + 8) * N + gn) =
                    make_float2(acc[mi][ni][2], acc[mi][ni][3]);
            }
        }
    }
}

// =====================================================================
// GEMM variant B: 256 threads, tile 128x128 (GEMM2) — unchanged
// =====================================================================
#define BM 128
#define BN 128
#define TILE_B   16384u
#define STAGE_B  (2u*TILE_B)
#define SMEM_GEMM (3u*STAGE_B)

template<bool RES>
__global__ __launch_bounds__(256, 1)
void gemm_mma(const __half* __restrict__ Ahp, const __half* __restrict__ Bhp,
              const float* __restrict__ resid, float* __restrict__ C,
              int N, int K)
{
    extern __shared__ __align__(1024) char smem[];
    const uint32_t sb = smem_u32(smem);

    const int tid = threadIdx.x;
    const int wid = tid >> 5, lane = tid & 31;
    const int wm = wid & 1, wn = wid >> 1;
    const int m0 = blockIdx.y * BM, n0 = blockIdx.x * BN;
    const int NC = K / KC;

    auto load_chunk = [&](int stage, int k0) {
        uint32_t s = sb + stage * STAGE_B;
#pragma unroll
        for (int it = 0; it < 4; it++) {
            int idx = tid + it * 256;
            int row = idx >> 3, seg = idx & 7;
            uint32_t d = swz(row, seg);
            cp16(s + d, Ahp + (size_t)(m0 + row) * K + k0 + seg * 8);
            int brow = n0 + row; if (brow >= N) brow = N - 1;
            cp16(s + TILE_B + d, Bhp + (size_t)brow * K + k0 + seg * 8);
        }
        cp_commit();
    };

    float acc[4][4][4];
#pragma unroll
    for (int mi = 0; mi < 4; mi++)
#pragma unroll
        for (int ni = 0; ni < 4; ni++)
#pragma unroll
            for (int q = 0; q < 4; q++) acc[mi][ni][q] = 0.f;

    const int lgrp = lane >> 3, lr = lane & 7;
    const int a_roff = lr + (lgrp & 1) * 8;
    const int a_koff = lgrp >> 1;
    const int b_roff = lr + (lgrp >> 1) * 8;
    const int b_koff = lgrp & 1;

    load_chunk(0, 0);
    load_chunk(1, KC);

    for (int c = 0; c < NC; c++) {
        if (c + 2 < NC) load_chunk((c + 2) % 3, (c + 2) * KC);
        else            cp_commit();
        cp_wait<2>();
        __syncthreads();

        uint32_t s = sb + (c % 3) * STAGE_B;
#pragma unroll
        for (int k16 = 0; k16 < 4; k16++) {
            int k2 = k16 * 2;
            uint32_t ah[4][4], bh[4][2];
#pragma unroll
            for (int mi = 0; mi < 4; mi++) {
                int row = wm * 64 + mi * 16 + a_roff;
                uint32_t ad = swz(row, k2 + a_koff);
                ldsm_x4(ah[mi][0], ah[mi][1], ah[mi][2], ah[mi][3], s + ad);
            }
#pragma unroll
            for (int nj = 0; nj < 2; nj++) {
                int row = wn * 32 + nj * 16 + b_roff;
                uint32_t bd = swz(row, k2 + b_koff);
                uint32_t r0, r1, r2, r3;
                ldsm_x4(r0, r1, r2, r3, s + TILE_B + bd);
                bh[nj * 2][0] = r0; bh[nj * 2][1] = r1;
                bh[nj * 2 + 1][0] = r2; bh[nj * 2 + 1][1] = r3;
            }
#pragma unroll
            for (int mi = 0; mi < 4; mi++)
#pragma unroll
                for (int ni = 0; ni < 4; ni++)
                    mma_fp16(acc[mi][ni], ah[mi], bh[ni][0], bh[ni][1]);
        }
        __syncthreads();
    }

    const int quad = lane >> 2, qt = lane & 3;
#pragma unroll
    for (int mi = 0; mi < 4; mi++) {
#pragma unroll
        for (int ni = 0; ni < 4; ni++) {
            int gm = m0 + wm * 64 + mi * 16 + quad;
            int gn = n0 + wn * 32 + ni * 8 + qt * 2;
            if (gn < N) {
                {
                    float2 v = make_float2(acc[mi][ni][0], acc[mi][ni][1]);
                    size_t o = (size_t)gm * N + gn;
                    if (RES) { float2 rv = *(const float2*)(resid + o); v.x += rv.x; v.y += rv.y; }
                    *(float2*)(C + o) = v;
                }
                {
                    float2 v = make_float2(acc[mi][ni][2], acc[mi][ni][3]);
                    size_t o = (size_t)(gm + 8) * N + gn;
                    if (RES) { float2 rv = *(const float2*)(resid + o); v.x += rv.x; v.y += rv.y; }
                    *(float2*)(C + o) = v;
                }
            }
        }
    }
}

// =====================================================================
// fp32 -> fp16 conversions (2 float4 per thread for MLP)
// =====================================================================
#define N4_X  (ROWS*DMODEL/4)
#define N4_W1 (DINPROJ*DMODEL/4)
#define N4_W2 (DMODEL*DINNER/4)
#define N4_TOT (N4_X + N4_W1 + N4_W2)

__device__ __forceinline__ void cvt4h(float4 v, __half2* hi, int i) {
    hi[i * 2]     = __floats2half2_rn(v.x, v.y);
    hi[i * 2 + 1] = __floats2half2_rn(v.z, v.w);
}

__device__ __forceinline__ void cvt_one(const float4* x, const float4* w1,
                                        const float4* w2, int i) {
    if (i < N4_X) {
        cvt4h(x[i], (__half2*)g_xh, i);
    } else if (i < N4_X + N4_W1) {
        int j = i - N4_X;
        cvt4h(w1[j], (__half2*)g_w1h, j);
    } else if (i < N4_TOT) {
        int j = i - N4_X - N4_W1;
        cvt4h(w2[j], (__half2*)g_w2h, j);
    }
}

__global__ __launch_bounds__(256)
void cvt_all(const float4* __restrict__ x, const float4* __restrict__ w1,
             const float4* __restrict__ w2)
{
    int i0 = blockIdx.x * 512 + threadIdx.x;
    cvt_one(x, w1, w2, i0);
    cvt_one(x, w1, w2, i0 + 256);
}

// =====================================================================
// Causal depthwise conv + SiLU; dt softplus (B/C -> packed fp16 tiles)
// =====================================================================
__global__ __launch_bounds__(256)
void conv_act_kernel(const float* __restrict__ conv_w, const float* __restrict__ conv_b,
                     const float* __restrict__ dt_bias)
{
    const int c  = blockIdx.x * 256 + threadIdx.x;
    const int tb = blockIdx.y * 4;
    const int b  = blockIdx.z;

    float w0 = conv_w[c * 4 + 0], w1 = conv_w[c * 4 + 1];
    float w2 = conv_w[c * 4 + 2], w3 = conv_w[c * 4 + 3];
    float bias = conv_b[c];

    float v[7];
#pragma unroll
    for (int k = 0; k < 7; k++) {
        int tt = tb - 3 + k;
        v[k] = (tt >= 0) ? g_zx[((size_t)b * SEQLEN + tt) * DINPROJ + DINNER + c] : 0.f;
    }

    if (c < DINNER) {
#pragma unroll
        for (int i = 0; i < 4; i++) {
            float a = bias + v[i] * w0 + v[i + 1] * w1 + v[i + 2] * w2 + v[i + 3] * w3;
            g_xbc[((size_t)b * SEQLEN + tb + i) * CONVDIM + c] = a / (1.f + expf(-a));
        }
    } else {
        const int isC = (c >= DINNER + DSTATE);
        const int n   = c - DINNER - (isC ? DSTATE : 0);
        const int kp  = n >> 6, nl = n & 63;
        const int sgr = nl >> 3, e = nl & 7;
        const int ch  = tb >> 6;
        __half* dst = (isC ? g_pC : g_pB) + (size_t)(((b * NCH + ch) * 2) + kp) * 4096;
#pragma unroll
        for (int i = 0; i < 4; i++) {
            float a = bias + v[i] * w0 + v[i + 1] * w1 + v[i + 2] * w2 + v[i + 3] * w3;
            float sv = a / (1.f + expf(-a));
            int tloc = (tb & 63) + i;
            dst[tloc * 64 + ((sgr ^ (tloc & 7)) << 3) + e] = __float2half_rn(sv);
        }
    }

    if (blockIdx.x == 0 && threadIdx.x < NHEADS) {
        int hh = threadIdx.x;
        float bth = dt_bias[hh];
#pragma unroll
        for (int i = 0; i < 4; i++) {
            size_t row = (size_t)b * SEQLEN + tb + i;
            float raw = g_zx[row * DINPROJ + (DINNER + CONVDIM) + hh] + bth;
            g_dt[row * NHEADS + hh] = (raw > 20.f) ? raw : log1pf(expf(raw));
        }
    }
}

// =====================================================================
// SSD phase 1: packed conversions + fused 8B stores
// =====================================================================
#define OFF_CP  0u
#define OFF_BP  16384u
#define OFF_UT  32768u
#define OFF_UW  40960u
#define OFF_G   OFF_CP
#define OFF_SDT 49152u
#define OFF_DTS 49408u
#define OFF_WS  49664u
#define SMEM_SSD1 49920u

__global__ __launch_bounds__(256, 2)
void ssd_chunk_kernel(const float* __restrict__ A_log)
{
    extern __shared__ __align__(1024) char smem[];
    const uint32_t sb = smem_u32(smem);
    const int c = blockIdx.x, b = blockIdx.y, hh = blockIdx.z;
    const int tid = threadIdx.x;
    const int wid = tid >> 5, lane = tid & 31;
    const int wm = wid & 1, wn = wid >> 1;
    const int t0 = c * CLEN;
    const float Ah = -expf(A_log[hh]);

    {
        size_t tb = (size_t)((b * NCH + c) * 2) * 4096;
#pragma unroll
        for (int i = 0; i < 4; i++) {
            int idx = tid + i * 256;
            cp16(sb + OFF_BP + idx * 16, g_pB + tb + idx * 8);
            cp16(sb + OFF_CP + idx * 16, g_pC + tb + idx * 8);
        }
        cp_commit();
    }

    float* s_sdt = (float*)(smem + OFF_SDT);
    float* s_dt  = (float*)(smem + OFF_DTS);
    float* s_w   = (float*)(smem + OFF_WS);

    if (wid == 0) {
        size_t r = ((size_t)b * SEQLEN + t0 + lane * 2) * NHEADS + hh;
        float d0 = g_dt[r];
        float d1 = g_dt[r + NHEADS];
        float s = d0 + d1;
#pragma unroll
        for (int off = 1; off < 32; off <<= 1) {
            float n = __shfl_up_sync(0xffffffffu, s, off);
            if (lane >= off) s += n;
        }
        float tot  = __shfl_sync(0xffffffffu, s, 31);
        float sdt1 = s;
        float sdt0 = s - d1;
        s_dt[lane * 2] = d0;      s_dt[lane * 2 + 1] = d1;
        s_sdt[lane * 2] = sdt0;   s_sdt[lane * 2 + 1] = sdt1;
        s_w[lane * 2]     = expf(Ah * (tot - sdt0));
        s_w[lane * 2 + 1] = expf(Ah * (tot - sdt1));
        if (lane == 0) g_pi[((size_t)b * NHEADS + hh) * NCH + c] = tot;
    }
    __syncthreads();

    // U = dt*x, Uw = w*U  — packed cvt + 8B stores
#pragma unroll
    for (int i = 0; i < 4; i++) {
        int idx = tid + i * 256;
        int t = idx >> 4, p4 = idx & 15;
        size_t row = ((size_t)b * SEQLEN + t0 + t) * CONVDIM;
        float4 xv = *(const float4*)&g_xbc[row + hh * HEADDIM + p4 * 4];
        float dtv = s_dt[t];
        __half2 w2v = __float2half2_rn(s_w[t]);
        __half2 u01 = __floats2half2_rn(dtv * xv.x, dtv * xv.y);
        __half2 u23 = __floats2half2_rn(dtv * xv.z, dtv * xv.w);
        uint32_t off = swzb(t, p4 * 8);
        union { __half2 h[2]; uint2 u; } ut, uw;
        ut.h[0] = u01; ut.h[1] = u23;
        uw.h[0] = __hmul2(u01, w2v); uw.h[1] = __hmul2(u23, w2v);
        *(uint2*)(smem + OFF_UT + off) = ut.u;
        *(uint2*)(smem + OFF_UW + off) = uw.u;
    }
    cp_wait<0>();
    __syncthreads();

    const int lgrp = lane >> 3, lr = lane & 7;
    const int a_roff = lr + (lgrp & 1) * 8;
    const int a_koff = lgrp >> 1;
    const int b_roff = lr + (lgrp >> 1) * 8;
    const int b_koff = lgrp & 1;
    const int quad = lane >> 2, qt = lane & 3;
    const int bt_row = lr + (lgrp & 1) * 8;
    const int bt_col = (lgrp >> 1) * 8;
    const int at_row = lr + (lgrp >> 1) * 8;
    const int at_col = (lgrp & 1) * 8;

    // GEMM2: G = C @ B^T
    float accG[2][2][4];
#pragma unroll
    for (int mi = 0; mi < 2; mi++)
#pragma unroll
        for (int ni = 0; ni < 2; ni++)
#pragma unroll
            for (int q = 0; q < 4; q++) accG[mi][ni][q] = 0.f;

#pragma unroll
    for (int kp = 0; kp < 2; kp++) {
#pragma unroll
        for (int k16 = 0; k16 < 4; k16++) {
            int k2 = k16 * 2;
            uint32_t aH[2][4], bH[2][2];
#pragma unroll
            for (int mi = 0; mi < 2; mi++) {
                int row = wm * 32 + mi * 16 + a_roff;
                uint32_t ad = kp * 8192u + swz(row, k2 + a_koff);
                ldsm_x4(aH[mi][0], aH[mi][1], aH[mi][2], aH[mi][3], sb + OFF_CP + ad);
            }
            {
                int row = wn * 16 + b_roff;
                uint32_t bd = kp * 8192u + swz(row, k2 + b_koff);
                uint32_t r0, r1, r2, r3;
                ldsm_x4(r0, r1, r2, r3, sb + OFF_BP + bd);
                bH[0][0] = r0; bH[0][1] = r1; bH[1][0] = r2; bH[1][1] = r3;
            }
#pragma unroll
            for (int mi = 0; mi < 2; mi++)
#pragma unroll
                for (int ni = 0; ni < 2; ni++)
                    mma_fp16(accG[mi][ni], aH[mi], bH[ni][0], bH[ni][1]);
        }
    }
    __syncthreads();

#pragma unroll
    for (int mi = 0; mi < 2; mi++)
#pragma unroll
        for (int ni = 0; ni < 2; ni++)
#pragma unroll
            for (int half = 0; half < 2; half++) {
                int t = wm * 32 + mi * 16 + quad + half * 8;
                int s = wn * 16 + ni * 8 + qt * 2;
                float sdt_t = s_sdt[t];
                float v0 = accG[mi][ni][half * 2 + 0];
                float v1 = accG[mi][ni][half * 2 + 1];
                v0 = (t >= s)     ? v0 * expf(Ah * (sdt_t - s_sdt[s]))     : 0.f;
                v1 = (t >= s + 1) ? v1 * expf(Ah * (sdt_t - s_sdt[s + 1])) : 0.f;
                uint32_t off = swzb(t, s * 2);
                *(__half2*)(smem + OFF_G + off) = __floats2half2_rn(v0, v1);
            }
    __syncthreads();

    // GEMM4: Y = G @ U
    {
        float accY[2][2][4];
#pragma unroll
        for (int mi = 0; mi < 2; mi++)
#pragma unroll
            for (int ni = 0; ni < 2; ni++)
#pragma unroll
                for (int q = 0; q < 4; q++) accY[mi][ni][q] = 0.f;

#pragma unroll
        for (int k16 = 0; k16 < 4; k16++) {
            int k2 = k16 * 2, kb = k16 * 16;
            uint32_t aH[2][4], bH[2][2];
#pragma unroll
            for (int mi = 0; mi < 2; mi++) {
                int row = wm * 32 + mi * 16 + a_roff;
                uint32_t ad = swz(row, k2 + a_koff);
                ldsm_x4(aH[mi][0], aH[mi][1], aH[mi][2], aH[mi][3], sb + OFF_G + ad);
            }
            {
                int row = kb + bt_row;
                int col = wn * 16 + bt_col;
                uint32_t bd = swzb(row, col * 2);
                uint32_t r0, r1, r2, r3;
                ldsm_x4_t(r0, r1, r2, r3, sb + OFF_UT + bd);
                bH[0][0] = r0; bH[0][1] = r1; bH[1][0] = r2; bH[1][1] = r3;
            }
#pragma unroll
            for (int mi = 0; mi < 2; mi++)
#pragma unroll
                for (int ni = 0; ni < 2; ni++)
                    mma_fp16(accY[mi][ni], aH[mi], bH[ni][0], bH[ni][1]);
        }
#pragma unroll
        for (int mi = 0; mi < 2; mi++)
#pragma unroll
            for (int ni = 0; ni < 2; ni++) {
                int t = wm * 32 + mi * 16 + quad;
                int p = wn * 16 + ni * 8 + qt * 2;
                size_t o = ((size_t)b * SEQLEN + t0 + t) * DINNER + hh * HEADDIM + p;
                *(float2*)&g_y[o] = make_float2(accY[mi][ni][0], accY[mi][ni][1]);
                o += (size_t)8 * DINNER;
                *(float2*)&g_y[o] = make_float2(accY[mi][ni][2], accY[mi][ni][3]);
            }
    }

    // GEMM5: Hc = Uw^T-form @ B
    {
        float accH[2][4][4];
#pragma unroll
        for (int mi = 0; mi < 2; mi++)
#pragma unroll
            for (int ni = 0; ni < 4; ni++)
#pragma unroll
                for (int q = 0; q < 4; q++) accH[mi][ni][q] = 0.f;

#pragma unroll
        for (int k16 = 0; k16 < 4; k16++) {
            int kb = k16 * 16;
            uint32_t aH[2][4], bH[4][2];
#pragma unroll
            for (int mi = 0; mi < 2; mi++) {
                int row = kb + at_row;
                int col = wm * 32 + mi * 16 + at_col;
                uint32_t ad = swzb(row, col * 2);
                ldsm_x4_t(aH[mi][0], aH[mi][1], aH[mi][2], aH[mi][3], sb + OFF_UW + ad);
            }
#pragma unroll
            for (int nj = 0; nj < 2; nj++) {
                int n0 = wn * 32 + nj * 16;
                int kp = n0 >> 6, ncol = n0 & 63;
                int row = kb + bt_row;
                int col = ncol + bt_col;
                uint32_t bd = kp * 8192u + swzb(row, col * 2);
                uint32_t r0, r1, r2, r3;
                ldsm_x4_t(r0, r1, r2, r3, sb + OFF_BP + bd);
                bH[nj*2][0] = r0; bH[nj*2][1] = r1; bH[nj*2+1][0] = r2; bH[nj*2+1][1] = r3;
            }
#pragma unroll
            for (int mi = 0; mi < 2; mi++)
#pragma unroll
                for (int ni = 0; ni < 4; ni++)
                    mma_fp16(accH[mi][ni], aH[mi], bH[ni][0], bH[ni][1]);
        }
        float* hc = &g_hc[(((size_t)b * NHEADS + hh) * NCH + c) * (HEADDIM * DSTATE)];
#pragma unroll
        for (int mi = 0; mi < 2; mi++)
#pragma unroll
            for (int ni = 0; ni < 4; ni++) {
                int p = wm * 32 + mi * 16 + quad;
                int n = wn * 32 + ni * 8 + qt * 2;
                *(float2*)&hc[p * DSTATE + n] = make_float2(accH[mi][ni][0], accH[mi][ni][1]);
                *(float2*)&hc[(p + 8) * DSTATE + n] = make_float2(accH[mi][ni][2], accH[mi][ni][3]);
            }
    }
}

// =====================================================================
// SSD phase 2 (unchanged)
// =====================================================================
__global__ __launch_bounds__(256)
void ssd_prop_kernel(const float* __restrict__ A_log)
{
    const int bh = blockIdx.x;
    const int q  = blockIdx.y;
    const int hh = bh & (NHEADS - 1);
    const int tid = threadIdx.x;
    const float Ah = -expf(A_log[hh]);
    const int base = q * 512 + tid * 2;

    float4 acc[2];
    acc[0] = make_float4(0.f, 0.f, 0.f, 0.f);
    acc[1] = make_float4(0.f, 0.f, 0.f, 0.f);

    for (int c = 1; c < NCH; c++) {
        float Pi = expf(Ah * g_pi[(size_t)bh * NCH + c - 1]);
        const float4* hc = (const float4*)&g_hc[((size_t)bh * NCH + c - 1) * (HEADDIM * DSTATE)];
        float4* h0 = (float4*)&g_h0[((size_t)bh * NCH + c) * (HEADDIM * DSTATE)];
#pragma unroll
        for (int j = 0; j < 2; j++) {
            float4 v = hc[base + j];
            acc[j].x = Pi * acc[j].x + v.x;
            acc[j].y = Pi * acc[j].y + v.y;
            acc[j].z = Pi * acc[j].z + v.z;
            acc[j].w = Pi * acc[j].w + v.w;
            h0[base + j] = acc[j];
        }
    }
}

// =====================================================================
// SSD phase 3: writes carry term to g_yc (no RMW); packed h0 conversion
// =====================================================================
#define C3_CP  0u
#define C3_H0  16384u
#define C3_R   32768u
#define SMEM_SSD3 33024u

__global__ __launch_bounds__(256, 2)
void ssd_carry_kernel(const float* __restrict__ A_log)
{
    extern __shared__ __align__(1024) char smem[];
    const uint32_t sb = smem_u32(smem);
    const int c = blockIdx.x + 1, b = blockIdx.y, hh = blockIdx.z;
    const int tid = threadIdx.x;
    const int wid = tid >> 5, lane = tid & 31;
    const int wm = wid & 1, wn = wid >> 1;
    const int t0 = c * CLEN;
    const float Ah = -expf(A_log[hh]);

    {
        size_t tb = (size_t)((b * NCH + c) * 2) * 4096;
#pragma unroll
        for (int i = 0; i < 4; i++) {
            int idx = tid + i * 256;
            cp16(sb + C3_CP + idx * 16, g_pC + tb + idx * 8);
        }
        cp_commit();
    }

    float* s_r = (float*)(smem + C3_R);

    if (wid == 0) {
        size_t r = ((size_t)b * SEQLEN + t0 + lane * 2) * NHEADS + hh;
        float d0 = g_dt[r];
        float d1 = g_dt[r + NHEADS];
        float s = d0 + d1;
#pragma unroll
        for (int off = 1; off < 32; off <<= 1) {
            float n = __shfl_up_sync(0xffffffffu, s, off);
            if (lane >= off) s += n;
        }
        float sdt1 = s;
        float sdt0 = s - d1;
        s_r[lane * 2]     = expf(Ah * sdt0);
        s_r[lane * 2 + 1] = expf(Ah * sdt1);
    }

    const float* h0src = &g_h0[(((size_t)b * NHEADS + hh) * NCH + c) * (HEADDIM * DSTATE)];
#pragma unroll
    for (int i = 0; i < 8; i++) {
        int idx = tid + i * 256;
        int r = idx >> 5, n4 = idx & 31;
        int kp = n4 >> 4, cb = n4 & 15;
        uint32_t off = (uint32_t)kp * 8192u + (uint32_t)r * 128u
                     + ((((uint32_t)cb >> 1) ^ (r & 7)) << 4) + (cb & 1) * 8;
        float4 v = *(const float4*)&h0src[r * DSTATE + n4 * 4];
        union { __half2 h[2]; uint2 u; } pk;
        pk.h[0] = __floats2half2_rn(v.x, v.y);
        pk.h[1] = __floats2half2_rn(v.z, v.w);
        *(uint2*)(smem + C3_H0 + off) = pk.u;
    }
    cp_wait<0>();
    __syncthreads();

    const int lgrp = lane >> 3, lr = lane & 7;
    const int a_roff = lr + (lgrp & 1) * 8;
    const int a_koff = lgrp >> 1;
    const int b_roff = lr + (lgrp >> 1) * 8;
    const int b_koff = lgrp & 1;
    const int quad = lane >> 2, qt = lane & 3;

    float acc[2][2][4];
#pragma unroll
    for (int mi = 0; mi < 2; mi++)
#pragma unroll
        for (int ni = 0; ni < 2; ni++)
#pragma unroll
            for (int q = 0; q < 4; q++) acc[mi][ni][q] = 0.f;

#pragma unroll
    for (int kp = 0; kp < 2; kp++) {
#pragma unroll
        for (int k16 = 0; k16 < 4; k16++) {
            int k2 = k16 * 2;
            uint32_t aH[2][4], bH[2][2];
#pragma unroll
            for (int mi = 0; mi < 2; mi++) {
                int row = wm * 32 + mi * 16 + a_roff;
                uint32_t ad = kp * 8192u + swz(row, k2 + a_koff);
                ldsm_x4(aH[mi][0], aH[mi][1], aH[mi][2], aH[mi][3], sb + C3_CP + ad);
            }
            {
                int row = wn * 16 + b_roff;
                uint32_t bd = kp * 8192u + swz(row, k2 + b_koff);
                uint32_t r0, r1, r2, r3;
                ldsm_x4(r0, r1, r2, r3, sb + C3_H0 + bd);
                bH[0][0] = r0; bH[0][1] = r1; bH[1][0] = r2; bH[1][1] = r3;
            }
#pragma unroll
            for (int mi = 0; mi < 2; mi++)
#pragma unroll
                for (int ni = 0; ni < 2; ni++)
                    mma_fp16(acc[mi][ni], aH[mi], bH[ni][0], bH[ni][1]);
        }
    }

#pragma unroll
    for (int mi = 0; mi < 2; mi++)
#pragma unroll
        for (int ni = 0; ni < 2; ni++) {
            int t = wm * 32 + mi * 16 + quad;
            int p = wn * 16 + ni * 8 + qt * 2;
            {
                float rt = s_r[t];
                size_t o = ((size_t)b * SEQLEN + t0 + t) * DINNER + hh * HEADDIM + p;
                *(float2*)&g_yc[o] = make_float2(rt * acc[mi][ni][0], rt * acc[mi][ni][1]);
            }
            {
                float rt = s_r[t + 8];
                size_t o = ((size_t)b * SEQLEN + t0 + t + 8) * DINNER + hh * HEADDIM + p;
                *(float2*)&g_yc[o] = make_float2(rt * acc[mi][ni][2], rt * acc[mi][ni][3]);
            }
        }
}

// =====================================================================
// skip + gate + RMSNorm -> fp16 (adds g_yc for t >= CLEN)
// =====================================================================
__global__ __launch_bounds__(256)
void gate_norm_kernel(const float* __restrict__ Dw, const float* __restrict__ norm_w)
{
    const int t = blockIdx.x;
    const int b = blockIdx.y;
    const size_t row = (size_t)b * SEQLEN + t;
    const float4* __restrict__ z4 = (const float4*)&g_zx [row * DINPROJ];
    const float4* __restrict__ x4 = (const float4*)&g_xbc[row * CONVDIM];
    const float4* __restrict__ y4 = (const float4*)&g_y  [row * DINNER];
    const float4* __restrict__ yc4 = (const float4*)&g_yc[row * DINNER];
    const bool hasC = (t >= CLEN);
    const int tid = threadIdx.x;
    const int wid = tid >> 5, lane = tid & 31;

    float4 vals[2];
    float ss = 0.f;
#pragma unroll
    for (int r = 0; r < 2; r++) {
        int f = r * 256 + tid;
        float dv = Dw[f >> 4];
        float4 a = y4[f], xv = x4[f], zv = z4[f];
        if (hasC) {
            float4 cv = yc4[f];
            a.x += cv.x; a.y += cv.y; a.z += cv.z; a.w += cv.w;
        }
        float4 v;
        v.x = a.x + dv * xv.x;
        v.y = a.y + dv * xv.y;
        v.z = a.z + dv * xv.z;
        v.w = a.w + dv * xv.w;
        v.x *= zv.x / (1.f + expf(-zv.x));
        v.y *= zv.y / (1.f + expf(-zv.y));
        v.z *= zv.z / (1.f + expf(-zv.z));
        v.w *= zv.w / (1.f + expf(-zv.w));
        vals[r] = v;
        ss += v.x * v.x + v.y * v.y + v.z * v.z + v.w * v.w;
    }
#pragma unroll
    for (int off = 16; off > 0; off >>= 1)
        ss += __shfl_xor_sync(0xffffffffu, ss, off);
    __shared__ float red[8];
    __shared__ float s_scale;
    if (lane == 0) red[wid] = ss;
    __syncthreads();
    if (tid == 0) {
        float tot = red[0] + red[1] + red[2] + red[3]
                  + red[4] + red[5] + red[6] + red[7];
        s_scale = rsqrtf(tot / (float)DINNER + EPS);
    }
    __syncthreads();
    float scale = s_scale;
    __half2* outh = (__half2*)&g_ynh[row * DINNER];
    const float4* nw4 = (const float4*)norm_w;
#pragma unroll
    for (int r = 0; r < 2; r++) {
        int f = r * 256 + tid;
        float4 w = nw4[f];
        float4 v = vals[r];
        v.x *= scale * w.x; v.y *= scale * w.y; v.z *= scale * w.z; v.w *= scale * w.w;
        cvt4h(v, outh, f);
    }
}

// =====================================================================
extern "C" void kernel_launch(void* const* d_in, const int* in_sizes, int n_in,
                              void* d_out, int out_size)
{
    const float* x          = (const float*)d_in[0];
    const float* in_proj_w  = (const float*)d_in[1];
    const float* conv_w     = (const float*)d_in[2];
    const float* conv_b     = (const float*)d_in[3];
    const float* dt_bias    = (const float*)d_in[4];
    const float* A_log      = (const float*)d_in[5];
    const float* Dw         = (const float*)d_in[6];
    const float* norm_w     = (const float*)d_in[7];
    const float* out_proj_w = (const float*)d_in[8];
    float* out = (float*)d_out;

    float *p_zx = nullptr;
    void *p_xh, *p_w1h, *p_w2h, *p_ynh;
    cudaGetSymbolAddress((void**)&p_zx, g_zx);
    cudaGetSymbolAddress(&p_xh,  g_xh);
    cudaGetSymbolAddress(&p_w1h, g_w1h); cudaGetSymbolAddress(&p_w2h, g_w2h);
    cudaGetSymbolAddress(&p_ynh, g_ynh);

    cudaFuncSetAttribute(gemm_mma512,    cudaFuncAttributeMaxDynamicSharedMemorySize, SMEM_G1);
    cudaFuncSetAttribute(gemm_mma<true>, cudaFuncAttributeMaxDynamicSharedMemorySize, SMEM_GEMM);
    cudaFuncSetAttribute(ssd_chunk_kernel, cudaFuncAttributeMaxDynamicSharedMemorySize, SMEM_SSD1);
    cudaFuncSetAttribute(ssd_carry_kernel, cudaFuncAttributeMaxDynamicSharedMemorySize, SMEM_SSD3);

    // 0) fp32 -> fp16 conversions
    cvt_all<<<(N4_TOT + 511)/512, 256>>>(
        (const float4*)x, (const float4*)in_proj_w, (const float4*)out_proj_w);

    // 1) zxbcdt = x @ in_proj_w^T
    gemm_mma512<<<dim3((DINPROJ + 255)/256, ROWS/128), 512, SMEM_G1>>>(
        (const __half*)p_xh, (const __half*)p_w1h, p_zx, DINPROJ, DMODEL);

    // 2) conv + SiLU (B/C packed fp16); dt softplus
    conv_act_kernel<<<dim3(CONVDIM/256, SEQLEN/4, BATCH), 256>>>(conv_w, conv_b, dt_bias);

    // 3) SSD scan
    ssd_chunk_kernel<<<dim3(NCH, BATCH, NHEADS), 256, SMEM_SSD1>>>(A_log);
    ssd_prop_kernel<<<dim3(BATCH * NHEADS, 4), 256>>>(A_log);
    ssd_carry_kernel<<<dim3(NCH - 1, BATCH, NHEADS), 256, SMEM_SSD3>>>(A_log);

    // 4) skip + gate + RMSNorm
    gate_norm_kernel<<<dim3(SEQLEN, BATCH), 256>>>(Dw, norm_w);

    // 5) out = x + yn @ out_proj_w^T
    gemm_mma<true><<<dim3(DMODEL/BN, ROWS/BM), 256, SMEM_GEMM>>>(
        (const __half*)p_ynh, (const __half*)p_w2h, x, out, DMODEL, DINNER);
}